// round 1
// baseline (speedup 1.0000x reference)
#include <cuda_runtime.h>
#include <math.h>

#define B_SZ  2048
#define D_IN  1024
#define D_OUT 2048
#define D_C   256

// ---- hyperparameters (from reference) ----
#define GAMMA_F 0.1f
#define RHO_F   0.9f
#define ONE_M_RHO_F 0.1f
#define LR_F    0.009f
#define MOM_F   0.9f
#define EPS_F   1e-8f

// ---- persistent scratch (allocation-free rule: __device__ globals) ----
__device__ float g_E [B_SZ * D_IN];    // inputs - x@W
__device__ float g_G [B_SZ * D_OUT];   // dcost/ds  (for gu GEMM)
__device__ float g_T [B_SZ * D_OUT];   // elementwise part of gx
__device__ float g_a1[B_SZ * D_OUT];
__device__ float g_a2[B_SZ * D_OUT];
__device__ float g_u [B_SZ * D_C];
__device__ float g_b1[B_SZ * D_C];
__device__ float g_b2[B_SZ * D_C];

__global__ void zero_kernel(float* __restrict__ p, int n) {
    int i = blockIdx.x * blockDim.x + threadIdx.x;
    if (i < n) p[i] = 0.0f;
}

// ============================================================================
// SGEMM: C = A(MxK, row-major) * B, 128x128 tile, BK=16, 8x8 per thread.
// TRANSB=false: B is [K,N] row-major.  TRANSB=true: B is [N,K] row-major.
// Epilogues (fused):
//   EPI=0: p1[idx] = p0[idx] - acc                      (E = inputs - xW)
//   EPI=1: s=acc; from x=p0: G->p1, T->p2
//   EPI=2: g = -2*acc + p0; rmsprop update (p1=x, p2=a1, p3=a2)
//   EPI=3: g = acc;         rmsprop update (p1=u, p2=b1, p3=b2)
// All dims here are multiples of tile sizes; no bounds checks needed.
// ============================================================================
template<bool TRANSB, int EPI>
__global__ __launch_bounds__(256)
void sgemm(const float* __restrict__ A, const float* __restrict__ Bm,
           int M, int N, int K,
           const float* __restrict__ p0, float* __restrict__ p1,
           float* __restrict__ p2, float* __restrict__ p3)
{
    constexpr int BM = 128, BN = 128, BK = 16;
    __shared__ float As[BK][BM];
    __shared__ float Bs[BK][BN + 4];   // +4 pad keeps 16B alignment, breaks conflicts

    const int tid  = threadIdx.x;
    const int row0 = blockIdx.y * BM;
    const int col0 = blockIdx.x * BN;
    const int tr   = tid >> 4;   // 0..15
    const int tc   = tid & 15;   // 0..15

    float acc[8][8];
    #pragma unroll
    for (int i = 0; i < 8; i++)
        #pragma unroll
        for (int j = 0; j < 8; j++)
            acc[i][j] = 0.0f;

    for (int k0 = 0; k0 < K; k0 += BK) {
        // ---- load A tile (128 x 16), transposed into As[k][m] ----
        #pragma unroll
        for (int l = 0; l < 2; l++) {
            int i  = tid + l * 256;       // 512 float4 total
            int r  = i >> 2;              // row within tile (0..127)
            int c4 = (i & 3) << 2;        // k offset (0,4,8,12)
            float4 v = *reinterpret_cast<const float4*>(
                &A[(size_t)(row0 + r) * K + k0 + c4]);
            As[c4 + 0][r] = v.x; As[c4 + 1][r] = v.y;
            As[c4 + 2][r] = v.z; As[c4 + 3][r] = v.w;
        }
        // ---- load B tile into Bs[k][n] ----
        if (!TRANSB) {
            #pragma unroll
            for (int l = 0; l < 2; l++) {
                int i  = tid + l * 256;
                int r  = i >> 5;          // k row (0..15)
                int c4 = (i & 31) << 2;   // n offset
                float4 v = *reinterpret_cast<const float4*>(
                    &Bm[(size_t)(k0 + r) * N + col0 + c4]);
                *reinterpret_cast<float4*>(&Bs[r][c4]) = v;
            }
        } else {
            #pragma unroll
            for (int l = 0; l < 2; l++) {
                int i  = tid + l * 256;
                int n  = i >> 2;          // n row (0..127)
                int c4 = (i & 3) << 2;    // k offset
                float4 v = *reinterpret_cast<const float4*>(
                    &Bm[(size_t)(col0 + n) * K + k0 + c4]);
                Bs[c4 + 0][n] = v.x; Bs[c4 + 1][n] = v.y;
                Bs[c4 + 2][n] = v.z; Bs[c4 + 3][n] = v.w;
            }
        }
        __syncthreads();

        #pragma unroll
        for (int k = 0; k < BK; k++) {
            float ar[8], br[8];
            *reinterpret_cast<float4*>(&ar[0]) =
                *reinterpret_cast<const float4*>(&As[k][tr * 8]);
            *reinterpret_cast<float4*>(&ar[4]) =
                *reinterpret_cast<const float4*>(&As[k][tr * 8 + 4]);
            *reinterpret_cast<float4*>(&br[0]) =
                *reinterpret_cast<const float4*>(&Bs[k][tc * 8]);
            *reinterpret_cast<float4*>(&br[4]) =
                *reinterpret_cast<const float4*>(&Bs[k][tc * 8 + 4]);
            #pragma unroll
            for (int i = 0; i < 8; i++)
                #pragma unroll
                for (int j = 0; j < 8; j++)
                    acc[i][j] = fmaf(ar[i], br[j], acc[i][j]);
        }
        __syncthreads();
    }

    // ---- fused epilogue ----
    #pragma unroll
    for (int i = 0; i < 8; i++) {
        const int m = row0 + tr * 8 + i;
        #pragma unroll
        for (int j = 0; j < 8; j++) {
            const int n = col0 + tc * 8 + j;
            const size_t idx = (size_t)m * N + n;
            const float a = acc[i][j];
            if (EPI == 0) {
                p1[idx] = p0[idx] - a;                       // E = inputs - xW
            } else if (EPI == 1) {
                const float xv = p0[idx];
                const float da = sqrtf(xv * xv + 1e-6f);     // diff_abs(x)
                const float ex = expf(-a);                   // exp(-s)
                p1[idx] = GAMMA_F * da * (-0.5f * ex);       // G
                const float causes = (1.0f + ex) * 0.5f;
                p2[idx] = (GAMMA_F * causes + GAMMA_F * 0.1f) * (xv / da);  // T
            } else {
                const float g  = (EPI == 2) ? fmaf(-2.0f, a, p0[idx]) : a;
                const float sv  = p1[idx];
                const float a1v = p2[idx];
                const float a2v = p3[idx];
                const float na1 = RHO_F * a1v + ONE_M_RHO_F * g * g;
                const float upd = LR_F * g / sqrtf(na1 + EPS_F);
                const float na2 = MOM_F * a2v - upd;
                p1[idx] = sv + MOM_F * na2 - upd;
                p2[idx] = na1;
                p3[idx] = na2;
            }
        }
    }
}

extern "C" void kernel_launch(void* const* d_in, const int* in_sizes, int n_in,
                              void* d_out, int out_size)
{
    (void)in_sizes; (void)n_in; (void)out_size;
    const float* inputs = (const float*)d_in[0];
    const float* W      = (const float*)d_in[1];   // [D_OUT, D_IN]
    const float* V      = (const float*)d_in[2];   // [D_C, D_OUT]
    float* x = (float*)d_out;                      // states live in d_out

    float *pE, *pG, *pT, *pa1, *pa2, *pu, *pb1, *pb2;
    cudaGetSymbolAddress((void**)&pE,  g_E);
    cudaGetSymbolAddress((void**)&pG,  g_G);
    cudaGetSymbolAddress((void**)&pT,  g_T);
    cudaGetSymbolAddress((void**)&pa1, g_a1);
    cudaGetSymbolAddress((void**)&pa2, g_a2);
    cudaGetSymbolAddress((void**)&pu,  g_u);
    cudaGetSymbolAddress((void**)&pb1, g_b1);
    cudaGetSymbolAddress((void**)&pb2, g_b2);

    // zero-init all state (every call: deterministic + graph-replayable)
    const int TPB = 256;
    zero_kernel<<<(B_SZ * D_OUT + TPB - 1) / TPB, TPB>>>(x,   B_SZ * D_OUT);
    zero_kernel<<<(B_SZ * D_OUT + TPB - 1) / TPB, TPB>>>(pa1, B_SZ * D_OUT);
    zero_kernel<<<(B_SZ * D_OUT + TPB - 1) / TPB, TPB>>>(pa2, B_SZ * D_OUT);
    zero_kernel<<<(B_SZ * D_C   + TPB - 1) / TPB, TPB>>>(pu,  B_SZ * D_C);
    zero_kernel<<<(B_SZ * D_C   + TPB - 1) / TPB, TPB>>>(pb1, B_SZ * D_C);
    zero_kernel<<<(B_SZ * D_C   + TPB - 1) / TPB, TPB>>>(pb2, B_SZ * D_C);

    dim3 blk(256);
    for (int s = 0; s < 10; s++) {
        // 1) E = inputs - x @ W            [2048,1024], K=2048, NN
        sgemm<false, 0><<<dim3(D_IN / 128, B_SZ / 128), blk>>>(
            x, W, B_SZ, D_IN, D_OUT, inputs, pE, nullptr, nullptr);
        // 2) s = u @ V; G,T from old x     [2048,2048], K=256, NN
        sgemm<false, 1><<<dim3(D_OUT / 128, B_SZ / 128), blk>>>(
            pu, V, B_SZ, D_OUT, D_C, x, pG, pT, nullptr);
        // 3) gx = -2*E@W^T + T; update x   [2048,2048], K=1024, NT
        sgemm<true, 2><<<dim3(D_OUT / 128, B_SZ / 128), blk>>>(
            pE, W, B_SZ, D_OUT, D_IN, pT, x, pa1, pa2);
        // 4) gu = G @ V^T; update u        [2048,256],  K=2048, NT
        sgemm<true, 3><<<dim3(D_C / 128, B_SZ / 128), blk>>>(
            pG, V, B_SZ, D_C, D_OUT, nullptr, pu, pb1, pb2);
    }
}

// round 3
// speedup vs baseline: 2.8038x; 2.8038x over previous
#include <cuda_runtime.h>
#include <cuda_bf16.h>
#include <cstdint>
#include <math.h>

#define B_SZ  2048
#define D_IN  1024
#define D_OUT 2048
#define D_C   256

#define GAMMA_F 0.1f
#define RHO_F   0.9f
#define ONE_M_RHO_F 0.1f
#define LR_F    0.009f
#define MOM_F   0.9f
#define EPS_F   1e-8f

// ---- persistent scratch (__device__ globals; no allocation allowed) ----
__device__ float g_E [B_SZ * D_IN];
__device__ float g_G [B_SZ * D_OUT];
__device__ float g_T [B_SZ * D_OUT];
__device__ float g_a1[B_SZ * D_OUT];
__device__ float g_a2[B_SZ * D_OUT];
__device__ float g_u [B_SZ * D_C];
__device__ float g_b1[B_SZ * D_C];
__device__ float g_b2[B_SZ * D_C];
__device__ float g_WT[D_IN * D_OUT];   // W^T  [1024,2048]
__device__ float g_VT[D_OUT * D_C];    // V^T  [2048,256]

__global__ void zero_kernel(float* __restrict__ p, int n) {
    int i = blockIdx.x * blockDim.x + threadIdx.x;
    if (i < n) p[i] = 0.0f;
}

// 32x32 tiled transpose: src [rows, cols] -> dst [cols, rows]
__global__ void transpose_k(const float* __restrict__ src, float* __restrict__ dst,
                            int rows, int cols) {
    __shared__ float t[32][33];
    int bx = blockIdx.x * 32, by = blockIdx.y * 32;
    int x = bx + threadIdx.x;
    #pragma unroll
    for (int j = 0; j < 32; j += 8)
        t[threadIdx.y + j][threadIdx.x] = src[(size_t)(by + threadIdx.y + j) * cols + x];
    __syncthreads();
    int x2 = by + threadIdx.x;
    #pragma unroll
    for (int j = 0; j < 32; j += 8)
        dst[(size_t)(bx + threadIdx.y + j) * rows + x2] = t[threadIdx.x][threadIdx.y + j];
}

// ============================ helpers ============================

__device__ __forceinline__ uint32_t cvta_smem(const void* p) {
    uint32_t a;
    asm("{ .reg .u64 t; cvta.to.shared.u64 t, %1; cvt.u32.u64 %0, t; }" : "=r"(a) : "l"(p));
    return a;
}

__device__ __forceinline__ void split2(float x, float y, uint32_t& hi, uint32_t& lo) {
    __nv_bfloat16 hx = __float2bfloat16(x);
    __nv_bfloat16 hy = __float2bfloat16(y);
    float rx = x - __bfloat162float(hx);
    float ry = y - __bfloat162float(hy);
    __nv_bfloat162 H; H.x = hx; H.y = hy;
    hi = *reinterpret_cast<uint32_t*>(&H);
    __nv_bfloat162 L = __floats2bfloat162_rn(rx, ry);
    lo = *reinterpret_cast<uint32_t*>(&L);
}

__device__ __forceinline__ void mma_bf16(float* c, const uint32_t* a, const uint32_t* b) {
    asm volatile(
        "mma.sync.aligned.m16n8k16.row.col.f32.bf16.bf16.f32 "
        "{%0,%1,%2,%3}, {%4,%5,%6,%7}, {%8,%9}, {%0,%1,%2,%3};"
        : "+f"(c[0]), "+f"(c[1]), "+f"(c[2]), "+f"(c[3])
        : "r"(a[0]), "r"(a[1]), "r"(a[2]), "r"(a[3]), "r"(b[0]), "r"(b[1]));
}

#define LDSM_X4(R, addr) \
    asm volatile("ldmatrix.sync.aligned.m8n8.x4.shared.b16 {%0,%1,%2,%3}, [%4];" \
        : "=r"((R)[0]), "=r"((R)[1]), "=r"((R)[2]), "=r"((R)[3]) : "r"(addr))

// elementwise epilogue on a pair (n, n+1)
template<int EPI>
__device__ __forceinline__ void epi_pair(float a0, float a1, int m, int n, int Nout,
                                         const float* __restrict__ p0,
                                         float* __restrict__ p1,
                                         float* __restrict__ p2,
                                         float* __restrict__ p3)
{
    const size_t idx = (size_t)m * (size_t)Nout + (size_t)n;
    if (EPI == 0) {
        float2 q = *reinterpret_cast<const float2*>(&p0[idx]);
        float2 o; o.x = q.x - a0; o.y = q.y - a1;
        *reinterpret_cast<float2*>(&p1[idx]) = o;
    } else if (EPI == 1) {
        float2 xv = *reinterpret_cast<const float2*>(&p0[idx]);
        float2 G, T;
        {
            float da = sqrtf(xv.x * xv.x + 1e-6f);
            float ex = expf(-a0);
            G.x = GAMMA_F * da * (-0.5f * ex);
            T.x = (GAMMA_F * (1.0f + ex) * 0.5f + GAMMA_F * 0.1f) * (xv.x / da);
        }
        {
            float da = sqrtf(xv.y * xv.y + 1e-6f);
            float ex = expf(-a1);
            G.y = GAMMA_F * da * (-0.5f * ex);
            T.y = (GAMMA_F * (1.0f + ex) * 0.5f + GAMMA_F * 0.1f) * (xv.y / da);
        }
        *reinterpret_cast<float2*>(&p1[idx]) = G;
        *reinterpret_cast<float2*>(&p2[idx]) = T;
    } else {
        float2 g2;
        if (EPI == 2) {
            float2 t = *reinterpret_cast<const float2*>(&p0[idx]);
            g2.x = fmaf(-2.0f, a0, t.x);
            g2.y = fmaf(-2.0f, a1, t.y);
        } else {
            g2.x = a0; g2.y = a1;
        }
        float2 sv  = *reinterpret_cast<const float2*>(&p1[idx]);
        float2 a1v = *reinterpret_cast<const float2*>(&p2[idx]);
        float2 a2v = *reinterpret_cast<const float2*>(&p3[idx]);
        float na1x = RHO_F * a1v.x + ONE_M_RHO_F * g2.x * g2.x;
        float updx = LR_F * g2.x / sqrtf(na1x + EPS_F);
        float na2x = MOM_F * a2v.x - updx;
        float svx  = sv.x + MOM_F * na2x - updx;
        float na1y = RHO_F * a1v.y + ONE_M_RHO_F * g2.y * g2.y;
        float updy = LR_F * g2.y / sqrtf(na1y + EPS_F);
        float na2y = MOM_F * a2v.y - updy;
        float svy  = sv.y + MOM_F * na2y - updy;
        float2 o1; o1.x = svx;  o1.y = svy;
        float2 o2; o2.x = na1x; o2.y = na1y;
        float2 o3; o3.x = na2x; o3.y = na2y;
        *reinterpret_cast<float2*>(&p1[idx]) = o1;
        *reinterpret_cast<float2*>(&p2[idx]) = o2;
        *reinterpret_cast<float2*>(&p3[idx]) = o3;
    }
}

// ============================================================================
// bf16x3 mma.sync GEMM.  D[M,N] = A[M,K(lda)] * Bg[N,K(ldb)]^T  (fp32 in/out)
// CTA tile BM x BN, BK=32, 8 warps (2x4), double-buffered SMEM.
// SMEM row = 128B: 8 chunks of 16B; logical chunk 2g=hi(k8 group g), 2g+1=lo;
// physical chunk = logical ^ (row&7).  Conflict-free STS and ldmatrix.
// ============================================================================
template<int BM, int BN, int EPI>
__global__ __launch_bounds__(256, 1)
void mma_gemm(const float* __restrict__ A, const float* __restrict__ Bg,
              int Nout, int K, int lda, int ldb,
              const float* __restrict__ p0, float* __restrict__ p1,
              float* __restrict__ p2, float* __restrict__ p3)
{
    constexpr int WTM = BM / 2, WTN = BN / 4;
    constexpr int MF  = WTM / 16, NF = WTN / 8;
    constexpr int AF4 = BM / 32;         // float4 LDGs per thread for A tile
    constexpr int BF4 = BN / 32;
    constexpr int STAGE = (BM + BN) * 128;

    extern __shared__ __align__(1024) char smem[];
    const uint32_t sbase = cvta_smem(smem);

    const int tid  = threadIdx.x;
    const int lane = tid & 31, wid = tid >> 5;
    const int wm = wid >> 2, wn = wid & 3;
    const int row0 = blockIdx.y * BM;
    const int col0 = blockIdx.x * BN;

    float acc[MF][NF][4];
    #pragma unroll
    for (int i = 0; i < MF; i++)
        #pragma unroll
        for (int j = 0; j < NF; j++)
            #pragma unroll
            for (int r = 0; r < 4; r++) acc[i][j][r] = 0.0f;

    const int iters = K / 32;
    float4 ra[AF4], rb[BF4];

    // thread -> (row, c4) mapping: warp covers 8 rows x 4 k-chunks (conflict-free STS)
    auto ldg_tile = [&](int kt) {
        const int k0 = kt * 32;
        #pragma unroll
        for (int i = 0; i < AF4; i++) {
            int idx = i * 256 + tid;
            int l = idx & 31, w = idx >> 5;
            int r  = (w >> 1) * 8 + (l >> 2);
            int c4 = (l & 3) + 4 * (w & 1);
            ra[i] = *reinterpret_cast<const float4*>(
                &A[(size_t)(row0 + r) * lda + k0 + c4 * 4]);
        }
        #pragma unroll
        for (int i = 0; i < BF4; i++) {
            int idx = i * 256 + tid;
            int l = idx & 31, w = idx >> 5;
            int r  = (w >> 1) * 8 + (l >> 2);
            int c4 = (l & 3) + 4 * (w & 1);
            rb[i] = *reinterpret_cast<const float4*>(
                &Bg[(size_t)(col0 + r) * ldb + k0 + c4 * 4]);
        }
    };

    auto sts_tile = [&](int buf) {
        char* sA = smem + buf * STAGE;
        char* sB = sA + BM * 128;
        #pragma unroll
        for (int i = 0; i < AF4; i++) {
            int idx = i * 256 + tid;
            int l = idx & 31, w = idx >> 5;
            int r  = (w >> 1) * 8 + (l >> 2);
            int c4 = (l & 3) + 4 * (w & 1);
            int g = c4 >> 1, h = c4 & 1, x = r & 7;
            uint32_t hi0, lo0, hi1, lo1;
            split2(ra[i].x, ra[i].y, hi0, lo0);
            split2(ra[i].z, ra[i].w, hi1, lo1);
            uint2 hv; hv.x = hi0; hv.y = hi1;
            uint2 lv; lv.x = lo0; lv.y = lo1;
            *reinterpret_cast<uint2*>(sA + r * 128 + (((2 * g    ) ^ x) << 4) + h * 8) = hv;
            *reinterpret_cast<uint2*>(sA + r * 128 + (((2 * g + 1) ^ x) << 4) + h * 8) = lv;
        }
        #pragma unroll
        for (int i = 0; i < BF4; i++) {
            int idx = i * 256 + tid;
            int l = idx & 31, w = idx >> 5;
            int r  = (w >> 1) * 8 + (l >> 2);
            int c4 = (l & 3) + 4 * (w & 1);
            int g = c4 >> 1, h = c4 & 1, x = r & 7;
            uint32_t hi0, lo0, hi1, lo1;
            split2(rb[i].x, rb[i].y, hi0, lo0);
            split2(rb[i].z, rb[i].w, hi1, lo1);
            uint2 hv; hv.x = hi0; hv.y = hi1;
            uint2 lv; lv.x = lo0; lv.y = lo1;
            *reinterpret_cast<uint2*>(sB + r * 128 + (((2 * g    ) ^ x) << 4) + h * 8) = hv;
            *reinterpret_cast<uint2*>(sB + r * 128 + (((2 * g + 1) ^ x) << 4) + h * 8) = lv;
        }
    };

    // prologue
    ldg_tile(0);
    sts_tile(0);
    __syncthreads();

    for (int kt = 0; kt < iters; kt++) {
        const int buf = kt & 1;
        if (kt + 1 < iters) ldg_tile(kt + 1);

        const uint32_t sA32 = sbase + buf * STAGE;
        const uint32_t sB32 = sA32 + BM * 128;

        #pragma unroll
        for (int j = 0; j < 2; j++) {               // two k16 blocks in BK=32
            uint32_t af[2][MF][4];                  // [hi/lo][mfrag][reg]
            #pragma unroll
            for (int hl = 0; hl < 2; hl++)
                #pragma unroll
                for (int mf = 0; mf < MF; mf++) {
                    int rr = wm * WTM + mf * 16 + (lane & 15);
                    int c  = 4 * j + hl + 2 * (lane >> 4);
                    uint32_t addr = sA32 + rr * 128 + (((c ^ (rr & 7))) << 4);
                    LDSM_X4(af[hl][mf], addr);
                }
            uint32_t bfr[2][NF][2];
            #pragma unroll
            for (int hl = 0; hl < 2; hl++)
                #pragma unroll
                for (int p = 0; p < NF / 2; p++) {
                    uint32_t q[4];
                    int rr = wn * WTN + (2 * p + (lane >> 4)) * 8 + (lane & 7);
                    int c  = 4 * j + hl + 2 * ((lane >> 3) & 1);
                    uint32_t addr = sB32 + rr * 128 + (((c ^ (rr & 7))) << 4);
                    LDSM_X4(q, addr);
                    bfr[hl][2 * p    ][0] = q[0]; bfr[hl][2 * p    ][1] = q[1];
                    bfr[hl][2 * p + 1][0] = q[2]; bfr[hl][2 * p + 1][1] = q[3];
                }
            #pragma unroll
            for (int mf = 0; mf < MF; mf++)
                #pragma unroll
                for (int nf = 0; nf < NF; nf++) {
                    mma_bf16(acc[mf][nf], af[0][mf], bfr[0][nf]);   // hi*hi
                    mma_bf16(acc[mf][nf], af[0][mf], bfr[1][nf]);   // hi*lo
                    mma_bf16(acc[mf][nf], af[1][mf], bfr[0][nf]);   // lo*hi
                }
        }

        if (kt + 1 < iters) sts_tile(buf ^ 1);
        __syncthreads();
    }

    // ---- fused epilogue (fragment-indexed, float2 granularity) ----
    #pragma unroll
    for (int mf = 0; mf < MF; mf++) {
        #pragma unroll
        for (int nf = 0; nf < NF; nf++) {
            int mlo = row0 + wm * WTM + mf * 16 + (lane >> 2);
            int n   = col0 + wn * WTN + nf * 8 + ((lane & 3) << 1);
            epi_pair<EPI>(acc[mf][nf][0], acc[mf][nf][1], mlo,     n, Nout, p0, p1, p2, p3);
            epi_pair<EPI>(acc[mf][nf][2], acc[mf][nf][3], mlo + 8, n, Nout, p0, p1, p2, p3);
        }
    }
}

// ============================================================================

extern "C" void kernel_launch(void* const* d_in, const int* in_sizes, int n_in,
                              void* d_out, int out_size)
{
    (void)in_sizes; (void)n_in; (void)out_size;
    const float* inputs = (const float*)d_in[0];
    const float* W      = (const float*)d_in[1];   // [D_OUT, D_IN]
    const float* V      = (const float*)d_in[2];   // [D_C, D_OUT]
    float* x = (float*)d_out;

    float *pE, *pG, *pT, *pa1, *pa2, *pu, *pb1, *pb2, *pWT, *pVT;
    cudaGetSymbolAddress((void**)&pE,  g_E);
    cudaGetSymbolAddress((void**)&pG,  g_G);
    cudaGetSymbolAddress((void**)&pT,  g_T);
    cudaGetSymbolAddress((void**)&pa1, g_a1);
    cudaGetSymbolAddress((void**)&pa2, g_a2);
    cudaGetSymbolAddress((void**)&pu,  g_u);
    cudaGetSymbolAddress((void**)&pb1, g_b1);
    cudaGetSymbolAddress((void**)&pb2, g_b2);
    cudaGetSymbolAddress((void**)&pWT, g_WT);
    cudaGetSymbolAddress((void**)&pVT, g_VT);

    constexpr int SM128 = 2 * (128 + 128) * 128;   // 65536
    constexpr int SM64  = 2 * (64 + 64) * 128;     // 32768
    cudaFuncSetAttribute(mma_gemm<128,128,0>, cudaFuncAttributeMaxDynamicSharedMemorySize, SM128);
    cudaFuncSetAttribute(mma_gemm<128,128,1>, cudaFuncAttributeMaxDynamicSharedMemorySize, SM128);
    cudaFuncSetAttribute(mma_gemm<128,128,2>, cudaFuncAttributeMaxDynamicSharedMemorySize, SM128);
    cudaFuncSetAttribute(mma_gemm<64, 64, 3>, cudaFuncAttributeMaxDynamicSharedMemorySize, SM64);

    const int TPB = 256;
    zero_kernel<<<(B_SZ * D_OUT + TPB - 1) / TPB, TPB>>>(x,   B_SZ * D_OUT);
    zero_kernel<<<(B_SZ * D_OUT + TPB - 1) / TPB, TPB>>>(pa1, B_SZ * D_OUT);
    zero_kernel<<<(B_SZ * D_OUT + TPB - 1) / TPB, TPB>>>(pa2, B_SZ * D_OUT);
    zero_kernel<<<(B_SZ * D_C   + TPB - 1) / TPB, TPB>>>(pu,  B_SZ * D_C);
    zero_kernel<<<(B_SZ * D_C   + TPB - 1) / TPB, TPB>>>(pb1, B_SZ * D_C);
    zero_kernel<<<(B_SZ * D_C   + TPB - 1) / TPB, TPB>>>(pb2, B_SZ * D_C);

    // W [2048,1024] -> WT [1024,2048]; V [256,2048] -> VT [2048,256]
    transpose_k<<<dim3(D_IN / 32,  D_OUT / 32), dim3(32, 8)>>>(W, pWT, D_OUT, D_IN);
    transpose_k<<<dim3(D_OUT / 32, D_C  / 32),  dim3(32, 8)>>>(V, pVT, D_C,  D_OUT);

    for (int s = 0; s < 10; s++) {
        // 1) E = inputs - x @ W        (B op = W^T [1024,2048] K-major)
        mma_gemm<128,128,0><<<dim3(D_IN / 128, B_SZ / 128), 256, SM128>>>(
            x, pWT, D_IN, D_OUT, D_OUT, D_OUT, inputs, pE, nullptr, nullptr);
        // 2) s = u @ V; G,T from old x (B op = V^T [2048,256] K-major)
        mma_gemm<128,128,1><<<dim3(D_OUT / 128, B_SZ / 128), 256, SM128>>>(
            pu, pVT, D_OUT, D_C, D_C, D_C, x, pG, pT, nullptr);
        // 3) gx = -2*E@W^T + T; rmsprop x (B op = W [2048,1024] K-major)
        mma_gemm<128,128,2><<<dim3(D_OUT / 128, B_SZ / 128), 256, SM128>>>(
            pE, W, D_OUT, D_IN, D_IN, D_IN, pT, x, pa1, pa2);
        // 4) gu = G @ V^T; rmsprop u   (B op = V [256,2048] K-major)
        mma_gemm<64,64,3><<<dim3(D_C / 64, B_SZ / 64), 256, SM64>>>(
            pG, V, D_C, D_OUT, D_OUT, D_OUT, nullptr, pu, pb1, pb2);
    }
}

// round 4
// speedup vs baseline: 3.4895x; 1.2445x over previous
#include <cuda_runtime.h>
#include <cuda_bf16.h>
#include <cstdint>
#include <math.h>

#define B_SZ  2048
#define D_IN  1024
#define D_OUT 2048
#define D_C   256

#define GAMMA_F 0.1f
#define RHO_F   0.9f
#define ONE_M_RHO_F 0.1f
#define LR_F    0.009f
#define MOM_F   0.9f
#define EPS_F   1e-8f

// ---- fp32 state ----
__device__ float g_T [B_SZ * D_OUT];
__device__ float g_a1[B_SZ * D_OUT];
__device__ float g_a2[B_SZ * D_OUT];
__device__ float g_u [B_SZ * D_C];
__device__ float g_b1[B_SZ * D_C];
__device__ float g_b2[B_SZ * D_C];
__device__ float g_WT[D_IN * D_OUT];
__device__ float g_VT[D_OUT * D_C];

// ---- packed bf16 hi/lo operands (1 uint32 per element; per 8-elem group:
//      4 words hi (bf16x2) then 4 words lo) ----
__device__ __align__(128) uint32_t g_pkW [D_OUT * D_IN];
__device__ __align__(128) uint32_t g_pkWT[D_IN * D_OUT];
__device__ __align__(128) uint32_t g_pkV [D_C * D_OUT];
__device__ __align__(128) uint32_t g_pkVT[D_OUT * D_C];
__device__ __align__(128) uint32_t g_pkX [B_SZ * D_OUT];
__device__ __align__(128) uint32_t g_pkU [B_SZ * D_C];
__device__ __align__(128) uint32_t g_pkE [B_SZ * D_IN];
__device__ __align__(128) uint32_t g_pkG [B_SZ * D_OUT];

__global__ void zero_kernel(float* __restrict__ p, int n) {
    int i = blockIdx.x * blockDim.x + threadIdx.x;
    if (i < n) p[i] = 0.0f;
}

__global__ void transpose_k(const float* __restrict__ src, float* __restrict__ dst,
                            int rows, int cols) {
    __shared__ float t[32][33];
    int bx = blockIdx.x * 32, by = blockIdx.y * 32;
    int x = bx + threadIdx.x;
    #pragma unroll
    for (int j = 0; j < 32; j += 8)
        t[threadIdx.y + j][threadIdx.x] = src[(size_t)(by + threadIdx.y + j) * cols + x];
    __syncthreads();
    int x2 = by + threadIdx.x;
    #pragma unroll
    for (int j = 0; j < 32; j += 8)
        dst[(size_t)(bx + threadIdx.y + j) * rows + x2] = t[threadIdx.x][threadIdx.y + j];
}

__device__ __forceinline__ void split2(float x, float y, uint32_t& hi, uint32_t& lo) {
    __nv_bfloat16 hx = __float2bfloat16(x);
    __nv_bfloat16 hy = __float2bfloat16(y);
    float rx = x - __bfloat162float(hx);
    float ry = y - __bfloat162float(hy);
    __nv_bfloat162 H; H.x = hx; H.y = hy;
    hi = *reinterpret_cast<uint32_t*>(&H);
    __nv_bfloat162 L = __floats2bfloat162_rn(rx, ry);
    lo = *reinterpret_cast<uint32_t*>(&L);
}

// pack fp32 -> hi/lo interleaved (one thread per 8-elem group)
__global__ void pack_k(const float* __restrict__ src, uint32_t* __restrict__ dst, int n8) {
    int i = blockIdx.x * blockDim.x + threadIdx.x;
    if (i >= n8) return;
    const float4* s = reinterpret_cast<const float4*>(src) + 2 * (size_t)i;
    float4 v0 = s[0], v1 = s[1];
    uint32_t h0,l0,h1,l1,h2,l2,h3,l3;
    split2(v0.x, v0.y, h0, l0); split2(v0.z, v0.w, h1, l1);
    split2(v1.x, v1.y, h2, l2); split2(v1.z, v1.w, h3, l3);
    uint4* d = reinterpret_cast<uint4*>(dst) + 2 * (size_t)i;
    uint4 H; H.x=h0; H.y=h1; H.z=h2; H.w=h3;
    uint4 L; L.x=l0; L.y=l1; L.z=l2; L.w=l3;
    d[0] = H; d[1] = L;
}

// fill packed array with a constant value (per 8-elem group)
__global__ void fill_pk_k(uint32_t* __restrict__ dst, float val, int n8) {
    int i = blockIdx.x * blockDim.x + threadIdx.x;
    if (i >= n8) return;
    uint32_t hi, lo; split2(val, val, hi, lo);
    uint4* d = reinterpret_cast<uint4*>(dst) + 2 * (size_t)i;
    uint4 H; H.x=hi; H.y=hi; H.z=hi; H.w=hi;
    uint4 L; L.x=lo; L.y=lo; L.z=lo; L.w=lo;
    d[0] = H; d[1] = L;
}

// ============================ mma helpers ============================

__device__ __forceinline__ uint32_t cvta_smem(const void* p) {
    uint32_t a;
    asm("{ .reg .u64 t; cvta.to.shared.u64 t, %1; cvt.u32.u64 %0, t; }" : "=r"(a) : "l"(p));
    return a;
}

__device__ __forceinline__ void mma_bf16(float* c, const uint32_t* a, const uint32_t* b) {
    asm volatile(
        "mma.sync.aligned.m16n8k16.row.col.f32.bf16.bf16.f32 "
        "{%0,%1,%2,%3}, {%4,%5,%6,%7}, {%8,%9}, {%0,%1,%2,%3};"
        : "+f"(c[0]), "+f"(c[1]), "+f"(c[2]), "+f"(c[3])
        : "r"(a[0]), "r"(a[1]), "r"(a[2]), "r"(a[3]), "r"(b[0]), "r"(b[1]));
}

#define LDSM_X4(R, addr) \
    asm volatile("ldmatrix.sync.aligned.m8n8.x4.shared.b16 {%0,%1,%2,%3}, [%4];" \
        : "=r"((R)[0]), "=r"((R)[1]), "=r"((R)[2]), "=r"((R)[3]) : "r"(addr))

#define CP16(dst, src) \
    asm volatile("cp.async.cg.shared.global [%0], [%1], 16;" :: "r"(dst), "l"(src))

// packed store of elements (m,n),(m,n+1); ncols = elements per row
__device__ __forceinline__ void store_pk2(uint32_t* __restrict__ q, int ncols,
                                          int m, int n, float v0, float v1) {
    uint32_t hi, lo; split2(v0, v1, hi, lo);
    uint32_t* p = q + (size_t)m * ncols + ((n >> 3) << 3) + ((n & 7) >> 1);
    p[0] = hi;
    p[4] = lo;
}

template<int EPI>
__device__ __forceinline__ void epi_pair(float a0, float a1, int m, int n, int Nout,
                                         const float* __restrict__ p0,
                                         float* __restrict__ p1,
                                         float* __restrict__ p2,
                                         float* __restrict__ p3,
                                         uint32_t* __restrict__ q1)
{
    const size_t idx = (size_t)m * (size_t)Nout + (size_t)n;
    if (EPI == 0) {
        float2 q = *reinterpret_cast<const float2*>(&p0[idx]);
        store_pk2(q1, Nout, m, n, q.x - a0, q.y - a1);          // packed E only
    } else if (EPI == 1) {
        float2 xv = *reinterpret_cast<const float2*>(&p0[idx]);
        float G0, G1; float2 T;
        {
            float da = sqrtf(xv.x * xv.x + 1e-6f);
            float ex = expf(-a0);
            G0  = GAMMA_F * da * (-0.5f * ex);
            T.x = (GAMMA_F * (1.0f + ex) * 0.5f + GAMMA_F * 0.1f) * (xv.x / da);
        }
        {
            float da = sqrtf(xv.y * xv.y + 1e-6f);
            float ex = expf(-a1);
            G1  = GAMMA_F * da * (-0.5f * ex);
            T.y = (GAMMA_F * (1.0f + ex) * 0.5f + GAMMA_F * 0.1f) * (xv.y / da);
        }
        store_pk2(q1, Nout, m, n, G0, G1);                       // packed G
        *reinterpret_cast<float2*>(&p2[idx]) = T;                // fp32 T
    } else {
        float2 g2;
        if (EPI == 2) {
            float2 t = *reinterpret_cast<const float2*>(&p0[idx]);
            g2.x = fmaf(-2.0f, a0, t.x);
            g2.y = fmaf(-2.0f, a1, t.y);
        } else {
            g2.x = a0; g2.y = a1;
        }
        float2 sv  = *reinterpret_cast<const float2*>(&p1[idx]);
        float2 a1v = *reinterpret_cast<const float2*>(&p2[idx]);
        float2 a2v = *reinterpret_cast<const float2*>(&p3[idx]);
        float na1x = RHO_F * a1v.x + ONE_M_RHO_F * g2.x * g2.x;
        float updx = LR_F * g2.x / sqrtf(na1x + EPS_F);
        float na2x = MOM_F * a2v.x - updx;
        float svx  = sv.x + MOM_F * na2x - updx;
        float na1y = RHO_F * a1v.y + ONE_M_RHO_F * g2.y * g2.y;
        float updy = LR_F * g2.y / sqrtf(na1y + EPS_F);
        float na2y = MOM_F * a2v.y - updy;
        float svy  = sv.y + MOM_F * na2y - updy;
        float2 o1; o1.x = svx;  o1.y = svy;
        float2 o2; o2.x = na1x; o2.y = na1y;
        float2 o3; o3.x = na2x; o3.y = na2y;
        *reinterpret_cast<float2*>(&p1[idx]) = o1;               // fp32 state
        store_pk2(q1, Nout, m, n, svx, svy);                     // packed copy
        *reinterpret_cast<float2*>(&p2[idx]) = o2;
        *reinterpret_cast<float2*>(&p3[idx]) = o3;
    }
}

// ============================================================================
// bf16x3 mma.sync GEMM, pre-packed operands, cp.async 4-stage pipeline.
// D[M,N] = A[M,K] * Bg[N,K]^T ; pkA/pkB hi/lo-interleaved (32B per 8 elems).
// SMEM row = 128B (BK=32 = 8 chunks of 16B), chunk swizzle c^(r&7).
// ============================================================================
template<int BM, int BN, int EPI>
__global__ __launch_bounds__(256, 1)
void mma_gemm(const uint32_t* __restrict__ pkA, const uint32_t* __restrict__ pkB,
              int Nout, int K,
              const float* __restrict__ p0, float* __restrict__ p1,
              float* __restrict__ p2, float* __restrict__ p3,
              uint32_t* __restrict__ q1)
{
    constexpr int S = 4;
    constexpr int WTM = BM / 2, WTN = BN / 4;
    constexpr int MF  = WTM / 16, NF = WTN / 8;
    constexpr int STAGE = (BM + BN) * 128;

    extern __shared__ __align__(1024) char smem[];
    const uint32_t sbase = cvta_smem(smem);

    const int tid  = threadIdx.x;
    const int lane = tid & 31, wid = tid >> 5;
    const int wm = wid >> 2, wn = wid & 3;
    const int row0 = blockIdx.y * BM;
    const int col0 = blockIdx.x * BN;

    const char* gA = reinterpret_cast<const char*>(pkA) + (size_t)row0 * (4 * K);
    const char* gB = reinterpret_cast<const char*>(pkB) + (size_t)col0 * (4 * K);
    const int pitch = 4 * K;
    const int iters = K / 32;

    auto issue = [&](int kt, int buf) {
        const uint32_t sd = sbase + buf * STAGE;
        const char* sA = gA + kt * 128;
        #pragma unroll
        for (int i = 0; i < BM * 8 / 256; i++) {
            int idx = i * 256 + tid;
            int r = idx >> 3, c = idx & 7;
            uint32_t dst = sd + r * 128 + ((c ^ (r & 7)) << 4);
            CP16(dst, sA + (size_t)r * pitch + (c << 4));
        }
        const char* sB = gB + kt * 128;
        #pragma unroll
        for (int i = 0; i < BN * 8 / 256; i++) {
            int idx = i * 256 + tid;
            int r = idx >> 3, c = idx & 7;
            uint32_t dst = sd + BM * 128 + r * 128 + ((c ^ (r & 7)) << 4);
            CP16(dst, sB + (size_t)r * pitch + (c << 4));
        }
        asm volatile("cp.async.commit_group;" ::: "memory");
    };

    float acc[MF][NF][4];
    #pragma unroll
    for (int i = 0; i < MF; i++)
        #pragma unroll
        for (int j = 0; j < NF; j++)
            #pragma unroll
            for (int r = 0; r < 4; r++) acc[i][j][r] = 0.0f;

    // prologue: S-1 stages in flight
    #pragma unroll
    for (int s = 0; s < S - 1; s++) issue(s, s);

    for (int kt = 0; kt < iters; kt++) {
        const int rem = iters - 1 - kt;
        if (rem >= S - 2)      asm volatile("cp.async.wait_group 2;" ::: "memory");
        else if (rem == 1)     asm volatile("cp.async.wait_group 1;" ::: "memory");
        else                   asm volatile("cp.async.wait_group 0;" ::: "memory");
        __syncthreads();
        if (kt + S - 1 < iters) issue(kt + S - 1, (kt + S - 1) % S);

        const int buf = kt % S;
        const uint32_t sA32 = sbase + buf * STAGE;
        const uint32_t sB32 = sA32 + BM * 128;

        #pragma unroll
        for (int j = 0; j < 2; j++) {
            uint32_t af[2][MF][4];
            #pragma unroll
            for (int hl = 0; hl < 2; hl++)
                #pragma unroll
                for (int mf = 0; mf < MF; mf++) {
                    int rr = wm * WTM + mf * 16 + (lane & 15);
                    int c  = 4 * j + hl + 2 * (lane >> 4);
                    uint32_t addr = sA32 + rr * 128 + ((c ^ (rr & 7)) << 4);
                    LDSM_X4(af[hl][mf], addr);
                }
            uint32_t bfr[2][NF][2];
            #pragma unroll
            for (int hl = 0; hl < 2; hl++)
                #pragma unroll
                for (int p = 0; p < NF / 2; p++) {
                    uint32_t q[4];
                    int rr = wn * WTN + (2 * p + (lane >> 4)) * 8 + (lane & 7);
                    int c  = 4 * j + hl + 2 * ((lane >> 3) & 1);
                    uint32_t addr = sB32 + rr * 128 + ((c ^ (rr & 7)) << 4);
                    LDSM_X4(q, addr);
                    bfr[hl][2 * p    ][0] = q[0]; bfr[hl][2 * p    ][1] = q[1];
                    bfr[hl][2 * p + 1][0] = q[2]; bfr[hl][2 * p + 1][1] = q[3];
                }
            #pragma unroll
            for (int mf = 0; mf < MF; mf++)
                #pragma unroll
                for (int nf = 0; nf < NF; nf++) {
                    mma_bf16(acc[mf][nf], af[0][mf], bfr[0][nf]);   // hi*hi
                    mma_bf16(acc[mf][nf], af[0][mf], bfr[1][nf]);   // hi*lo
                    mma_bf16(acc[mf][nf], af[1][mf], bfr[0][nf]);   // lo*hi
                }
        }
        __syncthreads();
    }

    #pragma unroll
    for (int mf = 0; mf < MF; mf++) {
        #pragma unroll
        for (int nf = 0; nf < NF; nf++) {
            int mlo = row0 + wm * WTM + mf * 16 + (lane >> 2);
            int n   = col0 + wn * WTN + nf * 8 + ((lane & 3) << 1);
            epi_pair<EPI>(acc[mf][nf][0], acc[mf][nf][1], mlo,     n, Nout, p0, p1, p2, p3, q1);
            epi_pair<EPI>(acc[mf][nf][2], acc[mf][nf][3], mlo + 8, n, Nout, p0, p1, p2, p3, q1);
        }
    }
}

// ============================================================================

extern "C" void kernel_launch(void* const* d_in, const int* in_sizes, int n_in,
                              void* d_out, int out_size)
{
    (void)in_sizes; (void)n_in; (void)out_size;
    const float* inputs = (const float*)d_in[0];
    const float* W      = (const float*)d_in[1];
    const float* V      = (const float*)d_in[2];
    float* x = (float*)d_out;

    float *pT, *pa1, *pa2, *pu, *pb1, *pb2, *pWT, *pVT;
    uint32_t *kW, *kWT, *kV, *kVT, *kX, *kU, *kE, *kG;
    cudaGetSymbolAddress((void**)&pT,  g_T);
    cudaGetSymbolAddress((void**)&pa1, g_a1);
    cudaGetSymbolAddress((void**)&pa2, g_a2);
    cudaGetSymbolAddress((void**)&pu,  g_u);
    cudaGetSymbolAddress((void**)&pb1, g_b1);
    cudaGetSymbolAddress((void**)&pb2, g_b2);
    cudaGetSymbolAddress((void**)&pWT, g_WT);
    cudaGetSymbolAddress((void**)&pVT, g_VT);
    cudaGetSymbolAddress((void**)&kW,  g_pkW);
    cudaGetSymbolAddress((void**)&kWT, g_pkWT);
    cudaGetSymbolAddress((void**)&kV,  g_pkV);
    cudaGetSymbolAddress((void**)&kVT, g_pkVT);
    cudaGetSymbolAddress((void**)&kX,  g_pkX);
    cudaGetSymbolAddress((void**)&kU,  g_pkU);
    cudaGetSymbolAddress((void**)&kE,  g_pkE);
    cudaGetSymbolAddress((void**)&kG,  g_pkG);

    constexpr int SM128 = 4 * (128 + 128) * 128;   // 131072
    constexpr int SM64  = 4 * (64 + 64) * 128;     //  65536
    cudaFuncSetAttribute(mma_gemm<128,128,0>, cudaFuncAttributeMaxDynamicSharedMemorySize, SM128);
    cudaFuncSetAttribute(mma_gemm<128,128,1>, cudaFuncAttributeMaxDynamicSharedMemorySize, SM128);
    cudaFuncSetAttribute(mma_gemm<128,128,2>, cudaFuncAttributeMaxDynamicSharedMemorySize, SM128);
    cudaFuncSetAttribute(mma_gemm<64, 64, 3>, cudaFuncAttributeMaxDynamicSharedMemorySize, SM64);

    const int TPB = 256;
    // zero fp32 state
    zero_kernel<<<(B_SZ * D_OUT + TPB - 1) / TPB, TPB>>>(x,   B_SZ * D_OUT);
    zero_kernel<<<(B_SZ * D_OUT + TPB - 1) / TPB, TPB>>>(pa1, B_SZ * D_OUT);
    zero_kernel<<<(B_SZ * D_OUT + TPB - 1) / TPB, TPB>>>(pa2, B_SZ * D_OUT);
    zero_kernel<<<(B_SZ * D_OUT + TPB - 1) / TPB, TPB>>>(pT,  B_SZ * D_OUT);  // step0 T = 0
    zero_kernel<<<(B_SZ * D_C   + TPB - 1) / TPB, TPB>>>(pu,  B_SZ * D_C);
    zero_kernel<<<(B_SZ * D_C   + TPB - 1) / TPB, TPB>>>(pb1, B_SZ * D_C);
    zero_kernel<<<(B_SZ * D_C   + TPB - 1) / TPB, TPB>>>(pb2, B_SZ * D_C);

    // transpose + pack weights
    transpose_k<<<dim3(D_IN / 32,  D_OUT / 32), dim3(32, 8)>>>(W, pWT, D_OUT, D_IN);
    transpose_k<<<dim3(D_OUT / 32, D_C  / 32),  dim3(32, 8)>>>(V, pVT, D_C,  D_OUT);
    pack_k<<<(D_OUT * D_IN / 8 + TPB - 1) / TPB, TPB>>>(W,   kW,  D_OUT * D_IN / 8);
    pack_k<<<(D_IN * D_OUT / 8 + TPB - 1) / TPB, TPB>>>(pWT, kWT, D_IN * D_OUT / 8);
    pack_k<<<(D_C * D_OUT / 8 + TPB - 1) / TPB, TPB>>>(V,   kV,  D_C * D_OUT / 8);
    pack_k<<<(D_OUT * D_C / 8 + TPB - 1) / TPB, TPB>>>(pVT, kVT, D_OUT * D_C / 8);

    // ---- step 0 shortcuts: x=0, u=0 -> E = inputs ; G = const ; T = 0 ----
    pack_k<<<(B_SZ * D_IN / 8 + TPB - 1) / TPB, TPB>>>(inputs, kE, B_SZ * D_IN / 8);
    {
        const float da0 = sqrtf(1e-6f);
        const float g0  = GAMMA_F * da0 * (-0.5f);  // exp(0)=1
        fill_pk_k<<<(B_SZ * D_OUT / 8 + TPB - 1) / TPB, TPB>>>(kG, g0, B_SZ * D_OUT / 8);
    }

    for (int s = 0; s < 10; s++) {
        if (s > 0) {
            // 1) E = inputs - x @ W        (A=pkX, B=pkWT)
            mma_gemm<128,128,0><<<dim3(D_IN / 128, B_SZ / 128), 256, SM128>>>(
                kX, kWT, D_IN, D_OUT, inputs, nullptr, nullptr, nullptr, kE);
            // 2) s = u @ V; G,T from old x (A=pkU, B=pkVT)
            mma_gemm<128,128,1><<<dim3(D_OUT / 128, B_SZ / 128), 256, SM128>>>(
                kU, kVT, D_OUT, D_C, x, nullptr, pT, nullptr, kG);
        }
        // 3) gx = -2*E@W^T + T; rmsprop x  (A=pkE, B=pkW)
        mma_gemm<128,128,2><<<dim3(D_OUT / 128, B_SZ / 128), 256, SM128>>>(
            kE, kW, D_OUT, D_IN, pT, x, pa1, pa2, kX);
        // 4) gu = G @ V^T; rmsprop u       (A=pkG, B=pkV)
        mma_gemm<64,64,3><<<dim3(D_C / 64, B_SZ / 64), 256, SM64>>>(
            kG, kV, D_C, D_OUT, nullptr, pu, pb1, pb2, kU);
    }
}

// round 5
// speedup vs baseline: 3.6217x; 1.0379x over previous
#include <cuda_runtime.h>
#include <cuda_bf16.h>
#include <cstdint>
#include <math.h>

#define B_SZ  2048
#define D_IN  1024
#define D_OUT 2048
#define D_C   256

#define GAMMA_F 0.1f
#define RHO_F   0.9f
#define ONE_M_RHO_F 0.1f
#define LR_F    0.009f
#define MOM_F   0.9f
#define EPS_F   1e-8f

// ---- fp32 state / scratch ----
__device__ float g_T  [B_SZ * D_OUT];
__device__ float g_a1 [B_SZ * D_OUT];
__device__ float g_a2 [B_SZ * D_OUT];
__device__ float g_u  [B_SZ * D_C];
__device__ float g_b1 [B_SZ * D_C];
__device__ float g_b2 [B_SZ * D_C];
__device__ float g_VT [D_OUT * D_C];
__device__ float g_c  [B_SZ * D_OUT];     // -2 * inputs @ W^T
__device__ float g_vs [D_C];              // rowsum of V

// ---- packed bf16 hi/lo operands (per 8-elem group: 4 hi words then 4 lo) ----
__device__ __align__(128) uint32_t g_pkW [D_OUT * D_IN];
__device__ __align__(128) uint32_t g_pkV [D_C * D_OUT];
__device__ __align__(128) uint32_t g_pkVT[D_OUT * D_C];
__device__ __align__(128) uint32_t g_pkIn[B_SZ * D_IN];
__device__ __align__(128) uint32_t g_pkM [D_OUT * D_OUT];   // 2*W@W^T
__device__ __align__(128) uint32_t g_pkG [B_SZ * D_OUT];
__device__ __align__(128) uint32_t g_pkX0[B_SZ * D_OUT];
__device__ __align__(128) uint32_t g_pkX1[B_SZ * D_OUT];
__device__ __align__(128) uint32_t g_pkU0[B_SZ * D_C];
__device__ __align__(128) uint32_t g_pkU1[B_SZ * D_C];

__device__ __forceinline__ void split2(float x, float y, uint32_t& hi, uint32_t& lo) {
    __nv_bfloat16 hx = __float2bfloat16(x);
    __nv_bfloat16 hy = __float2bfloat16(y);
    float rx = x - __bfloat162float(hx);
    float ry = y - __bfloat162float(hy);
    __nv_bfloat162 H; H.x = hx; H.y = hy;
    hi = *reinterpret_cast<uint32_t*>(&H);
    __nv_bfloat162 L = __floats2bfloat162_rn(rx, ry);
    lo = *reinterpret_cast<uint32_t*>(&L);
}

__global__ void transpose_k(const float* __restrict__ src, float* __restrict__ dst,
                            int rows, int cols) {
    __shared__ float t[32][33];
    int bx = blockIdx.x * 32, by = blockIdx.y * 32;
    int x = bx + threadIdx.x;
    #pragma unroll
    for (int j = 0; j < 32; j += 8)
        t[threadIdx.y + j][threadIdx.x] = src[(size_t)(by + threadIdx.y + j) * cols + x];
    __syncthreads();
    int x2 = by + threadIdx.x;
    #pragma unroll
    for (int j = 0; j < 32; j += 8)
        dst[(size_t)(bx + threadIdx.y + j) * rows + x2] = t[threadIdx.x][threadIdx.y + j];
}

__global__ void pack_k(const float* __restrict__ src, uint32_t* __restrict__ dst, int n8) {
    int i = blockIdx.x * blockDim.x + threadIdx.x;
    if (i >= n8) return;
    const float4* s = reinterpret_cast<const float4*>(src) + 2 * (size_t)i;
    float4 v0 = s[0], v1 = s[1];
    uint32_t h0,l0,h1,l1,h2,l2,h3,l3;
    split2(v0.x, v0.y, h0, l0); split2(v0.z, v0.w, h1, l1);
    split2(v1.x, v1.y, h2, l2); split2(v1.z, v1.w, h3, l3);
    uint4* d = reinterpret_cast<uint4*>(dst) + 2 * (size_t)i;
    uint4 H; H.x=h0; H.y=h1; H.z=h2; H.w=h3;
    uint4 L; L.x=l0; L.y=l1; L.z=l2; L.w=l3;
    d[0] = H; d[1] = L;
}

// rowsum of V: out[n] = sum_k V[n,k], V [D_C, D_OUT]
__global__ void vsum_k(const float* __restrict__ V, float* __restrict__ out) {
    __shared__ float red[256];
    int n = blockIdx.x;
    float s = 0.0f;
    for (int k = threadIdx.x; k < D_OUT; k += 256) s += V[(size_t)n * D_OUT + k];
    red[threadIdx.x] = s;
    __syncthreads();
    for (int st = 128; st > 0; st >>= 1) {
        if (threadIdx.x < st) red[threadIdx.x] += red[threadIdx.x + st];
        __syncthreads();
    }
    if (threadIdx.x == 0) out[n] = red[0];
}

// rmsprop from zero state, 8 elems/thread; MODE 0: g = c[i]; MODE 1: g = G0*vs[i%256]
template<int MODE>
__global__ void step0_k(const float* __restrict__ src, float* __restrict__ s,
                        float* __restrict__ a1, float* __restrict__ a2,
                        uint32_t* __restrict__ pk, int n8) {
    int i = blockIdx.x * blockDim.x + threadIdx.x;
    if (i >= n8) return;
    float gv[8];
    if (MODE == 0) {
        const float4* cs = reinterpret_cast<const float4*>(src) + 2 * (size_t)i;
        float4 v0 = cs[0], v1 = cs[1];
        gv[0]=v0.x; gv[1]=v0.y; gv[2]=v0.z; gv[3]=v0.w;
        gv[4]=v1.x; gv[5]=v1.y; gv[6]=v1.z; gv[7]=v1.w;
    } else {
        const float G0 = GAMMA_F * 1.0e-3f * (-0.5f);   // gamma*sqrt(1e-6)*(-0.5)
        int base = (8 * i) & (D_C - 1);
        #pragma unroll
        for (int j = 0; j < 8; j++) gv[j] = G0 * src[base + j];
    }
    float xs[8], A1[8], A2[8];
    #pragma unroll
    for (int j = 0; j < 8; j++) {
        float g   = gv[j];
        float na1 = ONE_M_RHO_F * g * g;
        float upd = LR_F * g / sqrtf(na1 + EPS_F);
        float na2 = -upd;
        xs[j] = MOM_F * na2 - upd;
        A1[j] = na1; A2[j] = na2;
    }
    float4* so = reinterpret_cast<float4*>(s)  + 2 * (size_t)i;
    float4* o1 = reinterpret_cast<float4*>(a1) + 2 * (size_t)i;
    float4* o2 = reinterpret_cast<float4*>(a2) + 2 * (size_t)i;
    so[0] = make_float4(xs[0],xs[1],xs[2],xs[3]); so[1] = make_float4(xs[4],xs[5],xs[6],xs[7]);
    o1[0] = make_float4(A1[0],A1[1],A1[2],A1[3]); o1[1] = make_float4(A1[4],A1[5],A1[6],A1[7]);
    o2[0] = make_float4(A2[0],A2[1],A2[2],A2[3]); o2[1] = make_float4(A2[4],A2[5],A2[6],A2[7]);
    uint32_t h[4], l[4];
    split2(xs[0],xs[1],h[0],l[0]); split2(xs[2],xs[3],h[1],l[1]);
    split2(xs[4],xs[5],h[2],l[2]); split2(xs[6],xs[7],h[3],l[3]);
    uint4* d = reinterpret_cast<uint4*>(pk) + 2 * (size_t)i;
    uint4 H; H.x=h[0]; H.y=h[1]; H.z=h[2]; H.w=h[3];
    uint4 L; L.x=l[0]; L.y=l[1]; L.z=l[2]; L.w=l[3];
    d[0] = H; d[1] = L;
}

// ============================ mma helpers ============================

__device__ __forceinline__ uint32_t cvta_smem(const void* p) {
    uint32_t a;
    asm("{ .reg .u64 t; cvta.to.shared.u64 t, %1; cvt.u32.u64 %0, t; }" : "=r"(a) : "l"(p));
    return a;
}

__device__ __forceinline__ void mma_bf16(float* c, const uint32_t* a, const uint32_t* b) {
    asm volatile(
        "mma.sync.aligned.m16n8k16.row.col.f32.bf16.bf16.f32 "
        "{%0,%1,%2,%3}, {%4,%5,%6,%7}, {%8,%9}, {%0,%1,%2,%3};"
        : "+f"(c[0]), "+f"(c[1]), "+f"(c[2]), "+f"(c[3])
        : "r"(a[0]), "r"(a[1]), "r"(a[2]), "r"(a[3]), "r"(b[0]), "r"(b[1]));
}

#define LDSM_X4(R, addr) \
    asm volatile("ldmatrix.sync.aligned.m8n8.x4.shared.b16 {%0,%1,%2,%3}, [%4];" \
        : "=r"((R)[0]), "=r"((R)[1]), "=r"((R)[2]), "=r"((R)[3]) : "r"(addr))

#define CP16(dst, src) \
    asm volatile("cp.async.cg.shared.global [%0], [%1], 16;" :: "r"(dst), "l"(src))

__device__ __forceinline__ void store_pk2(uint32_t* __restrict__ q, int ncols,
                                          int m, int n, float v0, float v1) {
    uint32_t hi, lo; split2(v0, v1, hi, lo);
    uint32_t* p = q + (size_t)m * ncols + ((n >> 3) << 3) + ((n & 7) >> 1);
    p[0] = hi;
    p[4] = lo;
}

// EPI 1: GEMM2 (s=u@V): reads p0=x; writes q1=pkG, p2=T
// EPI 2: GEMM3' (gx GEMM): g = acc + p4(c) + p0(T); rmsprop p1=x,p2=a1,p3=a2; q1=pkX
// EPI 3: GEMM4 (gu): g = acc; rmsprop p1=u,p2=b1,p3=b2; q1=pkU
// EPI 4: setup M2: pack 2*acc -> q1
// EPI 5: setup c:  p1 = -2*acc
template<int EPI>
__device__ __forceinline__ void epi_pair(float a0, float a1, int m, int n, int Nout,
                                         const float* __restrict__ p0,
                                         const float* __restrict__ p4,
                                         float* __restrict__ p1,
                                         float* __restrict__ p2,
                                         float* __restrict__ p3,
                                         uint32_t* __restrict__ q1)
{
    const size_t idx = (size_t)m * (size_t)Nout + (size_t)n;
    if (EPI == 4) {
        store_pk2(q1, Nout, m, n, 2.0f * a0, 2.0f * a1);
    } else if (EPI == 5) {
        float2 o; o.x = -2.0f * a0; o.y = -2.0f * a1;
        *reinterpret_cast<float2*>(&p1[idx]) = o;
    } else if (EPI == 1) {
        float2 xv = *reinterpret_cast<const float2*>(&p0[idx]);
        float G0, G1; float2 T;
        {
            float da = sqrtf(xv.x * xv.x + 1e-6f);
            float ex = expf(-a0);
            G0  = GAMMA_F * da * (-0.5f * ex);
            T.x = (GAMMA_F * (1.0f + ex) * 0.5f + GAMMA_F * 0.1f) * (xv.x / da);
        }
        {
            float da = sqrtf(xv.y * xv.y + 1e-6f);
            float ex = expf(-a1);
            G1  = GAMMA_F * da * (-0.5f * ex);
            T.y = (GAMMA_F * (1.0f + ex) * 0.5f + GAMMA_F * 0.1f) * (xv.y / da);
        }
        store_pk2(q1, Nout, m, n, G0, G1);
        *reinterpret_cast<float2*>(&p2[idx]) = T;
    } else {
        float2 g2;
        if (EPI == 2) {
            float2 tv = *reinterpret_cast<const float2*>(&p0[idx]);
            float2 cv = *reinterpret_cast<const float2*>(&p4[idx]);
            g2.x = a0 + cv.x + tv.x;
            g2.y = a1 + cv.y + tv.y;
        } else {
            g2.x = a0; g2.y = a1;
        }
        float2 sv  = *reinterpret_cast<const float2*>(&p1[idx]);
        float2 a1v = *reinterpret_cast<const float2*>(&p2[idx]);
        float2 a2v = *reinterpret_cast<const float2*>(&p3[idx]);
        float na1x = RHO_F * a1v.x + ONE_M_RHO_F * g2.x * g2.x;
        float updx = LR_F * g2.x / sqrtf(na1x + EPS_F);
        float na2x = MOM_F * a2v.x - updx;
        float svx  = sv.x + MOM_F * na2x - updx;
        float na1y = RHO_F * a1v.y + ONE_M_RHO_F * g2.y * g2.y;
        float updy = LR_F * g2.y / sqrtf(na1y + EPS_F);
        float na2y = MOM_F * a2v.y - updy;
        float svy  = sv.y + MOM_F * na2y - updy;
        float2 o1; o1.x = svx;  o1.y = svy;
        float2 o2; o2.x = na1x; o2.y = na1y;
        float2 o3; o3.x = na2x; o3.y = na2y;
        *reinterpret_cast<float2*>(&p1[idx]) = o1;
        store_pk2(q1, Nout, m, n, svx, svy);
        *reinterpret_cast<float2*>(&p2[idx]) = o2;
        *reinterpret_cast<float2*>(&p3[idx]) = o3;
    }
}

// ============================================================================
// bf16x3 mma.sync GEMM, pre-packed operands, cp.async 4-stage pipeline.
// D[M,N] = A[M,K] * Bg[N,K]^T ; pkA/pkB hi/lo-interleaved (32B per 8 elems).
// ============================================================================
template<int BM, int BN, int EPI>
__global__ __launch_bounds__(256, 1)
void mma_gemm(const uint32_t* __restrict__ pkA, const uint32_t* __restrict__ pkB,
              int Nout, int K,
              const float* __restrict__ p0, const float* __restrict__ p4,
              float* __restrict__ p1, float* __restrict__ p2, float* __restrict__ p3,
              uint32_t* __restrict__ q1)
{
    constexpr int S = 4;
    constexpr int WTM = BM / 2, WTN = BN / 4;
    constexpr int MF  = WTM / 16, NF = WTN / 8;
    constexpr int STAGE = (BM + BN) * 128;

    extern __shared__ __align__(1024) char smem[];
    const uint32_t sbase = cvta_smem(smem);

    const int tid  = threadIdx.x;
    const int lane = tid & 31, wid = tid >> 5;
    const int wm = wid >> 2, wn = wid & 3;
    const int row0 = blockIdx.y * BM;
    const int col0 = blockIdx.x * BN;

    const char* gA = reinterpret_cast<const char*>(pkA) + (size_t)row0 * (4 * K);
    const char* gB = reinterpret_cast<const char*>(pkB) + (size_t)col0 * (4 * K);
    const int pitch = 4 * K;
    const int iters = K / 32;

    auto issue = [&](int kt, int buf) {
        const uint32_t sd = sbase + buf * STAGE;
        const char* sA = gA + kt * 128;
        #pragma unroll
        for (int i = 0; i < BM * 8 / 256; i++) {
            int idx = i * 256 + tid;
            int r = idx >> 3, c = idx & 7;
            uint32_t dst = sd + r * 128 + ((c ^ (r & 7)) << 4);
            CP16(dst, sA + (size_t)r * pitch + (c << 4));
        }
        const char* sB = gB + kt * 128;
        #pragma unroll
        for (int i = 0; i < BN * 8 / 256; i++) {
            int idx = i * 256 + tid;
            int r = idx >> 3, c = idx & 7;
            uint32_t dst = sd + BM * 128 + r * 128 + ((c ^ (r & 7)) << 4);
            CP16(dst, sB + (size_t)r * pitch + (c << 4));
        }
        asm volatile("cp.async.commit_group;" ::: "memory");
    };

    float acc[MF][NF][4];
    #pragma unroll
    for (int i = 0; i < MF; i++)
        #pragma unroll
        for (int j = 0; j < NF; j++)
            #pragma unroll
            for (int r = 0; r < 4; r++) acc[i][j][r] = 0.0f;

    #pragma unroll
    for (int s = 0; s < S - 1; s++) issue(s, s);

    for (int kt = 0; kt < iters; kt++) {
        const int rem = iters - 1 - kt;
        if (rem >= S - 2)      asm volatile("cp.async.wait_group 2;" ::: "memory");
        else if (rem == 1)     asm volatile("cp.async.wait_group 1;" ::: "memory");
        else                   asm volatile("cp.async.wait_group 0;" ::: "memory");
        __syncthreads();
        if (kt + S - 1 < iters) issue(kt + S - 1, (kt + S - 1) % S);

        const int buf = kt % S;
        const uint32_t sA32 = sbase + buf * STAGE;
        const uint32_t sB32 = sA32 + BM * 128;

        #pragma unroll
        for (int j = 0; j < 2; j++) {
            uint32_t af[2][MF][4];
            #pragma unroll
            for (int hl = 0; hl < 2; hl++)
                #pragma unroll
                for (int mf = 0; mf < MF; mf++) {
                    int rr = wm * WTM + mf * 16 + (lane & 15);
                    int c  = 4 * j + hl + 2 * (lane >> 4);
                    uint32_t addr = sA32 + rr * 128 + ((c ^ (rr & 7)) << 4);
                    LDSM_X4(af[hl][mf], addr);
                }
            uint32_t bfr[2][NF][2];
            #pragma unroll
            for (int hl = 0; hl < 2; hl++)
                #pragma unroll
                for (int p = 0; p < NF / 2; p++) {
                    uint32_t q[4];
                    int rr = wn * WTN + (2 * p + (lane >> 4)) * 8 + (lane & 7);
                    int c  = 4 * j + hl + 2 * ((lane >> 3) & 1);
                    uint32_t addr = sB32 + rr * 128 + ((c ^ (rr & 7)) << 4);
                    LDSM_X4(q, addr);
                    bfr[hl][2 * p    ][0] = q[0]; bfr[hl][2 * p    ][1] = q[1];
                    bfr[hl][2 * p + 1][0] = q[2]; bfr[hl][2 * p + 1][1] = q[3];
                }
            #pragma unroll
            for (int mf = 0; mf < MF; mf++)
                #pragma unroll
                for (int nf = 0; nf < NF; nf++) {
                    mma_bf16(acc[mf][nf], af[0][mf], bfr[0][nf]);
                    mma_bf16(acc[mf][nf], af[0][mf], bfr[1][nf]);
                    mma_bf16(acc[mf][nf], af[1][mf], bfr[0][nf]);
                }
        }
        __syncthreads();
    }

    #pragma unroll
    for (int mf = 0; mf < MF; mf++) {
        #pragma unroll
        for (int nf = 0; nf < NF; nf++) {
            int mlo = row0 + wm * WTM + mf * 16 + (lane >> 2);
            int n   = col0 + wn * WTN + nf * 8 + ((lane & 3) << 1);
            epi_pair<EPI>(acc[mf][nf][0], acc[mf][nf][1], mlo,     n, Nout, p0, p4, p1, p2, p3, q1);
            epi_pair<EPI>(acc[mf][nf][2], acc[mf][nf][3], mlo + 8, n, Nout, p0, p4, p1, p2, p3, q1);
        }
    }
}

// ============================================================================

extern "C" void kernel_launch(void* const* d_in, const int* in_sizes, int n_in,
                              void* d_out, int out_size)
{
    (void)in_sizes; (void)n_in; (void)out_size;
    const float* inputs = (const float*)d_in[0];
    const float* W      = (const float*)d_in[1];
    const float* V      = (const float*)d_in[2];
    float* x = (float*)d_out;

    float *pT, *pa1, *pa2, *pu, *pb1, *pb2, *pVT, *pc, *pvs;
    uint32_t *kW, *kV, *kVT, *kIn, *kM, *kG, *kX[2], *kU[2];
    cudaGetSymbolAddress((void**)&pT,  g_T);
    cudaGetSymbolAddress((void**)&pa1, g_a1);
    cudaGetSymbolAddress((void**)&pa2, g_a2);
    cudaGetSymbolAddress((void**)&pu,  g_u);
    cudaGetSymbolAddress((void**)&pb1, g_b1);
    cudaGetSymbolAddress((void**)&pb2, g_b2);
    cudaGetSymbolAddress((void**)&pVT, g_VT);
    cudaGetSymbolAddress((void**)&pc,  g_c);
    cudaGetSymbolAddress((void**)&pvs, g_vs);
    cudaGetSymbolAddress((void**)&kW,  g_pkW);
    cudaGetSymbolAddress((void**)&kV,  g_pkV);
    cudaGetSymbolAddress((void**)&kVT, g_pkVT);
    cudaGetSymbolAddress((void**)&kIn, g_pkIn);
    cudaGetSymbolAddress((void**)&kM,  g_pkM);
    cudaGetSymbolAddress((void**)&kG,  g_pkG);
    cudaGetSymbolAddress((void**)&kX[0], g_pkX0);
    cudaGetSymbolAddress((void**)&kX[1], g_pkX1);
    cudaGetSymbolAddress((void**)&kU[0], g_pkU0);
    cudaGetSymbolAddress((void**)&kU[1], g_pkU1);

    constexpr int SM128 = 4 * (128 + 128) * 128;   // 131072
    constexpr int SM64  = 4 * (64 + 64) * 128;     //  65536
    cudaFuncSetAttribute(mma_gemm<128,128,1>, cudaFuncAttributeMaxDynamicSharedMemorySize, SM128);
    cudaFuncSetAttribute(mma_gemm<128,128,2>, cudaFuncAttributeMaxDynamicSharedMemorySize, SM128);
    cudaFuncSetAttribute(mma_gemm<64, 64, 3>, cudaFuncAttributeMaxDynamicSharedMemorySize, SM64);
    cudaFuncSetAttribute(mma_gemm<128,128,4>, cudaFuncAttributeMaxDynamicSharedMemorySize, SM128);
    cudaFuncSetAttribute(mma_gemm<128,128,5>, cudaFuncAttributeMaxDynamicSharedMemorySize, SM128);

    const int TPB = 256;

    // ---- setup: transpose/pack, M2 = 2*W@W^T, c = -2*inputs@W^T ----
    transpose_k<<<dim3(D_OUT / 32, D_C / 32), dim3(32, 8)>>>(V, pVT, D_C, D_OUT);
    pack_k<<<(D_OUT * D_IN / 8 + TPB - 1) / TPB, TPB>>>(W,      kW,  D_OUT * D_IN / 8);
    pack_k<<<(D_C * D_OUT / 8 + TPB - 1) / TPB, TPB>>>(V,       kV,  D_C * D_OUT / 8);
    pack_k<<<(D_OUT * D_C / 8 + TPB - 1) / TPB, TPB>>>(pVT,     kVT, D_OUT * D_C / 8);
    pack_k<<<(B_SZ * D_IN / 8 + TPB - 1) / TPB, TPB>>>(inputs,  kIn, B_SZ * D_IN / 8);

    // M2[m,n] = 2*sum_k W[m,k]W[n,k]   (A=W, Bg=W)
    mma_gemm<128,128,4><<<dim3(D_OUT / 128, D_OUT / 128), 256, SM128>>>(
        kW, kW, D_OUT, D_IN, nullptr, nullptr, nullptr, nullptr, nullptr, kM);
    // c = -2 * inputs @ W^T            (A=inputs, Bg=W)
    mma_gemm<128,128,5><<<dim3(D_OUT / 128, B_SZ / 128), 256, SM128>>>(
        kIn, kW, D_OUT, D_IN, nullptr, nullptr, pc, nullptr, nullptr, nullptr);

    // ---- step 0: x from g=c ; u from g = G0 * rowsum(V) broadcast ----
    vsum_k<<<D_C, 256>>>(V, pvs);
    step0_k<0><<<(B_SZ * D_OUT / 8 + TPB - 1) / TPB, TPB>>>(
        pc, x, pa1, pa2, kX[0], B_SZ * D_OUT / 8);
    step0_k<1><<<(B_SZ * D_C / 8 + TPB - 1) / TPB, TPB>>>(
        pvs, pu, pb1, pb2, kU[0], B_SZ * D_C / 8);

    // ---- steps 1..9: 3 GEMMs per step ----
    for (int s = 1; s < 10; s++) {
        const int rd = (s - 1) & 1, wr = s & 1;
        // GEMM2: s = u@V ; G,T from current x   (A=pkU, Bg=pkVT)
        mma_gemm<128,128,1><<<dim3(D_OUT / 128, B_SZ / 128), 256, SM128>>>(
            kU[rd], kVT, D_OUT, D_C, x, nullptr, nullptr, pT, nullptr, kG);
        // GEMM3': gx = x@M2 + c + T ; rmsprop x (A=pkX, Bg=pkM symmetric)
        mma_gemm<128,128,2><<<dim3(D_OUT / 128, B_SZ / 128), 256, SM128>>>(
            kX[rd], kM, D_OUT, D_OUT, pT, pc, x, pa1, pa2, kX[wr]);
        // GEMM4: gu = G@V^T ; rmsprop u         (A=pkG, Bg=pkV)
        mma_gemm<64,64,3><<<dim3(D_C / 64, B_SZ / 64), 256, SM64>>>(
            kG, kV, D_C, D_OUT, nullptr, nullptr, pu, pb1, pb2, kU[wr]);
    }
}

// round 6
// speedup vs baseline: 4.0165x; 1.1090x over previous
#include <cuda_runtime.h>
#include <cuda_bf16.h>
#include <cstdint>
#include <math.h>

#define B_SZ  2048
#define D_IN  1024
#define D_OUT 2048
#define D_C   256

#define GAMMA_F 0.1f
#define RHO_F   0.9f
#define ONE_M_RHO_F 0.1f
#define LR_F    0.009f
#define MOM_F   0.9f
#define EPS_F   1e-8f

// ---- fp32 state / scratch ----
__device__ float g_T  [B_SZ * D_OUT];
__device__ float g_a1 [B_SZ * D_OUT];
__device__ float g_a2 [B_SZ * D_OUT];
__device__ float g_u  [B_SZ * D_C];
__device__ float g_b1 [B_SZ * D_C];
__device__ float g_b2 [B_SZ * D_C];
__device__ float g_VT [D_OUT * D_C];
__device__ float g_c  [B_SZ * D_OUT];     // -2 * inputs @ W^T
__device__ float g_vs [D_C];              // rowsum of V

// ---- packed bf16 hi/lo operands (per 8-elem group: 4 hi words then 4 lo) ----
__device__ __align__(128) uint32_t g_pkW [D_OUT * D_IN];
__device__ __align__(128) uint32_t g_pkV [D_C * D_OUT];
__device__ __align__(128) uint32_t g_pkVT[D_OUT * D_C];
__device__ __align__(128) uint32_t g_pkIn[B_SZ * D_IN];
__device__ __align__(128) uint32_t g_pkM [D_OUT * D_OUT];   // 2*W@W^T
__device__ __align__(128) uint32_t g_pkG [B_SZ * D_OUT];
__device__ __align__(128) uint32_t g_pkX0[B_SZ * D_OUT];
__device__ __align__(128) uint32_t g_pkX1[B_SZ * D_OUT];
__device__ __align__(128) uint32_t g_pkU0[B_SZ * D_C];
__device__ __align__(128) uint32_t g_pkU1[B_SZ * D_C];

__device__ __forceinline__ void split2(float x, float y, uint32_t& hi, uint32_t& lo) {
    __nv_bfloat16 hx = __float2bfloat16(x);
    __nv_bfloat16 hy = __float2bfloat16(y);
    float rx = x - __bfloat162float(hx);
    float ry = y - __bfloat162float(hy);
    __nv_bfloat162 H; H.x = hx; H.y = hy;
    hi = *reinterpret_cast<uint32_t*>(&H);
    __nv_bfloat162 L = __floats2bfloat162_rn(rx, ry);
    lo = *reinterpret_cast<uint32_t*>(&L);
}

__global__ void transpose_k(const float* __restrict__ src, float* __restrict__ dst,
                            int rows, int cols) {
    __shared__ float t[32][33];
    int bx = blockIdx.x * 32, by = blockIdx.y * 32;
    int x = bx + threadIdx.x;
    #pragma unroll
    for (int j = 0; j < 32; j += 8)
        t[threadIdx.y + j][threadIdx.x] = src[(size_t)(by + threadIdx.y + j) * cols + x];
    __syncthreads();
    int x2 = by + threadIdx.x;
    #pragma unroll
    for (int j = 0; j < 32; j += 8)
        dst[(size_t)(bx + threadIdx.y + j) * rows + x2] = t[threadIdx.x][threadIdx.y + j];
}

__global__ void pack_k(const float* __restrict__ src, uint32_t* __restrict__ dst, int n8) {
    int i = blockIdx.x * blockDim.x + threadIdx.x;
    if (i >= n8) return;
    const float4* s = reinterpret_cast<const float4*>(src) + 2 * (size_t)i;
    float4 v0 = s[0], v1 = s[1];
    uint32_t h0,l0,h1,l1,h2,l2,h3,l3;
    split2(v0.x, v0.y, h0, l0); split2(v0.z, v0.w, h1, l1);
    split2(v1.x, v1.y, h2, l2); split2(v1.z, v1.w, h3, l3);
    uint4* d = reinterpret_cast<uint4*>(dst) + 2 * (size_t)i;
    uint4 H; H.x=h0; H.y=h1; H.z=h2; H.w=h3;
    uint4 L; L.x=l0; L.y=l1; L.z=l2; L.w=l3;
    d[0] = H; d[1] = L;
}

__global__ void vsum_k(const float* __restrict__ V, float* __restrict__ out) {
    __shared__ float red[256];
    int n = blockIdx.x;
    float s = 0.0f;
    for (int k = threadIdx.x; k < D_OUT; k += 256) s += V[(size_t)n * D_OUT + k];
    red[threadIdx.x] = s;
    __syncthreads();
    for (int st = 128; st > 0; st >>= 1) {
        if (threadIdx.x < st) red[threadIdx.x] += red[threadIdx.x + st];
        __syncthreads();
    }
    if (threadIdx.x == 0) out[n] = red[0];
}

template<int MODE>
__global__ void step0_k(const float* __restrict__ src, float* __restrict__ s,
                        float* __restrict__ a1, float* __restrict__ a2,
                        uint32_t* __restrict__ pk, int n8) {
    int i = blockIdx.x * blockDim.x + threadIdx.x;
    if (i >= n8) return;
    float gv[8];
    if (MODE == 0) {
        const float4* cs = reinterpret_cast<const float4*>(src) + 2 * (size_t)i;
        float4 v0 = cs[0], v1 = cs[1];
        gv[0]=v0.x; gv[1]=v0.y; gv[2]=v0.z; gv[3]=v0.w;
        gv[4]=v1.x; gv[5]=v1.y; gv[6]=v1.z; gv[7]=v1.w;
    } else {
        const float G0 = GAMMA_F * 1.0e-3f * (-0.5f);
        int base = (8 * i) & (D_C - 1);
        #pragma unroll
        for (int j = 0; j < 8; j++) gv[j] = G0 * src[base + j];
    }
    float xs[8], A1[8], A2[8];
    #pragma unroll
    for (int j = 0; j < 8; j++) {
        float g   = gv[j];
        float na1 = ONE_M_RHO_F * g * g;
        float upd = LR_F * g / sqrtf(na1 + EPS_F);
        float na2 = -upd;
        xs[j] = MOM_F * na2 - upd;
        A1[j] = na1; A2[j] = na2;
    }
    float4* so = reinterpret_cast<float4*>(s)  + 2 * (size_t)i;
    float4* o1 = reinterpret_cast<float4*>(a1) + 2 * (size_t)i;
    float4* o2 = reinterpret_cast<float4*>(a2) + 2 * (size_t)i;
    so[0] = make_float4(xs[0],xs[1],xs[2],xs[3]); so[1] = make_float4(xs[4],xs[5],xs[6],xs[7]);
    o1[0] = make_float4(A1[0],A1[1],A1[2],A1[3]); o1[1] = make_float4(A1[4],A1[5],A1[6],A1[7]);
    o2[0] = make_float4(A2[0],A2[1],A2[2],A2[3]); o2[1] = make_float4(A2[4],A2[5],A2[6],A2[7]);
    uint32_t h[4], l[4];
    split2(xs[0],xs[1],h[0],l[0]); split2(xs[2],xs[3],h[1],l[1]);
    split2(xs[4],xs[5],h[2],l[2]); split2(xs[6],xs[7],h[3],l[3]);
    uint4* d = reinterpret_cast<uint4*>(pk) + 2 * (size_t)i;
    uint4 H; H.x=h[0]; H.y=h[1]; H.z=h[2]; H.w=h[3];
    uint4 L; L.x=l[0]; L.y=l[1]; L.z=l[2]; L.w=l[3];
    d[0] = H; d[1] = L;
}

// ============================ mma helpers ============================

__device__ __forceinline__ uint32_t cvta_smem(const void* p) {
    uint32_t a;
    asm("{ .reg .u64 t; cvta.to.shared.u64 t, %1; cvt.u32.u64 %0, t; }" : "=r"(a) : "l"(p));
    return a;
}

__device__ __forceinline__ void mma_bf16(float* c, const uint32_t* a, const uint32_t* b) {
    asm volatile(
        "mma.sync.aligned.m16n8k16.row.col.f32.bf16.bf16.f32 "
        "{%0,%1,%2,%3}, {%4,%5,%6,%7}, {%8,%9}, {%0,%1,%2,%3};"
        : "+f"(c[0]), "+f"(c[1]), "+f"(c[2]), "+f"(c[3])
        : "r"(a[0]), "r"(a[1]), "r"(a[2]), "r"(a[3]), "r"(b[0]), "r"(b[1]));
}

#define LDSM_X4(R, addr) \
    asm volatile("ldmatrix.sync.aligned.m8n8.x4.shared.b16 {%0,%1,%2,%3}, [%4];" \
        : "=r"((R)[0]), "=r"((R)[1]), "=r"((R)[2]), "=r"((R)[3]) : "r"(addr))

#define CP16(dst, src) \
    asm volatile("cp.async.cg.shared.global [%0], [%1], 16;" :: "r"(dst), "l"(src))

__device__ __forceinline__ void store_pk2(uint32_t* __restrict__ q, int ncols,
                                          int m, int n, float v0, float v1) {
    uint32_t hi, lo; split2(v0, v1, hi, lo);
    uint32_t* p = q + (size_t)m * ncols + ((n >> 3) << 3) + ((n & 7) >> 1);
    p[0] = hi;
    p[4] = lo;
}

// EPI 1: GEMM2: reads p0=x; writes q1=pkG, p2=T
// EPI 2: gx GEMM: g = acc + p4(c) + p0(T); rmsprop p1=x,p2=a1,p3=a2; q1=pkX
// EPI 3: gu GEMM: g = acc; rmsprop p1=u,p2=b1,p3=b2; q1=pkU
// EPI 4: setup M2: pack 2*acc -> q1
// EPI 5: setup c:  p1 = -2*acc
template<int EPI>
__device__ __forceinline__ void epi_pair(float a0, float a1, int m, int n, int Nout,
                                         const float* __restrict__ p0,
                                         const float* __restrict__ p4,
                                         float* __restrict__ p1,
                                         float* __restrict__ p2,
                                         float* __restrict__ p3,
                                         uint32_t* __restrict__ q1)
{
    const size_t idx = (size_t)m * (size_t)Nout + (size_t)n;
    if (EPI == 4) {
        store_pk2(q1, Nout, m, n, 2.0f * a0, 2.0f * a1);
    } else if (EPI == 5) {
        float2 o; o.x = -2.0f * a0; o.y = -2.0f * a1;
        *reinterpret_cast<float2*>(&p1[idx]) = o;
    } else if (EPI == 1) {
        float2 xv = *reinterpret_cast<const float2*>(&p0[idx]);
        float G0, G1; float2 T;
        {
            float da = sqrtf(xv.x * xv.x + 1e-6f);
            float ex = expf(-a0);
            G0  = GAMMA_F * da * (-0.5f * ex);
            T.x = (GAMMA_F * (1.0f + ex) * 0.5f + GAMMA_F * 0.1f) * (xv.x / da);
        }
        {
            float da = sqrtf(xv.y * xv.y + 1e-6f);
            float ex = expf(-a1);
            G1  = GAMMA_F * da * (-0.5f * ex);
            T.y = (GAMMA_F * (1.0f + ex) * 0.5f + GAMMA_F * 0.1f) * (xv.y / da);
        }
        store_pk2(q1, Nout, m, n, G0, G1);
        *reinterpret_cast<float2*>(&p2[idx]) = T;
    } else {
        float2 g2;
        if (EPI == 2) {
            float2 tv = *reinterpret_cast<const float2*>(&p0[idx]);
            float2 cv = *reinterpret_cast<const float2*>(&p4[idx]);
            g2.x = a0 + cv.x + tv.x;
            g2.y = a1 + cv.y + tv.y;
        } else {
            g2.x = a0; g2.y = a1;
        }
        float2 sv  = *reinterpret_cast<const float2*>(&p1[idx]);
        float2 a1v = *reinterpret_cast<const float2*>(&p2[idx]);
        float2 a2v = *reinterpret_cast<const float2*>(&p3[idx]);
        float na1x = RHO_F * a1v.x + ONE_M_RHO_F * g2.x * g2.x;
        float updx = LR_F * g2.x / sqrtf(na1x + EPS_F);
        float na2x = MOM_F * a2v.x - updx;
        float svx  = sv.x + MOM_F * na2x - updx;
        float na1y = RHO_F * a1v.y + ONE_M_RHO_F * g2.y * g2.y;
        float updy = LR_F * g2.y / sqrtf(na1y + EPS_F);
        float na2y = MOM_F * a2v.y - updy;
        float svy  = sv.y + MOM_F * na2y - updy;
        float2 o1; o1.x = svx;  o1.y = svy;
        float2 o2; o2.x = na1x; o2.y = na1y;
        float2 o3; o3.x = na2x; o3.y = na2y;
        *reinterpret_cast<float2*>(&p1[idx]) = o1;
        store_pk2(q1, Nout, m, n, svx, svy);
        *reinterpret_cast<float2*>(&p2[idx]) = o2;
        *reinterpret_cast<float2*>(&p3[idx]) = o3;
    }
}

// ---- shared mainloop: BM=BN=128, BK=32, S=4, 256 threads ----
// One __syncthreads per k-tile: {wait; sync; issue; mma} — the top sync
// guarantees all warps finished reading the buffer `issue` overwrites.
struct Frag { float acc[4][4][4]; };

__device__ __forceinline__ void mainloop_128(
    const uint32_t* __restrict__ pkA, const uint32_t* __restrict__ pkB,
    int row0, int col0, int K, uint32_t sbase, char* smem, Frag& F)
{
    constexpr int S = 4;
    constexpr int STAGE = 256 * 128;
    const int tid  = threadIdx.x;
    const int lane = tid & 31, wid = tid >> 5;
    const int wm = wid >> 2, wn = wid & 3;

    const char* gA = reinterpret_cast<const char*>(pkA) + (size_t)row0 * (4 * K);
    const char* gB = reinterpret_cast<const char*>(pkB) + (size_t)col0 * (4 * K);
    const int pitch = 4 * K;
    const int iters = K / 32;

    auto issue = [&](int kt, int buf) {
        const uint32_t sd = sbase + buf * STAGE;
        const char* sA = gA + kt * 128;
        #pragma unroll
        for (int i = 0; i < 4; i++) {
            int idx = i * 256 + tid;
            int r = idx >> 3, c = idx & 7;
            uint32_t dst = sd + r * 128 + ((c ^ (r & 7)) << 4);
            CP16(dst, sA + (size_t)r * pitch + (c << 4));
        }
        const char* sB = gB + kt * 128;
        #pragma unroll
        for (int i = 0; i < 4; i++) {
            int idx = i * 256 + tid;
            int r = idx >> 3, c = idx & 7;
            uint32_t dst = sd + 128 * 128 + r * 128 + ((c ^ (r & 7)) << 4);
            CP16(dst, sB + (size_t)r * pitch + (c << 4));
        }
        asm volatile("cp.async.commit_group;" ::: "memory");
    };

    #pragma unroll
    for (int i = 0; i < 4; i++)
        #pragma unroll
        for (int j = 0; j < 4; j++)
            #pragma unroll
            for (int r = 0; r < 4; r++) F.acc[i][j][r] = 0.0f;

    #pragma unroll
    for (int s = 0; s < S - 1; s++) issue(s, s);

    for (int kt = 0; kt < iters; kt++) {
        const int rem = iters - 1 - kt;
        if (rem >= S - 2)      asm volatile("cp.async.wait_group 2;" ::: "memory");
        else if (rem == 1)     asm volatile("cp.async.wait_group 1;" ::: "memory");
        else                   asm volatile("cp.async.wait_group 0;" ::: "memory");
        __syncthreads();
        if (kt + S - 1 < iters) issue(kt + S - 1, (kt + S - 1) % S);

        const int buf = kt % S;
        const uint32_t sA32 = sbase + buf * STAGE;
        const uint32_t sB32 = sA32 + 128 * 128;

        #pragma unroll
        for (int j = 0; j < 2; j++) {
            uint32_t af[2][4][4];
            #pragma unroll
            for (int hl = 0; hl < 2; hl++)
                #pragma unroll
                for (int mf = 0; mf < 4; mf++) {
                    int rr = wm * 64 + mf * 16 + (lane & 15);
                    int c  = 4 * j + hl + 2 * (lane >> 4);
                    uint32_t addr = sA32 + rr * 128 + ((c ^ (rr & 7)) << 4);
                    LDSM_X4(af[hl][mf], addr);
                }
            uint32_t bfr[2][4][2];
            #pragma unroll
            for (int hl = 0; hl < 2; hl++)
                #pragma unroll
                for (int p = 0; p < 2; p++) {
                    uint32_t q[4];
                    int rr = wn * 32 + (2 * p + (lane >> 4)) * 8 + (lane & 7);
                    int c  = 4 * j + hl + 2 * ((lane >> 3) & 1);
                    uint32_t addr = sB32 + rr * 128 + ((c ^ (rr & 7)) << 4);
                    LDSM_X4(q, addr);
                    bfr[hl][2 * p    ][0] = q[0]; bfr[hl][2 * p    ][1] = q[1];
                    bfr[hl][2 * p + 1][0] = q[2]; bfr[hl][2 * p + 1][1] = q[3];
                }
            #pragma unroll
            for (int mf = 0; mf < 4; mf++)
                #pragma unroll
                for (int nf = 0; nf < 4; nf++) {
                    mma_bf16(F.acc[mf][nf], af[0][mf], bfr[0][nf]);
                    mma_bf16(F.acc[mf][nf], af[0][mf], bfr[1][nf]);
                    mma_bf16(F.acc[mf][nf], af[1][mf], bfr[0][nf]);
                }
        }
    }
    __syncthreads();   // protect smem reuse by any later use / exit ordering
}

template<int EPI>
__device__ __forceinline__ void run_epi(Frag& F, int row0, int col0, int Nout,
                                        const float* p0, const float* p4,
                                        float* p1, float* p2, float* p3, uint32_t* q1)
{
    const int tid  = threadIdx.x;
    const int lane = tid & 31, wid = tid >> 5;
    const int wm = wid >> 2, wn = wid & 3;
    #pragma unroll
    for (int mf = 0; mf < 4; mf++) {
        #pragma unroll
        for (int nf = 0; nf < 4; nf++) {
            int mlo = row0 + wm * 64 + mf * 16 + (lane >> 2);
            int n   = col0 + wn * 32 + nf * 8 + ((lane & 3) << 1);
            epi_pair<EPI>(F.acc[mf][nf][0], F.acc[mf][nf][1], mlo,     n, Nout, p0, p4, p1, p2, p3, q1);
            epi_pair<EPI>(F.acc[mf][nf][2], F.acc[mf][nf][3], mlo + 8, n, Nout, p0, p4, p1, p2, p3, q1);
        }
    }
}

// GEMM2 (standalone): s = u@V, EPI 1
__global__ __launch_bounds__(256, 1)
void gemm2_k(const uint32_t* __restrict__ pkU, const uint32_t* __restrict__ pkVT,
             const float* __restrict__ x, float* __restrict__ pT,
             uint32_t* __restrict__ pkG)
{
    extern __shared__ __align__(1024) char smem[];
    Frag F;
    int col0 = (blockIdx.x & 15) * 128, row0 = (blockIdx.x >> 4) * 128;
    mainloop_128(pkU, pkVT, row0, col0, D_C, cvta_smem(smem), smem, F);
    run_epi<1>(F, row0, col0, D_OUT, x, nullptr, nullptr, pT, nullptr, pkG);
}

// merged gx + gu kernel: blocks [0,256) = gx (EPI2), [256,288) = gu (EPI3)
__global__ __launch_bounds__(256, 1)
void gemm34_k(const uint32_t* __restrict__ pkX, const uint32_t* __restrict__ pkM,
              const uint32_t* __restrict__ pkG, const uint32_t* __restrict__ pkV,
              const float* __restrict__ pT, const float* __restrict__ pc,
              float* __restrict__ x,  float* __restrict__ a1, float* __restrict__ a2,
              uint32_t* __restrict__ pkXw,
              float* __restrict__ u,  float* __restrict__ b1, float* __restrict__ b2,
              uint32_t* __restrict__ pkUw)
{
    extern __shared__ __align__(1024) char smem[];
    Frag F;
    const bool role4 = blockIdx.x >= 256;
    int row0, col0;
    const uint32_t *pkA, *pkB;
    if (!role4) {
        col0 = (blockIdx.x & 15) * 128; row0 = (blockIdx.x >> 4) * 128;
        pkA = pkX; pkB = pkM;
    } else {
        int b = blockIdx.x - 256;
        col0 = (b & 1) * 128; row0 = (b >> 1) * 128;
        pkA = pkG; pkB = pkV;
    }
    mainloop_128(pkA, pkB, row0, col0, D_OUT, cvta_smem(smem), smem, F);
    if (!role4)
        run_epi<2>(F, row0, col0, D_OUT, pT, pc, x, a1, a2, pkXw);
    else
        run_epi<3>(F, row0, col0, D_C, nullptr, nullptr, u, b1, b2, pkUw);
}

// merged setup kernel: blocks [0,256) = M2 (EPI4), [256,512) = c (EPI5); K=1024
__global__ __launch_bounds__(256, 1)
void setup_k(const uint32_t* __restrict__ pkW, const uint32_t* __restrict__ pkIn,
             uint32_t* __restrict__ pkM, float* __restrict__ pc)
{
    extern __shared__ __align__(1024) char smem[];
    Frag F;
    const bool rolec = blockIdx.x >= 256;
    int b = rolec ? blockIdx.x - 256 : blockIdx.x;
    int col0 = (b & 15) * 128, row0 = (b >> 4) * 128;
    const uint32_t* pkA = rolec ? pkIn : pkW;
    mainloop_128(pkA, pkW, row0, col0, D_IN, cvta_smem(smem), smem, F);
    if (!rolec)
        run_epi<4>(F, row0, col0, D_OUT, nullptr, nullptr, nullptr, nullptr, nullptr, pkM);
    else
        run_epi<5>(F, row0, col0, D_OUT, nullptr, nullptr, pc, nullptr, nullptr, nullptr);
}

// ============================================================================

extern "C" void kernel_launch(void* const* d_in, const int* in_sizes, int n_in,
                              void* d_out, int out_size)
{
    (void)in_sizes; (void)n_in; (void)out_size;
    const float* inputs = (const float*)d_in[0];
    const float* W      = (const float*)d_in[1];
    const float* V      = (const float*)d_in[2];
    float* x = (float*)d_out;

    float *pT, *pa1, *pa2, *pu, *pb1, *pb2, *pVT, *pc, *pvs;
    uint32_t *kW, *kV, *kVT, *kIn, *kM, *kG, *kX[2], *kU[2];
    cudaGetSymbolAddress((void**)&pT,  g_T);
    cudaGetSymbolAddress((void**)&pa1, g_a1);
    cudaGetSymbolAddress((void**)&pa2, g_a2);
    cudaGetSymbolAddress((void**)&pu,  g_u);
    cudaGetSymbolAddress((void**)&pb1, g_b1);
    cudaGetSymbolAddress((void**)&pb2, g_b2);
    cudaGetSymbolAddress((void**)&pVT, g_VT);
    cudaGetSymbolAddress((void**)&pc,  g_c);
    cudaGetSymbolAddress((void**)&pvs, g_vs);
    cudaGetSymbolAddress((void**)&kW,  g_pkW);
    cudaGetSymbolAddress((void**)&kV,  g_pkV);
    cudaGetSymbolAddress((void**)&kVT, g_pkVT);
    cudaGetSymbolAddress((void**)&kIn, g_pkIn);
    cudaGetSymbolAddress((void**)&kM,  g_pkM);
    cudaGetSymbolAddress((void**)&kG,  g_pkG);
    cudaGetSymbolAddress((void**)&kX[0], g_pkX0);
    cudaGetSymbolAddress((void**)&kX[1], g_pkX1);
    cudaGetSymbolAddress((void**)&kU[0], g_pkU0);
    cudaGetSymbolAddress((void**)&kU[1], g_pkU1);

    constexpr int SM128 = 4 * 256 * 128;   // 131072
    cudaFuncSetAttribute(gemm2_k,  cudaFuncAttributeMaxDynamicSharedMemorySize, SM128);
    cudaFuncSetAttribute(gemm34_k, cudaFuncAttributeMaxDynamicSharedMemorySize, SM128);
    cudaFuncSetAttribute(setup_k,  cudaFuncAttributeMaxDynamicSharedMemorySize, SM128);

    const int TPB = 256;

    // ---- setup: transpose/pack; merged M2 = 2*W@W^T and c = -2*inputs@W^T ----
    transpose_k<<<dim3(D_OUT / 32, D_C / 32), dim3(32, 8)>>>(V, pVT, D_C, D_OUT);
    pack_k<<<(D_OUT * D_IN / 8 + TPB - 1) / TPB, TPB>>>(W,      kW,  D_OUT * D_IN / 8);
    pack_k<<<(D_C * D_OUT / 8 + TPB - 1) / TPB, TPB>>>(V,       kV,  D_C * D_OUT / 8);
    pack_k<<<(D_OUT * D_C / 8 + TPB - 1) / TPB, TPB>>>(pVT,     kVT, D_OUT * D_C / 8);
    pack_k<<<(B_SZ * D_IN / 8 + TPB - 1) / TPB, TPB>>>(inputs,  kIn, B_SZ * D_IN / 8);

    setup_k<<<512, 256, SM128>>>(kW, kIn, kM, pc);

    // ---- step 0: x from g=c ; u from g = G0 * rowsum(V) broadcast ----
    vsum_k<<<D_C, 256>>>(V, pvs);
    step0_k<0><<<(B_SZ * D_OUT / 8 + TPB - 1) / TPB, TPB>>>(
        pc, x, pa1, pa2, kX[0], B_SZ * D_OUT / 8);
    step0_k<1><<<(B_SZ * D_C / 8 + TPB - 1) / TPB, TPB>>>(
        pvs, pu, pb1, pb2, kU[0], B_SZ * D_C / 8);

    // ---- steps 1..9: GEMM2 then merged gx+gu ----
    for (int s = 1; s < 10; s++) {
        const int rd = (s - 1) & 1, wr = s & 1;
        gemm2_k<<<256, 256, SM128>>>(kU[rd], kVT, x, pT, kG);
        gemm34_k<<<288, 256, SM128>>>(kX[rd], kM, kG, kV, pT, pc,
                                      x, pa1, pa2, kX[wr],
                                      pu, pb1, pb2, kU[wr]);
    }
}

// round 7
// speedup vs baseline: 4.2990x; 1.0703x over previous
#include <cuda_runtime.h>
#include <cuda_bf16.h>
#include <cstdint>
#include <math.h>

#define B_SZ  2048
#define D_IN  1024
#define D_OUT 2048
#define D_C   256

#define GAMMA_F 0.1f
#define RHO_F   0.9f
#define ONE_M_RHO_F 0.1f
#define LR_F    0.009f
#define MOM_F   0.9f
#define EPS_F   1e-8f

// ---- fp32 state / scratch ----
__device__ float g_T  [B_SZ * D_OUT];
__device__ float g_a1 [B_SZ * D_OUT];
__device__ float g_a2 [B_SZ * D_OUT];
__device__ float g_u  [B_SZ * D_C];
__device__ float g_b1 [B_SZ * D_C];
__device__ float g_b2 [B_SZ * D_C];
__device__ float g_VT [D_OUT * D_C];
__device__ float g_c  [B_SZ * D_OUT];     // -2 * inputs @ W^T
__device__ float g_vs [D_C];              // rowsum of V

// ---- packed bf16 hi/lo operands (per 8-elem group: 4 hi words then 4 lo) ----
__device__ __align__(128) uint32_t g_pkW [D_OUT * D_IN];
__device__ __align__(128) uint32_t g_pkV [D_C * D_OUT];
__device__ __align__(128) uint32_t g_pkVT[D_OUT * D_C];
__device__ __align__(128) uint32_t g_pkIn[B_SZ * D_IN];
__device__ __align__(128) uint32_t g_pkM [D_OUT * D_OUT];   // 2*W@W^T
__device__ __align__(128) uint32_t g_pkG [B_SZ * D_OUT];
__device__ __align__(128) uint32_t g_pkX0[B_SZ * D_OUT];
__device__ __align__(128) uint32_t g_pkX1[B_SZ * D_OUT];
__device__ __align__(128) uint32_t g_pkU0[B_SZ * D_C];
__device__ __align__(128) uint32_t g_pkU1[B_SZ * D_C];

__device__ __forceinline__ void split2(float x, float y, uint32_t& hi, uint32_t& lo) {
    __nv_bfloat16 hx = __float2bfloat16(x);
    __nv_bfloat16 hy = __float2bfloat16(y);
    float rx = x - __bfloat162float(hx);
    float ry = y - __bfloat162float(hy);
    __nv_bfloat162 H; H.x = hx; H.y = hy;
    hi = *reinterpret_cast<uint32_t*>(&H);
    __nv_bfloat162 L = __floats2bfloat162_rn(rx, ry);
    lo = *reinterpret_cast<uint32_t*>(&L);
}

__global__ void transpose_k(const float* __restrict__ src, float* __restrict__ dst,
                            int rows, int cols) {
    __shared__ float t[32][33];
    int bx = blockIdx.x * 32, by = blockIdx.y * 32;
    int x = bx + threadIdx.x;
    #pragma unroll
    for (int j = 0; j < 32; j += 8)
        t[threadIdx.y + j][threadIdx.x] = src[(size_t)(by + threadIdx.y + j) * cols + x];
    __syncthreads();
    int x2 = by + threadIdx.x;
    #pragma unroll
    for (int j = 0; j < 32; j += 8)
        dst[(size_t)(bx + threadIdx.y + j) * rows + x2] = t[threadIdx.x][threadIdx.y + j];
}

__global__ void pack_k(const float* __restrict__ src, uint32_t* __restrict__ dst, int n8) {
    int i = blockIdx.x * blockDim.x + threadIdx.x;
    if (i >= n8) return;
    const float4* s = reinterpret_cast<const float4*>(src) + 2 * (size_t)i;
    float4 v0 = s[0], v1 = s[1];
    uint32_t h0,l0,h1,l1,h2,l2,h3,l3;
    split2(v0.x, v0.y, h0, l0); split2(v0.z, v0.w, h1, l1);
    split2(v1.x, v1.y, h2, l2); split2(v1.z, v1.w, h3, l3);
    uint4* d = reinterpret_cast<uint4*>(dst) + 2 * (size_t)i;
    uint4 H; H.x=h0; H.y=h1; H.z=h2; H.w=h3;
    uint4 L; L.x=l0; L.y=l1; L.z=l2; L.w=l3;
    d[0] = H; d[1] = L;
}

__global__ void vsum_k(const float* __restrict__ V, float* __restrict__ out) {
    __shared__ float red[256];
    int n = blockIdx.x;
    float s = 0.0f;
    for (int k = threadIdx.x; k < D_OUT; k += 256) s += V[(size_t)n * D_OUT + k];
    red[threadIdx.x] = s;
    __syncthreads();
    for (int st = 128; st > 0; st >>= 1) {
        if (threadIdx.x < st) red[threadIdx.x] += red[threadIdx.x + st];
        __syncthreads();
    }
    if (threadIdx.x == 0) out[n] = red[0];
}

template<int MODE>
__global__ void step0_k(const float* __restrict__ src, float* __restrict__ s,
                        float* __restrict__ a1, float* __restrict__ a2,
                        uint32_t* __restrict__ pk, int n8) {
    int i = blockIdx.x * blockDim.x + threadIdx.x;
    if (i >= n8) return;
    float gv[8];
    if (MODE == 0) {
        const float4* cs = reinterpret_cast<const float4*>(src) + 2 * (size_t)i;
        float4 v0 = cs[0], v1 = cs[1];
        gv[0]=v0.x; gv[1]=v0.y; gv[2]=v0.z; gv[3]=v0.w;
        gv[4]=v1.x; gv[5]=v1.y; gv[6]=v1.z; gv[7]=v1.w;
    } else {
        const float G0 = GAMMA_F * 1.0e-3f * (-0.5f);
        int base = (8 * i) & (D_C - 1);
        #pragma unroll
        for (int j = 0; j < 8; j++) gv[j] = G0 * src[base + j];
    }
    float xs[8], A1[8], A2[8];
    #pragma unroll
    for (int j = 0; j < 8; j++) {
        float g   = gv[j];
        float na1 = ONE_M_RHO_F * g * g;
        float upd = LR_F * g / sqrtf(na1 + EPS_F);
        float na2 = -upd;
        xs[j] = MOM_F * na2 - upd;
        A1[j] = na1; A2[j] = na2;
    }
    float4* so = reinterpret_cast<float4*>(s)  + 2 * (size_t)i;
    float4* o1 = reinterpret_cast<float4*>(a1) + 2 * (size_t)i;
    float4* o2 = reinterpret_cast<float4*>(a2) + 2 * (size_t)i;
    so[0] = make_float4(xs[0],xs[1],xs[2],xs[3]); so[1] = make_float4(xs[4],xs[5],xs[6],xs[7]);
    o1[0] = make_float4(A1[0],A1[1],A1[2],A1[3]); o1[1] = make_float4(A1[4],A1[5],A1[6],A1[7]);
    o2[0] = make_float4(A2[0],A2[1],A2[2],A2[3]); o2[1] = make_float4(A2[4],A2[5],A2[6],A2[7]);
    uint32_t h[4], l[4];
    split2(xs[0],xs[1],h[0],l[0]); split2(xs[2],xs[3],h[1],l[1]);
    split2(xs[4],xs[5],h[2],l[2]); split2(xs[6],xs[7],h[3],l[3]);
    uint4* d = reinterpret_cast<uint4*>(pk) + 2 * (size_t)i;
    uint4 H; H.x=h[0]; H.y=h[1]; H.z=h[2]; H.w=h[3];
    uint4 L; L.x=l[0]; L.y=l[1]; L.z=l[2]; L.w=l[3];
    d[0] = H; d[1] = L;
}

// ============================ mma helpers ============================

__device__ __forceinline__ uint32_t cvta_smem(const void* p) {
    uint32_t a;
    asm("{ .reg .u64 t; cvta.to.shared.u64 t, %1; cvt.u32.u64 %0, t; }" : "=r"(a) : "l"(p));
    return a;
}

__device__ __forceinline__ void mma_bf16(float* c, const uint32_t* a, const uint32_t* b) {
    asm volatile(
        "mma.sync.aligned.m16n8k16.row.col.f32.bf16.bf16.f32 "
        "{%0,%1,%2,%3}, {%4,%5,%6,%7}, {%8,%9}, {%0,%1,%2,%3};"
        : "+f"(c[0]), "+f"(c[1]), "+f"(c[2]), "+f"(c[3])
        : "r"(a[0]), "r"(a[1]), "r"(a[2]), "r"(a[3]), "r"(b[0]), "r"(b[1]));
}

#define LDSM_X4(R, addr) \
    asm volatile("ldmatrix.sync.aligned.m8n8.x4.shared.b16 {%0,%1,%2,%3}, [%4];" \
        : "=r"((R)[0]), "=r"((R)[1]), "=r"((R)[2]), "=r"((R)[3]) : "r"(addr))

#define CP16(dst, src) \
    asm volatile("cp.async.cg.shared.global [%0], [%1], 16;" :: "r"(dst), "l"(src))

__device__ __forceinline__ void store_pk2(uint32_t* __restrict__ q, int ncols,
                                          int m, int n, float v0, float v1) {
    uint32_t hi, lo; split2(v0, v1, hi, lo);
    uint32_t* p = q + (size_t)m * ncols + ((n >> 3) << 3) + ((n & 7) >> 1);
    p[0] = hi;
    p[4] = lo;
}

// EPI 1: GEMM2: reads p0=x; writes q1=pkG, p2=T
// EPI 2: gx GEMM: g = acc + p4(c) + p0(T); rmsprop p1=x,p2=a1,p3=a2; q1=pkX
// EPI 3: gu GEMM: g = acc; rmsprop p1=u,p2=b1,p3=b2; q1=pkU
// EPI 4: setup M2: pack 2*acc -> q1
// EPI 5: setup c:  p1 = -2*acc
template<int EPI>
__device__ __forceinline__ void epi_pair(float a0, float a1, int m, int n, int Nout,
                                         const float* __restrict__ p0,
                                         const float* __restrict__ p4,
                                         float* __restrict__ p1,
                                         float* __restrict__ p2,
                                         float* __restrict__ p3,
                                         uint32_t* __restrict__ q1)
{
    const size_t idx = (size_t)m * (size_t)Nout + (size_t)n;
    if (EPI == 4) {
        store_pk2(q1, Nout, m, n, 2.0f * a0, 2.0f * a1);
    } else if (EPI == 5) {
        float2 o; o.x = -2.0f * a0; o.y = -2.0f * a1;
        *reinterpret_cast<float2*>(&p1[idx]) = o;
    } else if (EPI == 1) {
        float2 xv = *reinterpret_cast<const float2*>(&p0[idx]);
        float G0, G1; float2 T;
        {
            float da = sqrtf(xv.x * xv.x + 1e-6f);
            float ex = expf(-a0);
            G0  = GAMMA_F * da * (-0.5f * ex);
            T.x = (GAMMA_F * (1.0f + ex) * 0.5f + GAMMA_F * 0.1f) * (xv.x / da);
        }
        {
            float da = sqrtf(xv.y * xv.y + 1e-6f);
            float ex = expf(-a1);
            G1  = GAMMA_F * da * (-0.5f * ex);
            T.y = (GAMMA_F * (1.0f + ex) * 0.5f + GAMMA_F * 0.1f) * (xv.y / da);
        }
        store_pk2(q1, Nout, m, n, G0, G1);
        *reinterpret_cast<float2*>(&p2[idx]) = T;
    } else {
        float2 g2;
        if (EPI == 2) {
            float2 tv = *reinterpret_cast<const float2*>(&p0[idx]);
            float2 cv = *reinterpret_cast<const float2*>(&p4[idx]);
            g2.x = a0 + cv.x + tv.x;
            g2.y = a1 + cv.y + tv.y;
        } else {
            g2.x = a0; g2.y = a1;
        }
        float2 sv  = *reinterpret_cast<const float2*>(&p1[idx]);
        float2 a1v = *reinterpret_cast<const float2*>(&p2[idx]);
        float2 a2v = *reinterpret_cast<const float2*>(&p3[idx]);
        float na1x = RHO_F * a1v.x + ONE_M_RHO_F * g2.x * g2.x;
        float updx = LR_F * g2.x / sqrtf(na1x + EPS_F);
        float na2x = MOM_F * a2v.x - updx;
        float svx  = sv.x + MOM_F * na2x - updx;
        float na1y = RHO_F * a1v.y + ONE_M_RHO_F * g2.y * g2.y;
        float updy = LR_F * g2.y / sqrtf(na1y + EPS_F);
        float na2y = MOM_F * a2v.y - updy;
        float svy  = sv.y + MOM_F * na2y - updy;
        float2 o1; o1.x = svx;  o1.y = svy;
        float2 o2; o2.x = na1x; o2.y = na1y;
        float2 o3; o3.x = na2x; o3.y = na2y;
        *reinterpret_cast<float2*>(&p1[idx]) = o1;
        store_pk2(q1, Nout, m, n, svx, svy);
        *reinterpret_cast<float2*>(&p2[idx]) = o2;
        *reinterpret_cast<float2*>(&p3[idx]) = o3;
    }
}

// ---- shared mainloop: BM=128, BN=256, BK=32, S=3, 512 threads (16 warps 2x8)
struct Frag { float acc[4][4][4]; };

__device__ __forceinline__ void mainloop_128x256(
    const uint32_t* __restrict__ pkA, const uint32_t* __restrict__ pkB,
    int row0, int col0, int K, uint32_t sbase, Frag& F)
{
    constexpr int S = 3;
    constexpr int STAGE = (128 + 256) * 128;   // 49152
    const int tid  = threadIdx.x;
    const int lane = tid & 31, wid = tid >> 5;
    const int wm = wid >> 3, wn = wid & 7;

    const char* gA = reinterpret_cast<const char*>(pkA) + (size_t)row0 * (4 * K);
    const char* gB = reinterpret_cast<const char*>(pkB) + (size_t)col0 * (4 * K);
    const int pitch = 4 * K;
    const int iters = K / 32;

    auto issue = [&](int kt, int buf) {
        const uint32_t sd = sbase + buf * STAGE;
        const char* sA = gA + kt * 128;
        #pragma unroll
        for (int i = 0; i < 2; i++) {                       // 1024 chunks / 512 thr
            int idx = i * 512 + tid;
            int r = idx >> 3, c = idx & 7;
            uint32_t dst = sd + r * 128 + ((c ^ (r & 7)) << 4);
            CP16(dst, sA + (size_t)r * pitch + (c << 4));
        }
        const char* sB = gB + kt * 128;
        #pragma unroll
        for (int i = 0; i < 4; i++) {                       // 2048 chunks / 512 thr
            int idx = i * 512 + tid;
            int r = idx >> 3, c = idx & 7;
            uint32_t dst = sd + 128 * 128 + r * 128 + ((c ^ (r & 7)) << 4);
            CP16(dst, sB + (size_t)r * pitch + (c << 4));
        }
        asm volatile("cp.async.commit_group;" ::: "memory");
    };

    #pragma unroll
    for (int i = 0; i < 4; i++)
        #pragma unroll
        for (int j = 0; j < 4; j++)
            #pragma unroll
            for (int r = 0; r < 4; r++) F.acc[i][j][r] = 0.0f;

    issue(0, 0);
    issue(1, 1);

    for (int kt = 0; kt < iters; kt++) {
        if (kt < iters - 1) asm volatile("cp.async.wait_group 1;" ::: "memory");
        else                asm volatile("cp.async.wait_group 0;" ::: "memory");
        __syncthreads();
        if (kt + 2 < iters) issue(kt + 2, (kt + 2) % S);

        const int buf = kt % S;
        const uint32_t sA32 = sbase + buf * STAGE;
        const uint32_t sB32 = sA32 + 128 * 128;

        #pragma unroll
        for (int j = 0; j < 2; j++) {
            uint32_t af[2][4][4];
            #pragma unroll
            for (int hl = 0; hl < 2; hl++)
                #pragma unroll
                for (int mf = 0; mf < 4; mf++) {
                    int rr = wm * 64 + mf * 16 + (lane & 15);
                    int c  = 4 * j + hl + 2 * (lane >> 4);
                    uint32_t addr = sA32 + rr * 128 + ((c ^ (rr & 7)) << 4);
                    LDSM_X4(af[hl][mf], addr);
                }
            uint32_t bfr[2][4][2];
            #pragma unroll
            for (int hl = 0; hl < 2; hl++)
                #pragma unroll
                for (int p = 0; p < 2; p++) {
                    uint32_t q[4];
                    int rr = wn * 32 + (2 * p + (lane >> 4)) * 8 + (lane & 7);
                    int c  = 4 * j + hl + 2 * ((lane >> 3) & 1);
                    uint32_t addr = sB32 + rr * 128 + ((c ^ (rr & 7)) << 4);
                    LDSM_X4(q, addr);
                    bfr[hl][2 * p    ][0] = q[0]; bfr[hl][2 * p    ][1] = q[1];
                    bfr[hl][2 * p + 1][0] = q[2]; bfr[hl][2 * p + 1][1] = q[3];
                }
            #pragma unroll
            for (int mf = 0; mf < 4; mf++)
                #pragma unroll
                for (int nf = 0; nf < 4; nf++) {
                    mma_bf16(F.acc[mf][nf], af[0][mf], bfr[0][nf]);
                    mma_bf16(F.acc[mf][nf], af[0][mf], bfr[1][nf]);
                    mma_bf16(F.acc[mf][nf], af[1][mf], bfr[0][nf]);
                }
        }
    }
}

template<int EPI>
__device__ __forceinline__ void run_epi(Frag& F, int row0, int col0, int Nout,
                                        const float* p0, const float* p4,
                                        float* p1, float* p2, float* p3, uint32_t* q1)
{
    const int tid  = threadIdx.x;
    const int lane = tid & 31, wid = tid >> 5;
    const int wm = wid >> 3, wn = wid & 7;
    #pragma unroll
    for (int mf = 0; mf < 4; mf++) {
        #pragma unroll
        for (int nf = 0; nf < 4; nf++) {
            int mlo = row0 + wm * 64 + mf * 16 + (lane >> 2);
            int n   = col0 + wn * 32 + nf * 8 + ((lane & 3) << 1);
            epi_pair<EPI>(F.acc[mf][nf][0], F.acc[mf][nf][1], mlo,     n, Nout, p0, p4, p1, p2, p3, q1);
            epi_pair<EPI>(F.acc[mf][nf][2], F.acc[mf][nf][3], mlo + 8, n, Nout, p0, p4, p1, p2, p3, q1);
        }
    }
}

// GEMM2: s = u@V, EPI 1.  grid 128: col0=(b&7)*256, row0=(b>>3)*128
__global__ __launch_bounds__(512, 1)
void gemm2_k(const uint32_t* __restrict__ pkU, const uint32_t* __restrict__ pkVT,
             const float* __restrict__ x, float* __restrict__ pT,
             uint32_t* __restrict__ pkG)
{
    extern __shared__ __align__(1024) char smem[];
    Frag F;
    int col0 = (blockIdx.x & 7) * 256, row0 = (blockIdx.x >> 3) * 128;
    mainloop_128x256(pkU, pkVT, row0, col0, D_C, cvta_smem(smem), F);
    run_epi<1>(F, row0, col0, D_OUT, x, nullptr, nullptr, pT, nullptr, pkG);
}

// merged gx + gu: blocks [0,128) = gx (EPI2), [128,144) = gu (EPI3). Single wave.
__global__ __launch_bounds__(512, 1)
void gemm34_k(const uint32_t* __restrict__ pkX, const uint32_t* __restrict__ pkM,
              const uint32_t* __restrict__ pkG, const uint32_t* __restrict__ pkV,
              const float* __restrict__ pT, const float* __restrict__ pc,
              float* __restrict__ x,  float* __restrict__ a1, float* __restrict__ a2,
              uint32_t* __restrict__ pkXw,
              float* __restrict__ u,  float* __restrict__ b1, float* __restrict__ b2,
              uint32_t* __restrict__ pkUw)
{
    extern __shared__ __align__(1024) char smem[];
    Frag F;
    const bool role4 = blockIdx.x >= 128;
    int row0, col0;
    const uint32_t *pkA, *pkB;
    if (!role4) {
        col0 = (blockIdx.x & 7) * 256; row0 = (blockIdx.x >> 3) * 128;
        pkA = pkX; pkB = pkM;
    } else {
        col0 = 0; row0 = (blockIdx.x - 128) * 128;
        pkA = pkG; pkB = pkV;
    }
    mainloop_128x256(pkA, pkB, row0, col0, D_OUT, cvta_smem(smem), F);
    if (!role4)
        run_epi<2>(F, row0, col0, D_OUT, pT, pc, x, a1, a2, pkXw);
    else
        run_epi<3>(F, row0, col0, D_C, nullptr, nullptr, u, b1, b2, pkUw);
}

// merged setup: blocks [0,128) = M2 (EPI4), [128,256) = c (EPI5); K=1024
__global__ __launch_bounds__(512, 1)
void setup_k(const uint32_t* __restrict__ pkW, const uint32_t* __restrict__ pkIn,
             uint32_t* __restrict__ pkM, float* __restrict__ pc)
{
    extern __shared__ __align__(1024) char smem[];
    Frag F;
    const bool rolec = blockIdx.x >= 128;
    int b = rolec ? blockIdx.x - 128 : blockIdx.x;
    int col0 = (b & 7) * 256, row0 = (b >> 3) * 128;
    const uint32_t* pkA = rolec ? pkIn : pkW;
    mainloop_128x256(pkA, pkW, row0, col0, D_IN, cvta_smem(smem), F);
    if (!rolec)
        run_epi<4>(F, row0, col0, D_OUT, nullptr, nullptr, nullptr, nullptr, nullptr, pkM);
    else
        run_epi<5>(F, row0, col0, D_OUT, nullptr, nullptr, pc, nullptr, nullptr, nullptr);
}

// ============================================================================

extern "C" void kernel_launch(void* const* d_in, const int* in_sizes, int n_in,
                              void* d_out, int out_size)
{
    (void)in_sizes; (void)n_in; (void)out_size;
    const float* inputs = (const float*)d_in[0];
    const float* W      = (const float*)d_in[1];
    const float* V      = (const float*)d_in[2];
    float* x = (float*)d_out;

    float *pT, *pa1, *pa2, *pu, *pb1, *pb2, *pVT, *pc, *pvs;
    uint32_t *kW, *kV, *kVT, *kIn, *kM, *kG, *kX[2], *kU[2];
    cudaGetSymbolAddress((void**)&pT,  g_T);
    cudaGetSymbolAddress((void**)&pa1, g_a1);
    cudaGetSymbolAddress((void**)&pa2, g_a2);
    cudaGetSymbolAddress((void**)&pu,  g_u);
    cudaGetSymbolAddress((void**)&pb1, g_b1);
    cudaGetSymbolAddress((void**)&pb2, g_b2);
    cudaGetSymbolAddress((void**)&pVT, g_VT);
    cudaGetSymbolAddress((void**)&pc,  g_c);
    cudaGetSymbolAddress((void**)&pvs, g_vs);
    cudaGetSymbolAddress((void**)&kW,  g_pkW);
    cudaGetSymbolAddress((void**)&kV,  g_pkV);
    cudaGetSymbolAddress((void**)&kVT, g_pkVT);
    cudaGetSymbolAddress((void**)&kIn, g_pkIn);
    cudaGetSymbolAddress((void**)&kM,  g_pkM);
    cudaGetSymbolAddress((void**)&kG,  g_pkG);
    cudaGetSymbolAddress((void**)&kX[0], g_pkX0);
    cudaGetSymbolAddress((void**)&kX[1], g_pkX1);
    cudaGetSymbolAddress((void**)&kU[0], g_pkU0);
    cudaGetSymbolAddress((void**)&kU[1], g_pkU1);

    constexpr int SMEM = 3 * (128 + 256) * 128;   // 147456
    cudaFuncSetAttribute(gemm2_k,  cudaFuncAttributeMaxDynamicSharedMemorySize, SMEM);
    cudaFuncSetAttribute(gemm34_k, cudaFuncAttributeMaxDynamicSharedMemorySize, SMEM);
    cudaFuncSetAttribute(setup_k,  cudaFuncAttributeMaxDynamicSharedMemorySize, SMEM);

    const int TPB = 256;

    // ---- setup: transpose/pack; merged M2 = 2*W@W^T and c = -2*inputs@W^T ----
    transpose_k<<<dim3(D_OUT / 32, D_C / 32), dim3(32, 8)>>>(V, pVT, D_C, D_OUT);
    pack_k<<<(D_OUT * D_IN / 8 + TPB - 1) / TPB, TPB>>>(W,      kW,  D_OUT * D_IN / 8);
    pack_k<<<(D_C * D_OUT / 8 + TPB - 1) / TPB, TPB>>>(V,       kV,  D_C * D_OUT / 8);
    pack_k<<<(D_OUT * D_C / 8 + TPB - 1) / TPB, TPB>>>(pVT,     kVT, D_OUT * D_C / 8);
    pack_k<<<(B_SZ * D_IN / 8 + TPB - 1) / TPB, TPB>>>(inputs,  kIn, B_SZ * D_IN / 8);

    setup_k<<<256, 512, SMEM>>>(kW, kIn, kM, pc);

    // ---- step 0: x from g=c ; u from g = G0 * rowsum(V) broadcast ----
    vsum_k<<<D_C, 256>>>(V, pvs);
    step0_k<0><<<(B_SZ * D_OUT / 8 + TPB - 1) / TPB, TPB>>>(
        pc, x, pa1, pa2, kX[0], B_SZ * D_OUT / 8);
    step0_k<1><<<(B_SZ * D_C / 8 + TPB - 1) / TPB, TPB>>>(
        pvs, pu, pb1, pb2, kU[0], B_SZ * D_C / 8);

    // ---- steps 1..9: GEMM2 then single-wave merged gx+gu ----
    for (int s = 1; s < 10; s++) {
        const int rd = (s - 1) & 1, wr = s & 1;
        gemm2_k<<<128, 512, SMEM>>>(kU[rd], kVT, x, pT, kG);
        gemm34_k<<<144, 512, SMEM>>>(kX[rd], kM, kG, kV, pT, pc,
                                     x, pa1, pa2, kX[wr],
                                     pu, pb1, pb2, kU[wr]);
    }
}

// round 8
// speedup vs baseline: 5.6435x; 1.3127x over previous
#include <cuda_runtime.h>
#include <cuda_fp16.h>
#include <cstdint>
#include <math.h>

#define B_SZ  2048
#define D_IN  1024
#define D_OUT 2048
#define D_C   256

#define GAMMA_F 0.1f
#define RHO_F   0.9f
#define ONE_M_RHO_F 0.1f
#define LR_F    0.009f
#define MOM_F   0.9f
#define EPS_F   1e-8f

// ---- fp32 state / scratch ----
__device__ float g_T  [B_SZ * D_OUT];
__device__ float g_a1 [B_SZ * D_OUT];
__device__ float g_a2 [B_SZ * D_OUT];
__device__ float g_u  [B_SZ * D_C];
__device__ float g_b1 [B_SZ * D_C];
__device__ float g_b2 [B_SZ * D_C];
__device__ float g_VT [D_OUT * D_C];
__device__ float g_c  [B_SZ * D_OUT];     // -2 * inputs @ W^T
__device__ float g_vs [D_C];              // rowsum of V

// ---- packed fp16 hi/lo operands (per 8-elem group: 4 hi words then 4 lo) ----
__device__ __align__(128) uint32_t g_pkW [D_OUT * D_IN];
__device__ __align__(128) uint32_t g_pkV [D_C * D_OUT];
__device__ __align__(128) uint32_t g_pkVT[D_OUT * D_C];
__device__ __align__(128) uint32_t g_pkIn[B_SZ * D_IN];
__device__ __align__(128) uint32_t g_pkM [D_OUT * D_OUT];   // 2*W@W^T
__device__ __align__(128) uint32_t g_pkG [B_SZ * D_OUT];
__device__ __align__(128) uint32_t g_pkX0[B_SZ * D_OUT];
__device__ __align__(128) uint32_t g_pkX1[B_SZ * D_OUT];
__device__ __align__(128) uint32_t g_pkU0[B_SZ * D_C];
__device__ __align__(128) uint32_t g_pkU1[B_SZ * D_C];

__device__ __forceinline__ void split2(float x, float y, uint32_t& hi, uint32_t& lo) {
    __half hx = __float2half_rn(x);
    __half hy = __float2half_rn(y);
    float rx = x - __half2float(hx);
    float ry = y - __half2float(hy);
    __half2 H = __halves2half2(hx, hy);
    hi = *reinterpret_cast<uint32_t*>(&H);
    __half2 L = __floats2half2_rn(rx, ry);
    lo = *reinterpret_cast<uint32_t*>(&L);
}

__global__ void transpose_k(const float* __restrict__ src, float* __restrict__ dst,
                            int rows, int cols) {
    __shared__ float t[32][33];
    int bx = blockIdx.x * 32, by = blockIdx.y * 32;
    int x = bx + threadIdx.x;
    #pragma unroll
    for (int j = 0; j < 32; j += 8)
        t[threadIdx.y + j][threadIdx.x] = src[(size_t)(by + threadIdx.y + j) * cols + x];
    __syncthreads();
    int x2 = by + threadIdx.x;
    #pragma unroll
    for (int j = 0; j < 32; j += 8)
        dst[(size_t)(bx + threadIdx.y + j) * rows + x2] = t[threadIdx.x][threadIdx.y + j];
}

__global__ void pack_k(const float* __restrict__ src, uint32_t* __restrict__ dst, int n8) {
    int i = blockIdx.x * blockDim.x + threadIdx.x;
    if (i >= n8) return;
    const float4* s = reinterpret_cast<const float4*>(src) + 2 * (size_t)i;
    float4 v0 = s[0], v1 = s[1];
    uint32_t h0,l0,h1,l1,h2,l2,h3,l3;
    split2(v0.x, v0.y, h0, l0); split2(v0.z, v0.w, h1, l1);
    split2(v1.x, v1.y, h2, l2); split2(v1.z, v1.w, h3, l3);
    uint4* d = reinterpret_cast<uint4*>(dst) + 2 * (size_t)i;
    uint4 H; H.x=h0; H.y=h1; H.z=h2; H.w=h3;
    uint4 L; L.x=l0; L.y=l1; L.z=l2; L.w=l3;
    d[0] = H; d[1] = L;
}

__global__ void vsum_k(const float* __restrict__ V, float* __restrict__ out) {
    __shared__ float red[256];
    int n = blockIdx.x;
    float s = 0.0f;
    for (int k = threadIdx.x; k < D_OUT; k += 256) s += V[(size_t)n * D_OUT + k];
    red[threadIdx.x] = s;
    __syncthreads();
    for (int st = 128; st > 0; st >>= 1) {
        if (threadIdx.x < st) red[threadIdx.x] += red[threadIdx.x + st];
        __syncthreads();
    }
    if (threadIdx.x == 0) out[n] = red[0];
}

template<int MODE>
__global__ void step0_k(const float* __restrict__ src, float* __restrict__ s,
                        float* __restrict__ a1, float* __restrict__ a2,
                        uint32_t* __restrict__ pk, int n8) {
    int i = blockIdx.x * blockDim.x + threadIdx.x;
    if (i >= n8) return;
    float gv[8];
    if (MODE == 0) {
        const float4* cs = reinterpret_cast<const float4*>(src) + 2 * (size_t)i;
        float4 v0 = cs[0], v1 = cs[1];
        gv[0]=v0.x; gv[1]=v0.y; gv[2]=v0.z; gv[3]=v0.w;
        gv[4]=v1.x; gv[5]=v1.y; gv[6]=v1.z; gv[7]=v1.w;
    } else {
        const float G0 = GAMMA_F * 1.0e-3f * (-0.5f);
        int base = (8 * i) & (D_C - 1);
        #pragma unroll
        for (int j = 0; j < 8; j++) gv[j] = G0 * src[base + j];
    }
    float xs[8], A1[8], A2[8];
    #pragma unroll
    for (int j = 0; j < 8; j++) {
        float g   = gv[j];
        float na1 = ONE_M_RHO_F * g * g;
        float upd = LR_F * g / sqrtf(na1 + EPS_F);
        float na2 = -upd;
        xs[j] = MOM_F * na2 - upd;
        A1[j] = na1; A2[j] = na2;
    }
    float4* so = reinterpret_cast<float4*>(s)  + 2 * (size_t)i;
    float4* o1 = reinterpret_cast<float4*>(a1) + 2 * (size_t)i;
    float4* o2 = reinterpret_cast<float4*>(a2) + 2 * (size_t)i;
    so[0] = make_float4(xs[0],xs[1],xs[2],xs[3]); so[1] = make_float4(xs[4],xs[5],xs[6],xs[7]);
    o1[0] = make_float4(A1[0],A1[1],A1[2],A1[3]); o1[1] = make_float4(A1[4],A1[5],A1[6],A1[7]);
    o2[0] = make_float4(A2[0],A2[1],A2[2],A2[3]); o2[1] = make_float4(A2[4],A2[5],A2[6],A2[7]);
    uint32_t h[4], l[4];
    split2(xs[0],xs[1],h[0],l[0]); split2(xs[2],xs[3],h[1],l[1]);
    split2(xs[4],xs[5],h[2],l[2]); split2(xs[6],xs[7],h[3],l[3]);
    uint4* d = reinterpret_cast<uint4*>(pk) + 2 * (size_t)i;
    uint4 H; H.x=h[0]; H.y=h[1]; H.z=h[2]; H.w=h[3];
    uint4 L; L.x=l[0]; L.y=l[1]; L.z=l[2]; L.w=l[3];
    d[0] = H; d[1] = L;
}

// ============================ mma helpers ============================

__device__ __forceinline__ uint32_t cvta_smem(const void* p) {
    uint32_t a;
    asm("{ .reg .u64 t; cvta.to.shared.u64 t, %1; cvt.u32.u64 %0, t; }" : "=r"(a) : "l"(p));
    return a;
}

__device__ __forceinline__ void mma_f16(float* c, const uint32_t* a, const uint32_t* b) {
    asm volatile(
        "mma.sync.aligned.m16n8k16.row.col.f32.f16.f16.f32 "
        "{%0,%1,%2,%3}, {%4,%5,%6,%7}, {%8,%9}, {%0,%1,%2,%3};"
        : "+f"(c[0]), "+f"(c[1]), "+f"(c[2]), "+f"(c[3])
        : "r"(a[0]), "r"(a[1]), "r"(a[2]), "r"(a[3]), "r"(b[0]), "r"(b[1]));
}

#define LDSM_X4(R, addr) \
    asm volatile("ldmatrix.sync.aligned.m8n8.x4.shared.b16 {%0,%1,%2,%3}, [%4];" \
        : "=r"((R)[0]), "=r"((R)[1]), "=r"((R)[2]), "=r"((R)[3]) : "r"(addr))

#define CP16(dst, src) \
    asm volatile("cp.async.cg.shared.global [%0], [%1], 16;" :: "r"(dst), "l"(src))

__device__ __forceinline__ void store_pk2(uint32_t* __restrict__ q, int ncols,
                                          int m, int n, float v0, float v1) {
    uint32_t hi, lo; split2(v0, v1, hi, lo);
    uint32_t* p = q + (size_t)m * ncols + ((n >> 3) << 3) + ((n & 7) >> 1);
    p[0] = hi;
    p[4] = lo;
}

// EPI 1: GEMM2: reads p0=x; writes q1=pkG, p2=T
// EPI 2: gx GEMM: g = acc + p4(c) + p0(T); rmsprop p1=x,p2=a1,p3=a2; q1=pkX
// EPI 3: gu GEMM: g = acc; rmsprop p1=u,p2=b1,p3=b2; q1=pkU
// EPI 4: setup M2: pack 2*acc -> q1
// EPI 5: setup c:  p1 = -2*acc
template<int EPI>
__device__ __forceinline__ void epi_pair(float a0, float a1, int m, int n, int Nout,
                                         const float* __restrict__ p0,
                                         const float* __restrict__ p4,
                                         float* __restrict__ p1,
                                         float* __restrict__ p2,
                                         float* __restrict__ p3,
                                         uint32_t* __restrict__ q1)
{
    const size_t idx = (size_t)m * (size_t)Nout + (size_t)n;
    if (EPI == 4) {
        store_pk2(q1, Nout, m, n, 2.0f * a0, 2.0f * a1);
    } else if (EPI == 5) {
        float2 o; o.x = -2.0f * a0; o.y = -2.0f * a1;
        *reinterpret_cast<float2*>(&p1[idx]) = o;
    } else if (EPI == 1) {
        float2 xv = *reinterpret_cast<const float2*>(&p0[idx]);
        float G0, G1; float2 T;
        {
            float da = sqrtf(xv.x * xv.x + 1e-6f);
            float ex = expf(-a0);
            G0  = GAMMA_F * da * (-0.5f * ex);
            T.x = (GAMMA_F * (1.0f + ex) * 0.5f + GAMMA_F * 0.1f) * (xv.x / da);
        }
        {
            float da = sqrtf(xv.y * xv.y + 1e-6f);
            float ex = expf(-a1);
            G1  = GAMMA_F * da * (-0.5f * ex);
            T.y = (GAMMA_F * (1.0f + ex) * 0.5f + GAMMA_F * 0.1f) * (xv.y / da);
        }
        store_pk2(q1, Nout, m, n, G0, G1);
        *reinterpret_cast<float2*>(&p2[idx]) = T;
    } else {
        float2 g2;
        if (EPI == 2) {
            float2 tv = *reinterpret_cast<const float2*>(&p0[idx]);
            float2 cv = *reinterpret_cast<const float2*>(&p4[idx]);
            g2.x = a0 + cv.x + tv.x;
            g2.y = a1 + cv.y + tv.y;
        } else {
            g2.x = a0; g2.y = a1;
        }
        float2 sv  = *reinterpret_cast<const float2*>(&p1[idx]);
        float2 a1v = *reinterpret_cast<const float2*>(&p2[idx]);
        float2 a2v = *reinterpret_cast<const float2*>(&p3[idx]);
        float na1x = RHO_F * a1v.x + ONE_M_RHO_F * g2.x * g2.x;
        float updx = LR_F * g2.x / sqrtf(na1x + EPS_F);
        float na2x = MOM_F * a2v.x - updx;
        float svx  = sv.x + MOM_F * na2x - updx;
        float na1y = RHO_F * a1v.y + ONE_M_RHO_F * g2.y * g2.y;
        float updy = LR_F * g2.y / sqrtf(na1y + EPS_F);
        float na2y = MOM_F * a2v.y - updy;
        float svy  = sv.y + MOM_F * na2y - updy;
        float2 o1; o1.x = svx;  o1.y = svy;
        float2 o2; o2.x = na1x; o2.y = na1y;
        float2 o3; o3.x = na2x; o3.y = na2y;
        *reinterpret_cast<float2*>(&p1[idx]) = o1;
        store_pk2(q1, Nout, m, n, svx, svy);
        *reinterpret_cast<float2*>(&p2[idx]) = o2;
        *reinterpret_cast<float2*>(&p3[idx]) = o3;
    }
}

// ---- shared mainloop: BM=128, BN=256, BK=32, S=3, 512 threads (16 warps 2x8)
// NMMA=2: acc += a_hi*(b_hi+b_lo)  (A lo never loaded — fp16 2-term)
// NMMA=3: acc += a_hi*b_hi + a_hi*b_lo + a_lo*b_hi  (near-exact, setup only)
struct Frag { float acc[4][4][4]; };

template<int NMMA>
__device__ __forceinline__ void mainloop_128x256(
    const uint32_t* __restrict__ pkA, const uint32_t* __restrict__ pkB,
    int row0, int col0, int K, uint32_t sbase, Frag& F)
{
    constexpr int S = 3;
    constexpr int STAGE = (128 + 256) * 128;   // 49152
    const int tid  = threadIdx.x;
    const int lane = tid & 31, wid = tid >> 5;
    const int wm = wid >> 3, wn = wid & 7;

    const char* gA = reinterpret_cast<const char*>(pkA) + (size_t)row0 * (4 * K);
    const char* gB = reinterpret_cast<const char*>(pkB) + (size_t)col0 * (4 * K);
    const int pitch = 4 * K;
    const int iters = K / 32;

    auto issue = [&](int kt, int buf) {
        const uint32_t sd = sbase + buf * STAGE;
        const char* sA = gA + kt * 128;
        if (NMMA == 3) {
            #pragma unroll
            for (int i = 0; i < 2; i++) {                   // all 8 chunks/row
                int idx = i * 512 + tid;
                int r = idx >> 3, c = idx & 7;
                uint32_t dst = sd + r * 128 + ((c ^ (r & 7)) << 4);
                CP16(dst, sA + (size_t)r * pitch + (c << 4));
            }
        } else {
            // hi chunks only: logical chunk 2g, g=0..3  (512 total)
            int r = tid >> 2, g = tid & 3;
            int c = 2 * g;
            uint32_t dst = sd + r * 128 + ((c ^ (r & 7)) << 4);
            CP16(dst, sA + (size_t)r * pitch + (c << 4));
        }
        const char* sB = gB + kt * 128;
        #pragma unroll
        for (int i = 0; i < 4; i++) {                       // 2048 chunks / 512 thr
            int idx = i * 512 + tid;
            int r = idx >> 3, c = idx & 7;
            uint32_t dst = sd + 128 * 128 + r * 128 + ((c ^ (r & 7)) << 4);
            CP16(dst, sB + (size_t)r * pitch + (c << 4));
        }
        asm volatile("cp.async.commit_group;" ::: "memory");
    };

    #pragma unroll
    for (int i = 0; i < 4; i++)
        #pragma unroll
        for (int j = 0; j < 4; j++)
            #pragma unroll
            for (int r = 0; r < 4; r++) F.acc[i][j][r] = 0.0f;

    issue(0, 0);
    issue(1, 1);

    for (int kt = 0; kt < iters; kt++) {
        if (kt < iters - 1) asm volatile("cp.async.wait_group 1;" ::: "memory");
        else                asm volatile("cp.async.wait_group 0;" ::: "memory");
        __syncthreads();
        if (kt + 2 < iters) issue(kt + 2, (kt + 2) % S);

        const int buf = kt % S;
        const uint32_t sA32 = sbase + buf * STAGE;
        const uint32_t sB32 = sA32 + 128 * 128;

        #pragma unroll
        for (int j = 0; j < 2; j++) {
            uint32_t afh[4][4];
            #pragma unroll
            for (int mf = 0; mf < 4; mf++) {
                int rr = wm * 64 + mf * 16 + (lane & 15);
                int c  = 4 * j + 2 * (lane >> 4);           // hi chunk
                uint32_t addr = sA32 + rr * 128 + ((c ^ (rr & 7)) << 4);
                LDSM_X4(afh[mf], addr);
            }
            uint32_t afl[4][4];
            if (NMMA == 3) {
                #pragma unroll
                for (int mf = 0; mf < 4; mf++) {
                    int rr = wm * 64 + mf * 16 + (lane & 15);
                    int c  = 4 * j + 1 + 2 * (lane >> 4);   // lo chunk
                    uint32_t addr = sA32 + rr * 128 + ((c ^ (rr & 7)) << 4);
                    LDSM_X4(afl[mf], addr);
                }
            }
            uint32_t bfr[2][4][2];
            #pragma unroll
            for (int hl = 0; hl < 2; hl++)
                #pragma unroll
                for (int p = 0; p < 2; p++) {
                    uint32_t q[4];
                    int rr = wn * 32 + (2 * p + (lane >> 4)) * 8 + (lane & 7);
                    int c  = 4 * j + hl + 2 * ((lane >> 3) & 1);
                    uint32_t addr = sB32 + rr * 128 + ((c ^ (rr & 7)) << 4);
                    LDSM_X4(q, addr);
                    bfr[hl][2 * p    ][0] = q[0]; bfr[hl][2 * p    ][1] = q[1];
                    bfr[hl][2 * p + 1][0] = q[2]; bfr[hl][2 * p + 1][1] = q[3];
                }
            #pragma unroll
            for (int mf = 0; mf < 4; mf++)
                #pragma unroll
                for (int nf = 0; nf < 4; nf++) {
                    mma_f16(F.acc[mf][nf], afh[mf], bfr[0][nf]);   // hi*hi
                    mma_f16(F.acc[mf][nf], afh[mf], bfr[1][nf]);   // hi*lo
                    if (NMMA == 3)
                        mma_f16(F.acc[mf][nf], afl[mf], bfr[0][nf]);  // lo*hi
                }
        }
    }
}

template<int EPI>
__device__ __forceinline__ void run_epi(Frag& F, int row0, int col0, int Nout,
                                        const float* p0, const float* p4,
                                        float* p1, float* p2, float* p3, uint32_t* q1)
{
    const int tid  = threadIdx.x;
    const int lane = tid & 31, wid = tid >> 5;
    const int wm = wid >> 3, wn = wid & 7;
    #pragma unroll
    for (int mf = 0; mf < 4; mf++) {
        #pragma unroll
        for (int nf = 0; nf < 4; nf++) {
            int mlo = row0 + wm * 64 + mf * 16 + (lane >> 2);
            int n   = col0 + wn * 32 + nf * 8 + ((lane & 3) << 1);
            epi_pair<EPI>(F.acc[mf][nf][0], F.acc[mf][nf][1], mlo,     n, Nout, p0, p4, p1, p2, p3, q1);
            epi_pair<EPI>(F.acc[mf][nf][2], F.acc[mf][nf][3], mlo + 8, n, Nout, p0, p4, p1, p2, p3, q1);
        }
    }
}

// GEMM2: s = u@V, EPI 1.  grid 128: col0=(b&7)*256, row0=(b>>3)*128
__global__ __launch_bounds__(512, 1)
void gemm2_k(const uint32_t* __restrict__ pkU, const uint32_t* __restrict__ pkVT,
             const float* __restrict__ x, float* __restrict__ pT,
             uint32_t* __restrict__ pkG)
{
    extern __shared__ __align__(1024) char smem[];
    Frag F;
    int col0 = (blockIdx.x & 7) * 256, row0 = (blockIdx.x >> 3) * 128;
    mainloop_128x256<2>(pkU, pkVT, row0, col0, D_C, cvta_smem(smem), F);
    run_epi<1>(F, row0, col0, D_OUT, x, nullptr, nullptr, pT, nullptr, pkG);
}

// merged gx + gu: blocks [0,128) = gx (EPI2), [128,144) = gu (EPI3). Single wave.
__global__ __launch_bounds__(512, 1)
void gemm34_k(const uint32_t* __restrict__ pkX, const uint32_t* __restrict__ pkM,
              const uint32_t* __restrict__ pkG, const uint32_t* __restrict__ pkV,
              const float* __restrict__ pT, const float* __restrict__ pc,
              float* __restrict__ x,  float* __restrict__ a1, float* __restrict__ a2,
              uint32_t* __restrict__ pkXw,
              float* __restrict__ u,  float* __restrict__ b1, float* __restrict__ b2,
              uint32_t* __restrict__ pkUw)
{
    extern __shared__ __align__(1024) char smem[];
    Frag F;
    const bool role4 = blockIdx.x >= 128;
    int row0, col0;
    const uint32_t *pkA, *pkB;
    if (!role4) {
        col0 = (blockIdx.x & 7) * 256; row0 = (blockIdx.x >> 3) * 128;
        pkA = pkX; pkB = pkM;
    } else {
        col0 = 0; row0 = (blockIdx.x - 128) * 128;
        pkA = pkG; pkB = pkV;
    }
    mainloop_128x256<2>(pkA, pkB, row0, col0, D_OUT, cvta_smem(smem), F);
    if (!role4)
        run_epi<2>(F, row0, col0, D_OUT, pT, pc, x, a1, a2, pkXw);
    else
        run_epi<3>(F, row0, col0, D_C, nullptr, nullptr, u, b1, b2, pkUw);
}

// merged setup: blocks [0,128) = M2 (EPI4), [128,256) = c (EPI5); K=1024, 3-term
__global__ __launch_bounds__(512, 1)
void setup_k(const uint32_t* __restrict__ pkW, const uint32_t* __restrict__ pkIn,
             uint32_t* __restrict__ pkM, float* __restrict__ pc)
{
    extern __shared__ __align__(1024) char smem[];
    Frag F;
    const bool rolec = blockIdx.x >= 128;
    int b = rolec ? blockIdx.x - 128 : blockIdx.x;
    int col0 = (b & 7) * 256, row0 = (b >> 3) * 128;
    const uint32_t* pkA = rolec ? pkIn : pkW;
    mainloop_128x256<3>(pkA, pkW, row0, col0, D_IN, cvta_smem(smem), F);
    if (!rolec)
        run_epi<4>(F, row0, col0, D_OUT, nullptr, nullptr, nullptr, nullptr, nullptr, pkM);
    else
        run_epi<5>(F, row0, col0, D_OUT, nullptr, nullptr, pc, nullptr, nullptr, nullptr);
}

// ============================================================================

extern "C" void kernel_launch(void* const* d_in, const int* in_sizes, int n_in,
                              void* d_out, int out_size)
{
    (void)in_sizes; (void)n_in; (void)out_size;
    const float* inputs = (const float*)d_in[0];
    const float* W      = (const float*)d_in[1];
    const float* V      = (const float*)d_in[2];
    float* x = (float*)d_out;

    float *pT, *pa1, *pa2, *pu, *pb1, *pb2, *pVT, *pc, *pvs;
    uint32_t *kW, *kV, *kVT, *kIn, *kM, *kG, *kX[2], *kU[2];
    cudaGetSymbolAddress((void**)&pT,  g_T);
    cudaGetSymbolAddress((void**)&pa1, g_a1);
    cudaGetSymbolAddress((void**)&pa2, g_a2);
    cudaGetSymbolAddress((void**)&pu,  g_u);
    cudaGetSymbolAddress((void**)&pb1, g_b1);
    cudaGetSymbolAddress((void**)&pb2, g_b2);
    cudaGetSymbolAddress((void**)&pVT, g_VT);
    cudaGetSymbolAddress((void**)&pc,  g_c);
    cudaGetSymbolAddress((void**)&pvs, g_vs);
    cudaGetSymbolAddress((void**)&kW,  g_pkW);
    cudaGetSymbolAddress((void**)&kV,  g_pkV);
    cudaGetSymbolAddress((void**)&kVT, g_pkVT);
    cudaGetSymbolAddress((void**)&kIn, g_pkIn);
    cudaGetSymbolAddress((void**)&kM,  g_pkM);
    cudaGetSymbolAddress((void**)&kG,  g_pkG);
    cudaGetSymbolAddress((void**)&kX[0], g_pkX0);
    cudaGetSymbolAddress((void**)&kX[1], g_pkX1);
    cudaGetSymbolAddress((void**)&kU[0], g_pkU0);
    cudaGetSymbolAddress((void**)&kU[1], g_pkU1);

    constexpr int SMEM = 3 * (128 + 256) * 128;   // 147456
    cudaFuncSetAttribute(gemm2_k,  cudaFuncAttributeMaxDynamicSharedMemorySize, SMEM);
    cudaFuncSetAttribute(gemm34_k, cudaFuncAttributeMaxDynamicSharedMemorySize, SMEM);
    cudaFuncSetAttribute(setup_k,  cudaFuncAttributeMaxDynamicSharedMemorySize, SMEM);

    const int TPB = 256;

    // ---- setup: transpose/pack; merged M2 = 2*W@W^T and c = -2*inputs@W^T ----
    transpose_k<<<dim3(D_OUT / 32, D_C / 32), dim3(32, 8)>>>(V, pVT, D_C, D_OUT);
    pack_k<<<(D_OUT * D_IN / 8 + TPB - 1) / TPB, TPB>>>(W,      kW,  D_OUT * D_IN / 8);
    pack_k<<<(D_C * D_OUT / 8 + TPB - 1) / TPB, TPB>>>(V,       kV,  D_C * D_OUT / 8);
    pack_k<<<(D_OUT * D_C / 8 + TPB - 1) / TPB, TPB>>>(pVT,     kVT, D_OUT * D_C / 8);
    pack_k<<<(B_SZ * D_IN / 8 + TPB - 1) / TPB, TPB>>>(inputs,  kIn, B_SZ * D_IN / 8);

    setup_k<<<256, 512, SMEM>>>(kW, kIn, kM, pc);

    // ---- step 0: x from g=c ; u from g = G0 * rowsum(V) broadcast ----
    vsum_k<<<D_C, 256>>>(V, pvs);
    step0_k<0><<<(B_SZ * D_OUT / 8 + TPB - 1) / TPB, TPB>>>(
        pc, x, pa1, pa2, kX[0], B_SZ * D_OUT / 8);
    step0_k<1><<<(B_SZ * D_C / 8 + TPB - 1) / TPB, TPB>>>(
        pvs, pu, pb1, pb2, kU[0], B_SZ * D_C / 8);

    // ---- steps 1..9: GEMM2 then single-wave merged gx+gu ----
    for (int s = 1; s < 10; s++) {
        const int rd = (s - 1) & 1, wr = s & 1;
        gemm2_k<<<128, 512, SMEM>>>(kU[rd], kVT, x, pT, kG);
        gemm34_k<<<144, 512, SMEM>>>(kX[rd], kM, kG, kV, pT, pc,
                                     x, pa1, pa2, kX[wr],
                                     pu, pb1, pb2, kU[wr]);
    }
}

// round 9
// speedup vs baseline: 5.8477x; 1.0362x over previous
#include <cuda_runtime.h>
#include <cuda_fp16.h>
#include <cstdint>
#include <math.h>

#define B_SZ  2048
#define D_IN  1024
#define D_OUT 2048
#define D_C   256

#define GAMMA_F 0.1f
#define RHO_F   0.9f
#define ONE_M_RHO_F 0.1f
#define LR_F    0.009f
#define MOM_F   0.9f
#define EPS_F   1e-8f

// ---- fp32 state / scratch ----
__device__ float g_T  [B_SZ * D_OUT];
__device__ float g_a1 [B_SZ * D_OUT];
__device__ float g_a2 [B_SZ * D_OUT];
__device__ float g_u  [B_SZ * D_C];
__device__ float g_b1 [B_SZ * D_C];
__device__ float g_b2 [B_SZ * D_C];
__device__ float g_VT [D_OUT * D_C];
__device__ float g_c  [B_SZ * D_OUT];     // -2 * inputs @ W^T
__device__ float g_vs [D_C];              // rowsum of V
__device__ float g_d  [D_OUT];            // diag of 2*W@W^T

// ---- packed fp16 hi/lo operands (per 8-elem group: 4 hi words then 4 lo) ----
__device__ __align__(128) uint32_t g_pkW [D_OUT * D_IN];
__device__ __align__(128) uint32_t g_pkV [D_C * D_OUT];
__device__ __align__(128) uint32_t g_pkVT[D_OUT * D_C];
__device__ __align__(128) uint32_t g_pkIn[B_SZ * D_IN];
__device__ __align__(128) uint32_t g_pkR [D_OUT * D_OUT];   // 2*W@W^T minus diag
__device__ __align__(128) uint32_t g_pkG [B_SZ * D_OUT];
__device__ __align__(128) uint32_t g_pkX0[B_SZ * D_OUT];
__device__ __align__(128) uint32_t g_pkX1[B_SZ * D_OUT];
__device__ __align__(128) uint32_t g_pkU0[B_SZ * D_C];
__device__ __align__(128) uint32_t g_pkU1[B_SZ * D_C];

__device__ __forceinline__ void split2(float x, float y, uint32_t& hi, uint32_t& lo) {
    __half hx = __float2half_rn(x);
    __half hy = __float2half_rn(y);
    float rx = x - __half2float(hx);
    float ry = y - __half2float(hy);
    __half2 H = __halves2half2(hx, hy);
    hi = *reinterpret_cast<uint32_t*>(&H);
    __half2 L = __floats2half2_rn(rx, ry);
    lo = *reinterpret_cast<uint32_t*>(&L);
}

__global__ void transpose_k(const float* __restrict__ src, float* __restrict__ dst,
                            int rows, int cols) {
    __shared__ float t[32][33];
    int bx = blockIdx.x * 32, by = blockIdx.y * 32;
    int x = bx + threadIdx.x;
    #pragma unroll
    for (int j = 0; j < 32; j += 8)
        t[threadIdx.y + j][threadIdx.x] = src[(size_t)(by + threadIdx.y + j) * cols + x];
    __syncthreads();
    int x2 = by + threadIdx.x;
    #pragma unroll
    for (int j = 0; j < 32; j += 8)
        dst[(size_t)(bx + threadIdx.y + j) * rows + x2] = t[threadIdx.x][threadIdx.y + j];
}

__global__ void pack_k(const float* __restrict__ src, uint32_t* __restrict__ dst, int n8) {
    int i = blockIdx.x * blockDim.x + threadIdx.x;
    if (i >= n8) return;
    const float4* s = reinterpret_cast<const float4*>(src) + 2 * (size_t)i;
    float4 v0 = s[0], v1 = s[1];
    uint32_t h0,l0,h1,l1,h2,l2,h3,l3;
    split2(v0.x, v0.y, h0, l0); split2(v0.z, v0.w, h1, l1);
    split2(v1.x, v1.y, h2, l2); split2(v1.z, v1.w, h3, l3);
    uint4* d = reinterpret_cast<uint4*>(dst) + 2 * (size_t)i;
    uint4 H; H.x=h0; H.y=h1; H.z=h2; H.w=h3;
    uint4 L; L.x=l0; L.y=l1; L.z=l2; L.w=l3;
    d[0] = H; d[1] = L;
}

__global__ void vsum_k(const float* __restrict__ V, float* __restrict__ out) {
    __shared__ float red[256];
    int n = blockIdx.x;
    float s = 0.0f;
    for (int k = threadIdx.x; k < D_OUT; k += 256) s += V[(size_t)n * D_OUT + k];
    red[threadIdx.x] = s;
    __syncthreads();
    for (int st = 128; st > 0; st >>= 1) {
        if (threadIdx.x < st) red[threadIdx.x] += red[threadIdx.x + st];
        __syncthreads();
    }
    if (threadIdx.x == 0) out[n] = red[0];
}

template<int MODE>
__global__ void step0_k(const float* __restrict__ src, float* __restrict__ s,
                        float* __restrict__ a1, float* __restrict__ a2,
                        uint32_t* __restrict__ pk, int n8) {
    int i = blockIdx.x * blockDim.x + threadIdx.x;
    if (i >= n8) return;
    float gv[8];
    if (MODE == 0) {
        const float4* cs = reinterpret_cast<const float4*>(src) + 2 * (size_t)i;
        float4 v0 = cs[0], v1 = cs[1];
        gv[0]=v0.x; gv[1]=v0.y; gv[2]=v0.z; gv[3]=v0.w;
        gv[4]=v1.x; gv[5]=v1.y; gv[6]=v1.z; gv[7]=v1.w;
    } else {
        const float G0 = GAMMA_F * 1.0e-3f * (-0.5f);
        int base = (8 * i) & (D_C - 1);
        #pragma unroll
        for (int j = 0; j < 8; j++) gv[j] = G0 * src[base + j];
    }
    float xs[8], A1[8], A2[8];
    #pragma unroll
    for (int j = 0; j < 8; j++) {
        float g   = gv[j];
        float na1 = ONE_M_RHO_F * g * g;
        float upd = LR_F * g / sqrtf(na1 + EPS_F);
        float na2 = -upd;
        xs[j] = MOM_F * na2 - upd;
        A1[j] = na1; A2[j] = na2;
    }
    float4* so = reinterpret_cast<float4*>(s)  + 2 * (size_t)i;
    float4* o1 = reinterpret_cast<float4*>(a1) + 2 * (size_t)i;
    float4* o2 = reinterpret_cast<float4*>(a2) + 2 * (size_t)i;
    so[0] = make_float4(xs[0],xs[1],xs[2],xs[3]); so[1] = make_float4(xs[4],xs[5],xs[6],xs[7]);
    o1[0] = make_float4(A1[0],A1[1],A1[2],A1[3]); o1[1] = make_float4(A1[4],A1[5],A1[6],A1[7]);
    o2[0] = make_float4(A2[0],A2[1],A2[2],A2[3]); o2[1] = make_float4(A2[4],A2[5],A2[6],A2[7]);
    uint32_t h[4], l[4];
    split2(xs[0],xs[1],h[0],l[0]); split2(xs[2],xs[3],h[1],l[1]);
    split2(xs[4],xs[5],h[2],l[2]); split2(xs[6],xs[7],h[3],l[3]);
    uint4* d = reinterpret_cast<uint4*>(pk) + 2 * (size_t)i;
    uint4 H; H.x=h[0]; H.y=h[1]; H.z=h[2]; H.w=h[3];
    uint4 L; L.x=l[0]; L.y=l[1]; L.z=l[2]; L.w=l[3];
    d[0] = H; d[1] = L;
}

// ============================ mma helpers ============================

__device__ __forceinline__ uint32_t cvta_smem(const void* p) {
    uint32_t a;
    asm("{ .reg .u64 t; cvta.to.shared.u64 t, %1; cvt.u32.u64 %0, t; }" : "=r"(a) : "l"(p));
    return a;
}

__device__ __forceinline__ void mma_f16(float* c, const uint32_t* a, const uint32_t* b) {
    asm volatile(
        "mma.sync.aligned.m16n8k16.row.col.f32.f16.f16.f32 "
        "{%0,%1,%2,%3}, {%4,%5,%6,%7}, {%8,%9}, {%0,%1,%2,%3};"
        : "+f"(c[0]), "+f"(c[1]), "+f"(c[2]), "+f"(c[3])
        : "r"(a[0]), "r"(a[1]), "r"(a[2]), "r"(a[3]), "r"(b[0]), "r"(b[1]));
}

#define LDSM_X4(R, addr) \
    asm volatile("ldmatrix.sync.aligned.m8n8.x4.shared.b16 {%0,%1,%2,%3}, [%4];" \
        : "=r"((R)[0]), "=r"((R)[1]), "=r"((R)[2]), "=r"((R)[3]) : "r"(addr))

#define CP16(dst, src) \
    asm volatile("cp.async.cg.shared.global [%0], [%1], 16;" :: "r"(dst), "l"(src))

__device__ __forceinline__ void store_pk2(uint32_t* __restrict__ q, int ncols,
                                          int m, int n, float v0, float v1) {
    uint32_t hi, lo; split2(v0, v1, hi, lo);
    uint32_t* p = q + (size_t)m * ncols + ((n >> 3) << 3) + ((n & 7) >> 1);
    p[0] = hi;
    p[4] = lo;
}

// EPI 1: GEMM2: reads p0=x; writes q1=pkG, p2=T
// EPI 2: gx GEMM: g = acc + x*d[n] + p4(c) + p0(T); rmsprop p1=x,p2=a1,p3=a2; q1=pkX
// EPI 3: gu GEMM: g = acc; rmsprop p1=u,p2=b1,p3=b2; q1=pkU
// EPI 4: setup M2: diag -> p1(d), pack off-diag 2*acc -> q1
// EPI 5: setup c:  p1 = -2*acc
template<int EPI>
__device__ __forceinline__ void epi_pair(float a0, float a1, int m, int n, int Nout,
                                         const float* __restrict__ p0,
                                         const float* __restrict__ p4,
                                         const float* __restrict__ pd,
                                         float* __restrict__ p1,
                                         float* __restrict__ p2,
                                         float* __restrict__ p3,
                                         uint32_t* __restrict__ q1)
{
    const size_t idx = (size_t)m * (size_t)Nout + (size_t)n;
    if (EPI == 4) {
        float v0 = 2.0f * a0, v1 = 2.0f * a1;
        if (m == n)     { p1[m] = v0; v0 = 0.0f; }
        if (m == n + 1) { p1[m] = v1; v1 = 0.0f; }
        store_pk2(q1, Nout, m, n, v0, v1);
    } else if (EPI == 5) {
        float2 o; o.x = -2.0f * a0; o.y = -2.0f * a1;
        *reinterpret_cast<float2*>(&p1[idx]) = o;
    } else if (EPI == 1) {
        float2 xv = *reinterpret_cast<const float2*>(&p0[idx]);
        float G0, G1; float2 T;
        {
            float da = sqrtf(xv.x * xv.x + 1e-6f);
            float ex = expf(-a0);
            G0  = GAMMA_F * da * (-0.5f * ex);
            T.x = (GAMMA_F * (1.0f + ex) * 0.5f + GAMMA_F * 0.1f) * (xv.x / da);
        }
        {
            float da = sqrtf(xv.y * xv.y + 1e-6f);
            float ex = expf(-a1);
            G1  = GAMMA_F * da * (-0.5f * ex);
            T.y = (GAMMA_F * (1.0f + ex) * 0.5f + GAMMA_F * 0.1f) * (xv.y / da);
        }
        store_pk2(q1, Nout, m, n, G0, G1);
        *reinterpret_cast<float2*>(&p2[idx]) = T;
    } else {
        float2 sv  = *reinterpret_cast<const float2*>(&p1[idx]);
        float2 g2;
        if (EPI == 2) {
            float2 tv = *reinterpret_cast<const float2*>(&p0[idx]);
            float2 cv = *reinterpret_cast<const float2*>(&p4[idx]);
            float2 dv = *reinterpret_cast<const float2*>(&pd[n]);
            g2.x = a0 + sv.x * dv.x + cv.x + tv.x;
            g2.y = a1 + sv.y * dv.y + cv.y + tv.y;
        } else {
            g2.x = a0; g2.y = a1;
        }
        float2 a1v = *reinterpret_cast<const float2*>(&p2[idx]);
        float2 a2v = *reinterpret_cast<const float2*>(&p3[idx]);
        float na1x = RHO_F * a1v.x + ONE_M_RHO_F * g2.x * g2.x;
        float updx = LR_F * g2.x / sqrtf(na1x + EPS_F);
        float na2x = MOM_F * a2v.x - updx;
        float svx  = sv.x + MOM_F * na2x - updx;
        float na1y = RHO_F * a1v.y + ONE_M_RHO_F * g2.y * g2.y;
        float updy = LR_F * g2.y / sqrtf(na1y + EPS_F);
        float na2y = MOM_F * a2v.y - updy;
        float svy  = sv.y + MOM_F * na2y - updy;
        float2 o1; o1.x = svx;  o1.y = svy;
        float2 o2; o2.x = na1x; o2.y = na1y;
        float2 o3; o3.x = na2x; o3.y = na2y;
        *reinterpret_cast<float2*>(&p1[idx]) = o1;
        store_pk2(q1, Nout, m, n, svx, svy);
        *reinterpret_cast<float2*>(&p2[idx]) = o2;
        *reinterpret_cast<float2*>(&p3[idx]) = o3;
    }
}

// ---- shared mainloop: BM=128, BN=256, BK=32, S=3, 512 threads (16 warps 2x8)
// NMMA=1: acc += a_hi*b_hi                       (gx GEMM on residual R)
// NMMA=2: acc += a_hi*(b_hi+b_lo)                (fp16 2-term)
// NMMA=3: acc += a_hi*b_hi + a_hi*b_lo + a_lo*b_hi  (near-exact, setup only)
struct Frag { float acc[4][4][4]; };

template<int NMMA>
__device__ __forceinline__ void mainloop_128x256(
    const uint32_t* __restrict__ pkA, const uint32_t* __restrict__ pkB,
    int row0, int col0, int K, uint32_t sbase, Frag& F)
{
    constexpr int S = 3;
    constexpr int STAGE = (128 + 256) * 128;   // 49152
    const int tid  = threadIdx.x;
    const int lane = tid & 31, wid = tid >> 5;
    const int wm = wid >> 3, wn = wid & 7;

    const char* gA = reinterpret_cast<const char*>(pkA) + (size_t)row0 * (4 * K);
    const char* gB = reinterpret_cast<const char*>(pkB) + (size_t)col0 * (4 * K);
    const int pitch = 4 * K;
    const int iters = K / 32;

    auto issue = [&](int kt, int buf) {
        const uint32_t sd = sbase + buf * STAGE;
        const char* sA = gA + kt * 128;
        if (NMMA == 3) {
            #pragma unroll
            for (int i = 0; i < 2; i++) {                   // all 8 chunks/row
                int idx = i * 512 + tid;
                int r = idx >> 3, c = idx & 7;
                uint32_t dst = sd + r * 128 + ((c ^ (r & 7)) << 4);
                CP16(dst, sA + (size_t)r * pitch + (c << 4));
            }
        } else {
            // hi chunks only (512 total)
            int r = tid >> 2, g = tid & 3;
            int c = 2 * g;
            uint32_t dst = sd + r * 128 + ((c ^ (r & 7)) << 4);
            CP16(dst, sA + (size_t)r * pitch + (c << 4));
        }
        const char* sB = gB + kt * 128;
        if (NMMA >= 2) {
            #pragma unroll
            for (int i = 0; i < 4; i++) {                   // 2048 chunks
                int idx = i * 512 + tid;
                int r = idx >> 3, c = idx & 7;
                uint32_t dst = sd + 128 * 128 + r * 128 + ((c ^ (r & 7)) << 4);
                CP16(dst, sB + (size_t)r * pitch + (c << 4));
            }
        } else {
            #pragma unroll
            for (int i = 0; i < 2; i++) {                   // hi chunks only (1024)
                int idx = i * 512 + tid;
                int r = idx >> 2, g = idx & 3;
                int c = 2 * g;
                uint32_t dst = sd + 128 * 128 + r * 128 + ((c ^ (r & 7)) << 4);
                CP16(dst, sB + (size_t)r * pitch + (c << 4));
            }
        }
        asm volatile("cp.async.commit_group;" ::: "memory");
    };

    #pragma unroll
    for (int i = 0; i < 4; i++)
        #pragma unroll
        for (int j = 0; j < 4; j++)
            #pragma unroll
            for (int r = 0; r < 4; r++) F.acc[i][j][r] = 0.0f;

    issue(0, 0);
    issue(1, 1);

    for (int kt = 0; kt < iters; kt++) {
        if (kt < iters - 1) asm volatile("cp.async.wait_group 1;" ::: "memory");
        else                asm volatile("cp.async.wait_group 0;" ::: "memory");
        __syncthreads();
        if (kt + 2 < iters) issue(kt + 2, (kt + 2) % S);

        const int buf = kt % S;
        const uint32_t sA32 = sbase + buf * STAGE;
        const uint32_t sB32 = sA32 + 128 * 128;

        #pragma unroll
        for (int j = 0; j < 2; j++) {
            uint32_t afh[4][4];
            #pragma unroll
            for (int mf = 0; mf < 4; mf++) {
                int rr = wm * 64 + mf * 16 + (lane & 15);
                int c  = 4 * j + 2 * (lane >> 4);           // hi chunk
                uint32_t addr = sA32 + rr * 128 + ((c ^ (rr & 7)) << 4);
                LDSM_X4(afh[mf], addr);
            }
            uint32_t afl[4][4];
            if (NMMA == 3) {
                #pragma unroll
                for (int mf = 0; mf < 4; mf++) {
                    int rr = wm * 64 + mf * 16 + (lane & 15);
                    int c  = 4 * j + 1 + 2 * (lane >> 4);   // lo chunk
                    uint32_t addr = sA32 + rr * 128 + ((c ^ (rr & 7)) << 4);
                    LDSM_X4(afl[mf], addr);
                }
            }
            constexpr int NB = (NMMA >= 2) ? 2 : 1;
            uint32_t bfr[NB][4][2];
            #pragma unroll
            for (int hl = 0; hl < NB; hl++)
                #pragma unroll
                for (int p = 0; p < 2; p++) {
                    uint32_t q[4];
                    int rr = wn * 32 + (2 * p + (lane >> 4)) * 8 + (lane & 7);
                    int c  = 4 * j + hl + 2 * ((lane >> 3) & 1);
                    uint32_t addr = sB32 + rr * 128 + ((c ^ (rr & 7)) << 4);
                    LDSM_X4(q, addr);
                    bfr[hl][2 * p    ][0] = q[0]; bfr[hl][2 * p    ][1] = q[1];
                    bfr[hl][2 * p + 1][0] = q[2]; bfr[hl][2 * p + 1][1] = q[3];
                }
            #pragma unroll
            for (int mf = 0; mf < 4; mf++)
                #pragma unroll
                for (int nf = 0; nf < 4; nf++) {
                    mma_f16(F.acc[mf][nf], afh[mf], bfr[0][nf]);        // hi*hi
                    if (NMMA >= 2)
                        mma_f16(F.acc[mf][nf], afh[mf], bfr[1][nf]);    // hi*lo
                    if (NMMA == 3)
                        mma_f16(F.acc[mf][nf], afl[mf], bfr[0][nf]);    // lo*hi
                }
        }
    }
}

template<int EPI>
__device__ __forceinline__ void run_epi(Frag& F, int row0, int col0, int Nout,
                                        const float* p0, const float* p4, const float* pd,
                                        float* p1, float* p2, float* p3, uint32_t* q1)
{
    const int tid  = threadIdx.x;
    const int lane = tid & 31, wid = tid >> 5;
    const int wm = wid >> 3, wn = wid & 7;
    #pragma unroll
    for (int mf = 0; mf < 4; mf++) {
        #pragma unroll
        for (int nf = 0; nf < 4; nf++) {
            int mlo = row0 + wm * 64 + mf * 16 + (lane >> 2);
            int n   = col0 + wn * 32 + nf * 8 + ((lane & 3) << 1);
            epi_pair<EPI>(F.acc[mf][nf][0], F.acc[mf][nf][1], mlo,     n, Nout, p0, p4, pd, p1, p2, p3, q1);
            epi_pair<EPI>(F.acc[mf][nf][2], F.acc[mf][nf][3], mlo + 8, n, Nout, p0, p4, pd, p1, p2, p3, q1);
        }
    }
}

// GEMM2: s = u@V, EPI 1.  grid 128
__global__ __launch_bounds__(512, 1)
void gemm2_k(const uint32_t* __restrict__ pkU, const uint32_t* __restrict__ pkVT,
             const float* __restrict__ x, float* __restrict__ pT,
             uint32_t* __restrict__ pkG)
{
    extern __shared__ __align__(1024) char smem[];
    Frag F;
    int col0 = (blockIdx.x & 7) * 256, row0 = (blockIdx.x >> 3) * 128;
    mainloop_128x256<2>(pkU, pkVT, row0, col0, D_C, cvta_smem(smem), F);
    run_epi<1>(F, row0, col0, D_OUT, x, nullptr, nullptr, nullptr, pT, nullptr, pkG);
}

// merged gx + gu: blocks [0,128) = gx (EPI2, 1-term on R), [128,144) = gu (EPI3)
__global__ __launch_bounds__(512, 1)
void gemm34_k(const uint32_t* __restrict__ pkX, const uint32_t* __restrict__ pkR,
              const uint32_t* __restrict__ pkG, const uint32_t* __restrict__ pkV,
              const float* __restrict__ pT, const float* __restrict__ pc,
              const float* __restrict__ pd,
              float* __restrict__ x,  float* __restrict__ a1, float* __restrict__ a2,
              uint32_t* __restrict__ pkXw,
              float* __restrict__ u,  float* __restrict__ b1, float* __restrict__ b2,
              uint32_t* __restrict__ pkUw)
{
    extern __shared__ __align__(1024) char smem[];
    Frag F;
    if (blockIdx.x < 128) {
        int col0 = (blockIdx.x & 7) * 256, row0 = (blockIdx.x >> 3) * 128;
        mainloop_128x256<1>(pkX, pkR, row0, col0, D_OUT, cvta_smem(smem), F);
        run_epi<2>(F, row0, col0, D_OUT, pT, pc, pd, x, a1, a2, pkXw);
    } else {
        int col0 = 0, row0 = (blockIdx.x - 128) * 128;
        mainloop_128x256<2>(pkG, pkV, row0, col0, D_OUT, cvta_smem(smem), F);
        run_epi<3>(F, row0, col0, D_C, nullptr, nullptr, nullptr, u, b1, b2, pkUw);
    }
}

// merged setup: blocks [0,128) = M2->diag+R (EPI4), [128,256) = c (EPI5); K=1024, 3-term
__global__ __launch_bounds__(512, 1)
void setup_k(const uint32_t* __restrict__ pkW, const uint32_t* __restrict__ pkIn,
             uint32_t* __restrict__ pkR, float* __restrict__ pdiag, float* __restrict__ pc)
{
    extern __shared__ __align__(1024) char smem[];
    Frag F;
    const bool rolec = blockIdx.x >= 128;
    int b = rolec ? blockIdx.x - 128 : blockIdx.x;
    int col0 = (b & 7) * 256, row0 = (b >> 3) * 128;
    const uint32_t* pkA = rolec ? pkIn : pkW;
    mainloop_128x256<3>(pkA, pkW, row0, col0, D_IN, cvta_smem(smem), F);
    if (!rolec)
        run_epi<4>(F, row0, col0, D_OUT, nullptr, nullptr, nullptr, pdiag, nullptr, nullptr, pkR);
    else
        run_epi<5>(F, row0, col0, D_OUT, nullptr, nullptr, nullptr, pc, nullptr, nullptr, nullptr);
}

// ============================================================================

extern "C" void kernel_launch(void* const* d_in, const int* in_sizes, int n_in,
                              void* d_out, int out_size)
{
    (void)in_sizes; (void)n_in; (void)out_size;
    const float* inputs = (const float*)d_in[0];
    const float* W      = (const float*)d_in[1];
    const float* V      = (const float*)d_in[2];
    float* x = (float*)d_out;

    float *pT, *pa1, *pa2, *pu, *pb1, *pb2, *pVT, *pc, *pvs, *pd;
    uint32_t *kW, *kV, *kVT, *kIn, *kR, *kG, *kX[2], *kU[2];
    cudaGetSymbolAddress((void**)&pT,  g_T);
    cudaGetSymbolAddress((void**)&pa1, g_a1);
    cudaGetSymbolAddress((void**)&pa2, g_a2);
    cudaGetSymbolAddress((void**)&pu,  g_u);
    cudaGetSymbolAddress((void**)&pb1, g_b1);
    cudaGetSymbolAddress((void**)&pb2, g_b2);
    cudaGetSymbolAddress((void**)&pVT, g_VT);
    cudaGetSymbolAddress((void**)&pc,  g_c);
    cudaGetSymbolAddress((void**)&pvs, g_vs);
    cudaGetSymbolAddress((void**)&pd,  g_d);
    cudaGetSymbolAddress((void**)&kW,  g_pkW);
    cudaGetSymbolAddress((void**)&kV,  g_pkV);
    cudaGetSymbolAddress((void**)&kVT, g_pkVT);
    cudaGetSymbolAddress((void**)&kIn, g_pkIn);
    cudaGetSymbolAddress((void**)&kR,  g_pkR);
    cudaGetSymbolAddress((void**)&kG,  g_pkG);
    cudaGetSymbolAddress((void**)&kX[0], g_pkX0);
    cudaGetSymbolAddress((void**)&kX[1], g_pkX1);
    cudaGetSymbolAddress((void**)&kU[0], g_pkU0);
    cudaGetSymbolAddress((void**)&kU[1], g_pkU1);

    constexpr int SMEM = 3 * (128 + 256) * 128;   // 147456
    cudaFuncSetAttribute(gemm2_k,  cudaFuncAttributeMaxDynamicSharedMemorySize, SMEM);
    cudaFuncSetAttribute(gemm34_k, cudaFuncAttributeMaxDynamicSharedMemorySize, SMEM);
    cudaFuncSetAttribute(setup_k,  cudaFuncAttributeMaxDynamicSharedMemorySize, SMEM);

    const int TPB = 256;

    // ---- setup: transpose/pack; merged (diag+R) = 2*W@W^T and c = -2*inputs@W^T
    transpose_k<<<dim3(D_OUT / 32, D_C / 32), dim3(32, 8)>>>(V, pVT, D_C, D_OUT);
    pack_k<<<(D_OUT * D_IN / 8 + TPB - 1) / TPB, TPB>>>(W,      kW,  D_OUT * D_IN / 8);
    pack_k<<<(D_C * D_OUT / 8 + TPB - 1) / TPB, TPB>>>(V,       kV,  D_C * D_OUT / 8);
    pack_k<<<(D_OUT * D_C / 8 + TPB - 1) / TPB, TPB>>>(pVT,     kVT, D_OUT * D_C / 8);
    pack_k<<<(B_SZ * D_IN / 8 + TPB - 1) / TPB, TPB>>>(inputs,  kIn, B_SZ * D_IN / 8);

    setup_k<<<256, 512, SMEM>>>(kW, kIn, kR, pd, pc);

    // ---- step 0: x from g=c ; u from g = G0 * rowsum(V) broadcast ----
    vsum_k<<<D_C, 256>>>(V, pvs);
    step0_k<0><<<(B_SZ * D_OUT / 8 + TPB - 1) / TPB, TPB>>>(
        pc, x, pa1, pa2, kX[0], B_SZ * D_OUT / 8);
    step0_k<1><<<(B_SZ * D_C / 8 + TPB - 1) / TPB, TPB>>>(
        pvs, pu, pb1, pb2, kU[0], B_SZ * D_C / 8);

    // ---- steps 1..9: GEMM2 then single-wave merged gx+gu ----
    for (int s = 1; s < 10; s++) {
        const int rd = (s - 1) & 1, wr = s & 1;
        gemm2_k<<<128, 512, SMEM>>>(kU[rd], kVT, x, pT, kG);
        gemm34_k<<<144, 512, SMEM>>>(kX[rd], kR, kG, kV, pT, pc, pd,
                                     x, pa1, pa2, kX[wr],
                                     pu, pb1, pb2, kU[wr]);
    }
}

// round 10
// speedup vs baseline: 6.6029x; 1.1291x over previous
#include <cuda_runtime.h>
#include <cuda_fp16.h>
#include <cstdint>
#include <math.h>

#define B_SZ  2048
#define D_IN  1024
#define D_OUT 2048
#define D_C   256

#define GAMMA_F 0.1f
#define RHO_F   0.9f
#define ONE_M_RHO_F 0.1f
#define LR_F    0.009f
#define MOM_F   0.9f
#define EPS_F   1e-8f

// ---- fp32 state / scratch ----
__device__ float g_T  [B_SZ * D_OUT];
__device__ float g_a1 [B_SZ * D_OUT];
__device__ float g_a2 [B_SZ * D_OUT];
__device__ float g_u  [B_SZ * D_C];
__device__ float g_b1 [B_SZ * D_C];
__device__ float g_b2 [B_SZ * D_C];
__device__ float g_VT [D_OUT * D_C];
__device__ float g_c  [B_SZ * D_OUT];     // -2 * inputs @ W^T
__device__ float g_vs [D_C];              // rowsum of V
__device__ float g_d  [D_OUT];            // diag of 2*W@W^T
__device__ float g_gp0[B_SZ * D_C];       // gu partial, K-slice 0
__device__ float g_gp1[B_SZ * D_C];       // gu partial, K-slice 1

// ---- packed fp16 hi/lo operands (per 8-elem group: 4 hi words then 4 lo) ----
__device__ __align__(128) uint32_t g_pkW [D_OUT * D_IN];
__device__ __align__(128) uint32_t g_pkV [D_C * D_OUT];
__device__ __align__(128) uint32_t g_pkVT[D_OUT * D_C];
__device__ __align__(128) uint32_t g_pkIn[B_SZ * D_IN];
__device__ __align__(128) uint32_t g_pkR [D_OUT * D_OUT];   // 2*W@W^T minus diag
__device__ __align__(128) uint32_t g_pkG [B_SZ * D_OUT];
__device__ __align__(128) uint32_t g_pkX0[B_SZ * D_OUT];
__device__ __align__(128) uint32_t g_pkX1[B_SZ * D_OUT];
__device__ __align__(128) uint32_t g_pkU0[B_SZ * D_C];
__device__ __align__(128) uint32_t g_pkU1[B_SZ * D_C];

__device__ __forceinline__ void split2(float x, float y, uint32_t& hi, uint32_t& lo) {
    __half hx = __float2half_rn(x);
    __half hy = __float2half_rn(y);
    float rx = x - __half2float(hx);
    float ry = y - __half2float(hy);
    __half2 H = __halves2half2(hx, hy);
    hi = *reinterpret_cast<uint32_t*>(&H);
    __half2 L = __floats2half2_rn(rx, ry);
    lo = *reinterpret_cast<uint32_t*>(&L);
}

__global__ void transpose_k(const float* __restrict__ src, float* __restrict__ dst,
                            int rows, int cols) {
    __shared__ float t[32][33];
    int bx = blockIdx.x * 32, by = blockIdx.y * 32;
    int x = bx + threadIdx.x;
    #pragma unroll
    for (int j = 0; j < 32; j += 8)
        t[threadIdx.y + j][threadIdx.x] = src[(size_t)(by + threadIdx.y + j) * cols + x];
    __syncthreads();
    int x2 = by + threadIdx.x;
    #pragma unroll
    for (int j = 0; j < 32; j += 8)
        dst[(size_t)(bx + threadIdx.y + j) * rows + x2] = t[threadIdx.x][threadIdx.y + j];
}

__global__ void pack_k(const float* __restrict__ src, uint32_t* __restrict__ dst, int n8) {
    int i = blockIdx.x * blockDim.x + threadIdx.x;
    if (i >= n8) return;
    const float4* s = reinterpret_cast<const float4*>(src) + 2 * (size_t)i;
    float4 v0 = s[0], v1 = s[1];
    uint32_t h0,l0,h1,l1,h2,l2,h3,l3;
    split2(v0.x, v0.y, h0, l0); split2(v0.z, v0.w, h1, l1);
    split2(v1.x, v1.y, h2, l2); split2(v1.z, v1.w, h3, l3);
    uint4* d = reinterpret_cast<uint4*>(dst) + 2 * (size_t)i;
    uint4 H; H.x=h0; H.y=h1; H.z=h2; H.w=h3;
    uint4 L; L.x=l0; L.y=l1; L.z=l2; L.w=l3;
    d[0] = H; d[1] = L;
}

__global__ void vsum_k(const float* __restrict__ V, float* __restrict__ out) {
    __shared__ float red[256];
    int n = blockIdx.x;
    float s = 0.0f;
    for (int k = threadIdx.x; k < D_OUT; k += 256) s += V[(size_t)n * D_OUT + k];
    red[threadIdx.x] = s;
    __syncthreads();
    for (int st = 128; st > 0; st >>= 1) {
        if (threadIdx.x < st) red[threadIdx.x] += red[threadIdx.x + st];
        __syncthreads();
    }
    if (threadIdx.x == 0) out[n] = red[0];
}

template<int MODE>
__global__ void step0_k(const float* __restrict__ src, float* __restrict__ s,
                        float* __restrict__ a1, float* __restrict__ a2,
                        uint32_t* __restrict__ pk, int n8) {
    int i = blockIdx.x * blockDim.x + threadIdx.x;
    if (i >= n8) return;
    float gv[8];
    if (MODE == 0) {
        const float4* cs = reinterpret_cast<const float4*>(src) + 2 * (size_t)i;
        float4 v0 = cs[0], v1 = cs[1];
        gv[0]=v0.x; gv[1]=v0.y; gv[2]=v0.z; gv[3]=v0.w;
        gv[4]=v1.x; gv[5]=v1.y; gv[6]=v1.z; gv[7]=v1.w;
    } else {
        const float G0 = GAMMA_F * 1.0e-3f * (-0.5f);
        int base = (8 * i) & (D_C - 1);
        #pragma unroll
        for (int j = 0; j < 8; j++) gv[j] = G0 * src[base + j];
    }
    float xs[8], A1[8], A2[8];
    #pragma unroll
    for (int j = 0; j < 8; j++) {
        float g   = gv[j];
        float na1 = ONE_M_RHO_F * g * g;
        float upd = LR_F * g / sqrtf(na1 + EPS_F);
        float na2 = -upd;
        xs[j] = MOM_F * na2 - upd;
        A1[j] = na1; A2[j] = na2;
    }
    float4* so = reinterpret_cast<float4*>(s)  + 2 * (size_t)i;
    float4* o1 = reinterpret_cast<float4*>(a1) + 2 * (size_t)i;
    float4* o2 = reinterpret_cast<float4*>(a2) + 2 * (size_t)i;
    so[0] = make_float4(xs[0],xs[1],xs[2],xs[3]); so[1] = make_float4(xs[4],xs[5],xs[6],xs[7]);
    o1[0] = make_float4(A1[0],A1[1],A1[2],A1[3]); o1[1] = make_float4(A1[4],A1[5],A1[6],A1[7]);
    o2[0] = make_float4(A2[0],A2[1],A2[2],A2[3]); o2[1] = make_float4(A2[4],A2[5],A2[6],A2[7]);
    uint32_t h[4], l[4];
    split2(xs[0],xs[1],h[0],l[0]); split2(xs[2],xs[3],h[1],l[1]);
    split2(xs[4],xs[5],h[2],l[2]); split2(xs[6],xs[7],h[3],l[3]);
    uint4* d = reinterpret_cast<uint4*>(pk) + 2 * (size_t)i;
    uint4 H; H.x=h[0]; H.y=h[1]; H.z=h[2]; H.w=h[3];
    uint4 L; L.x=l[0]; L.y=l[1]; L.z=l[2]; L.w=l[3];
    d[0] = H; d[1] = L;
}

// gu reduction: g = part0 + part1; rmsprop on (u,b1,b2); write u + packed u
__global__ void guredux_k(const float* __restrict__ q0, const float* __restrict__ q1b,
                          float* __restrict__ u, float* __restrict__ b1,
                          float* __restrict__ b2, uint32_t* __restrict__ pk, int n8) {
    int i = blockIdx.x * blockDim.x + threadIdx.x;
    if (i >= n8) return;
    const float4* s0 = reinterpret_cast<const float4*>(q0)  + 2 * (size_t)i;
    const float4* s1 = reinterpret_cast<const float4*>(q1b) + 2 * (size_t)i;
    float4 p00 = s0[0], p01 = s0[1], p10 = s1[0], p11 = s1[1];
    float gv[8] = { p00.x + p10.x, p00.y + p10.y, p00.z + p10.z, p00.w + p10.w,
                    p01.x + p11.x, p01.y + p11.y, p01.z + p11.z, p01.w + p11.w };
    float4* su = reinterpret_cast<float4*>(u)  + 2 * (size_t)i;
    float4* s1p = reinterpret_cast<float4*>(b1) + 2 * (size_t)i;
    float4* s2p = reinterpret_cast<float4*>(b2) + 2 * (size_t)i;
    float uv[8], A1[8], A2[8];
    float4 u0 = su[0], u1 = su[1], a10 = s1p[0], a11 = s1p[1], a20 = s2p[0], a21 = s2p[1];
    float uin[8] = {u0.x,u0.y,u0.z,u0.w,u1.x,u1.y,u1.z,u1.w};
    float a1i[8] = {a10.x,a10.y,a10.z,a10.w,a11.x,a11.y,a11.z,a11.w};
    float a2i[8] = {a20.x,a20.y,a20.z,a20.w,a21.x,a21.y,a21.z,a21.w};
    #pragma unroll
    for (int j = 0; j < 8; j++) {
        float g   = gv[j];
        float na1 = RHO_F * a1i[j] + ONE_M_RHO_F * g * g;
        float upd = LR_F * g / sqrtf(na1 + EPS_F);
        float na2 = MOM_F * a2i[j] - upd;
        uv[j] = uin[j] + MOM_F * na2 - upd;
        A1[j] = na1; A2[j] = na2;
    }
    su[0] = make_float4(uv[0],uv[1],uv[2],uv[3]); su[1] = make_float4(uv[4],uv[5],uv[6],uv[7]);
    s1p[0] = make_float4(A1[0],A1[1],A1[2],A1[3]); s1p[1] = make_float4(A1[4],A1[5],A1[6],A1[7]);
    s2p[0] = make_float4(A2[0],A2[1],A2[2],A2[3]); s2p[1] = make_float4(A2[4],A2[5],A2[6],A2[7]);
    uint32_t h[4], l[4];
    split2(uv[0],uv[1],h[0],l[0]); split2(uv[2],uv[3],h[1],l[1]);
    split2(uv[4],uv[5],h[2],l[2]); split2(uv[6],uv[7],h[3],l[3]);
    uint4* d = reinterpret_cast<uint4*>(pk) + 2 * (size_t)i;
    uint4 H; H.x=h[0]; H.y=h[1]; H.z=h[2]; H.w=h[3];
    uint4 L; L.x=l[0]; L.y=l[1]; L.z=l[2]; L.w=l[3];
    d[0] = H; d[1] = L;
}

// ============================ mma helpers ============================

__device__ __forceinline__ uint32_t cvta_smem(const void* p) {
    uint32_t a;
    asm("{ .reg .u64 t; cvta.to.shared.u64 t, %1; cvt.u32.u64 %0, t; }" : "=r"(a) : "l"(p));
    return a;
}

__device__ __forceinline__ void mma_f16(float* c, const uint32_t* a, const uint32_t* b) {
    asm volatile(
        "mma.sync.aligned.m16n8k16.row.col.f32.f16.f16.f32 "
        "{%0,%1,%2,%3}, {%4,%5,%6,%7}, {%8,%9}, {%0,%1,%2,%3};"
        : "+f"(c[0]), "+f"(c[1]), "+f"(c[2]), "+f"(c[3])
        : "r"(a[0]), "r"(a[1]), "r"(a[2]), "r"(a[3]), "r"(b[0]), "r"(b[1]));
}

#define LDSM_X4(R, addr) \
    asm volatile("ldmatrix.sync.aligned.m8n8.x4.shared.b16 {%0,%1,%2,%3}, [%4];" \
        : "=r"((R)[0]), "=r"((R)[1]), "=r"((R)[2]), "=r"((R)[3]) : "r"(addr))

#define CP16(dst, src) \
    asm volatile("cp.async.cg.shared.global [%0], [%1], 16;" :: "r"(dst), "l"(src))

__device__ __forceinline__ void store_pk2(uint32_t* __restrict__ q, int ncols,
                                          int m, int n, float v0, float v1) {
    uint32_t hi, lo; split2(v0, v1, hi, lo);
    uint32_t* p = q + (size_t)m * ncols + ((n >> 3) << 3) + ((n & 7) >> 1);
    p[0] = hi;
    p[4] = lo;
}

// EPI 1: GEMM2: reads p0=x; writes q1=pkG, p2=T
// EPI 2: gx GEMM: g = acc + x*d[n] + p4(c) + p0(T); rmsprop; q1=pkX
// EPI 4: setup M2: diag -> p1(d), pack off-diag 2*acc -> q1
// EPI 5: setup c:  p1 = -2*acc
// EPI 6: gu partial: p1[idx] = acc (raw fp32)
template<int EPI>
__device__ __forceinline__ void epi_pair(float a0, float a1, int m, int n, int Nout,
                                         const float* __restrict__ p0,
                                         const float* __restrict__ p4,
                                         const float* __restrict__ pd,
                                         float* __restrict__ p1,
                                         float* __restrict__ p2,
                                         float* __restrict__ p3,
                                         uint32_t* __restrict__ q1)
{
    const size_t idx = (size_t)m * (size_t)Nout + (size_t)n;
    if (EPI == 6) {
        float2 o; o.x = a0; o.y = a1;
        *reinterpret_cast<float2*>(&p1[idx]) = o;
    } else if (EPI == 4) {
        float v0 = 2.0f * a0, v1 = 2.0f * a1;
        if (m == n)     { p1[m] = v0; v0 = 0.0f; }
        if (m == n + 1) { p1[m] = v1; v1 = 0.0f; }
        store_pk2(q1, Nout, m, n, v0, v1);
    } else if (EPI == 5) {
        float2 o; o.x = -2.0f * a0; o.y = -2.0f * a1;
        *reinterpret_cast<float2*>(&p1[idx]) = o;
    } else if (EPI == 1) {
        float2 xv = *reinterpret_cast<const float2*>(&p0[idx]);
        float G0, G1; float2 T;
        {
            float da = sqrtf(xv.x * xv.x + 1e-6f);
            float ex = expf(-a0);
            G0  = GAMMA_F * da * (-0.5f * ex);
            T.x = (GAMMA_F * (1.0f + ex) * 0.5f + GAMMA_F * 0.1f) * (xv.x / da);
        }
        {
            float da = sqrtf(xv.y * xv.y + 1e-6f);
            float ex = expf(-a1);
            G1  = GAMMA_F * da * (-0.5f * ex);
            T.y = (GAMMA_F * (1.0f + ex) * 0.5f + GAMMA_F * 0.1f) * (xv.y / da);
        }
        store_pk2(q1, Nout, m, n, G0, G1);
        *reinterpret_cast<float2*>(&p2[idx]) = T;
    } else {   // EPI == 2
        float2 sv  = *reinterpret_cast<const float2*>(&p1[idx]);
        float2 tv = *reinterpret_cast<const float2*>(&p0[idx]);
        float2 cv = *reinterpret_cast<const float2*>(&p4[idx]);
        float2 dv = *reinterpret_cast<const float2*>(&pd[n]);
        float2 g2;
        g2.x = a0 + sv.x * dv.x + cv.x + tv.x;
        g2.y = a1 + sv.y * dv.y + cv.y + tv.y;
        float2 a1v = *reinterpret_cast<const float2*>(&p2[idx]);
        float2 a2v = *reinterpret_cast<const float2*>(&p3[idx]);
        float na1x = RHO_F * a1v.x + ONE_M_RHO_F * g2.x * g2.x;
        float updx = LR_F * g2.x / sqrtf(na1x + EPS_F);
        float na2x = MOM_F * a2v.x - updx;
        float svx  = sv.x + MOM_F * na2x - updx;
        float na1y = RHO_F * a1v.y + ONE_M_RHO_F * g2.y * g2.y;
        float updy = LR_F * g2.y / sqrtf(na1y + EPS_F);
        float na2y = MOM_F * a2v.y - updy;
        float svy  = sv.y + MOM_F * na2y - updy;
        float2 o1; o1.x = svx;  o1.y = svy;
        float2 o2; o2.x = na1x; o2.y = na1y;
        float2 o3; o3.x = na2x; o3.y = na2y;
        *reinterpret_cast<float2*>(&p1[idx]) = o1;
        store_pk2(q1, Nout, m, n, svx, svy);
        *reinterpret_cast<float2*>(&p2[idx]) = o2;
        *reinterpret_cast<float2*>(&p3[idx]) = o3;
    }
}

// ---- shared mainloop: BM=128, BN=256, BK=32, S=3, 512 threads (16 warps 2x8)
// kpitch = stored K extent (elements), koff = starting k-tile, ktiles = #k-tiles
// NMMA=1: acc += a_hi*b_hi ; NMMA=2: + a_hi*b_lo ; NMMA=3: + a_lo*b_hi
struct Frag { float acc[4][4][4]; };

template<int NMMA>
__device__ __forceinline__ void mainloop_128x256(
    const uint32_t* __restrict__ pkA, const uint32_t* __restrict__ pkB,
    int row0, int col0, int kpitch, int koff, int ktiles, uint32_t sbase, Frag& F)
{
    constexpr int S = 3;
    constexpr int STAGE = (128 + 256) * 128;
    const int tid  = threadIdx.x;
    const int lane = tid & 31, wid = tid >> 5;
    const int wm = wid >> 3, wn = wid & 7;

    const char* gA = reinterpret_cast<const char*>(pkA) + (size_t)row0 * (4 * kpitch)
                   + (size_t)koff * 128;
    const char* gB = reinterpret_cast<const char*>(pkB) + (size_t)col0 * (4 * kpitch)
                   + (size_t)koff * 128;
    const int pitch = 4 * kpitch;

    auto issue = [&](int kt, int buf) {
        const uint32_t sd = sbase + buf * STAGE;
        const char* sA = gA + kt * 128;
        if (NMMA == 3) {
            #pragma unroll
            for (int i = 0; i < 2; i++) {
                int idx = i * 512 + tid;
                int r = idx >> 3, c = idx & 7;
                uint32_t dst = sd + r * 128 + ((c ^ (r & 7)) << 4);
                CP16(dst, sA + (size_t)r * pitch + (c << 4));
            }
        } else {
            int r = tid >> 2, g = tid & 3;
            int c = 2 * g;
            uint32_t dst = sd + r * 128 + ((c ^ (r & 7)) << 4);
            CP16(dst, sA + (size_t)r * pitch + (c << 4));
        }
        const char* sB = gB + kt * 128;
        if (NMMA >= 2) {
            #pragma unroll
            for (int i = 0; i < 4; i++) {
                int idx = i * 512 + tid;
                int r = idx >> 3, c = idx & 7;
                uint32_t dst = sd + 128 * 128 + r * 128 + ((c ^ (r & 7)) << 4);
                CP16(dst, sB + (size_t)r * pitch + (c << 4));
            }
        } else {
            #pragma unroll
            for (int i = 0; i < 2; i++) {
                int idx = i * 512 + tid;
                int r = idx >> 2, g = idx & 3;
                int c = 2 * g;
                uint32_t dst = sd + 128 * 128 + r * 128 + ((c ^ (r & 7)) << 4);
                CP16(dst, sB + (size_t)r * pitch + (c << 4));
            }
        }
        asm volatile("cp.async.commit_group;" ::: "memory");
    };

    #pragma unroll
    for (int i = 0; i < 4; i++)
        #pragma unroll
        for (int j = 0; j < 4; j++)
            #pragma unroll
            for (int r = 0; r < 4; r++) F.acc[i][j][r] = 0.0f;

    issue(0, 0);
    issue(1, 1);

    for (int kt = 0; kt < ktiles; kt++) {
        if (kt < ktiles - 1) asm volatile("cp.async.wait_group 1;" ::: "memory");
        else                 asm volatile("cp.async.wait_group 0;" ::: "memory");
        __syncthreads();
        if (kt + 2 < ktiles) issue(kt + 2, (kt + 2) % S);

        const int buf = kt % S;
        const uint32_t sA32 = sbase + buf * STAGE;
        const uint32_t sB32 = sA32 + 128 * 128;

        #pragma unroll
        for (int j = 0; j < 2; j++) {
            uint32_t afh[4][4];
            #pragma unroll
            for (int mf = 0; mf < 4; mf++) {
                int rr = wm * 64 + mf * 16 + (lane & 15);
                int c  = 4 * j + 2 * (lane >> 4);
                uint32_t addr = sA32 + rr * 128 + ((c ^ (rr & 7)) << 4);
                LDSM_X4(afh[mf], addr);
            }
            uint32_t afl[4][4];
            if (NMMA == 3) {
                #pragma unroll
                for (int mf = 0; mf < 4; mf++) {
                    int rr = wm * 64 + mf * 16 + (lane & 15);
                    int c  = 4 * j + 1 + 2 * (lane >> 4);
                    uint32_t addr = sA32 + rr * 128 + ((c ^ (rr & 7)) << 4);
                    LDSM_X4(afl[mf], addr);
                }
            }
            constexpr int NB = (NMMA >= 2) ? 2 : 1;
            uint32_t bfr[NB][4][2];
            #pragma unroll
            for (int hl = 0; hl < NB; hl++)
                #pragma unroll
                for (int p = 0; p < 2; p++) {
                    uint32_t q[4];
                    int rr = wn * 32 + (2 * p + (lane >> 4)) * 8 + (lane & 7);
                    int c  = 4 * j + hl + 2 * ((lane >> 3) & 1);
                    uint32_t addr = sB32 + rr * 128 + ((c ^ (rr & 7)) << 4);
                    LDSM_X4(q, addr);
                    bfr[hl][2 * p    ][0] = q[0]; bfr[hl][2 * p    ][1] = q[1];
                    bfr[hl][2 * p + 1][0] = q[2]; bfr[hl][2 * p + 1][1] = q[3];
                }
            #pragma unroll
            for (int mf = 0; mf < 4; mf++)
                #pragma unroll
                for (int nf = 0; nf < 4; nf++) {
                    mma_f16(F.acc[mf][nf], afh[mf], bfr[0][nf]);
                    if (NMMA >= 2)
                        mma_f16(F.acc[mf][nf], afh[mf], bfr[1][nf]);
                    if (NMMA == 3)
                        mma_f16(F.acc[mf][nf], afl[mf], bfr[0][nf]);
                }
        }
    }
}

template<int EPI>
__device__ __forceinline__ void run_epi(Frag& F, int row0, int col0, int Nout,
                                        const float* p0, const float* p4, const float* pd,
                                        float* p1, float* p2, float* p3, uint32_t* q1)
{
    const int tid  = threadIdx.x;
    const int lane = tid & 31, wid = tid >> 5;
    const int wm = wid >> 3, wn = wid & 7;
    #pragma unroll
    for (int mf = 0; mf < 4; mf++) {
        #pragma unroll
        for (int nf = 0; nf < 4; nf++) {
            int mlo = row0 + wm * 64 + mf * 16 + (lane >> 2);
            int n   = col0 + wn * 32 + nf * 8 + ((lane & 3) << 1);
            epi_pair<EPI>(F.acc[mf][nf][0], F.acc[mf][nf][1], mlo,     n, Nout, p0, p4, pd, p1, p2, p3, q1);
            epi_pair<EPI>(F.acc[mf][nf][2], F.acc[mf][nf][3], mlo + 8, n, Nout, p0, p4, pd, p1, p2, p3, q1);
        }
    }
}

// GEMM2: s = u@V, EPI 1.  grid 128
__global__ __launch_bounds__(512, 1)
void gemm2_k(const uint32_t* __restrict__ pkU, const uint32_t* __restrict__ pkVT,
             const float* __restrict__ x, float* __restrict__ pT,
             uint32_t* __restrict__ pkG)
{
    extern __shared__ __align__(1024) char smem[];
    Frag F;
    int col0 = (blockIdx.x & 7) * 256, row0 = (blockIdx.x >> 3) * 128;
    mainloop_128x256<2>(pkU, pkVT, row0, col0, D_C, 0, D_C / 32, cvta_smem(smem), F);
    run_epi<1>(F, row0, col0, D_OUT, x, nullptr, nullptr, nullptr, pT, nullptr, pkG);
}

// merged gx + gu: blocks [0,128) = gx (EPI2, 1-term on R),
// [128,160) = gu partial (EPI6, 2-term, K split in halves). 160 CTAs, balanced.
__global__ __launch_bounds__(512, 1)
void gemm34_k(const uint32_t* __restrict__ pkX, const uint32_t* __restrict__ pkR,
              const uint32_t* __restrict__ pkG, const uint32_t* __restrict__ pkV,
              const float* __restrict__ pT, const float* __restrict__ pc,
              const float* __restrict__ pd,
              float* __restrict__ x,  float* __restrict__ a1, float* __restrict__ a2,
              uint32_t* __restrict__ pkXw,
              float* __restrict__ gp0, float* __restrict__ gp1)
{
    extern __shared__ __align__(1024) char smem[];
    Frag F;
    if (blockIdx.x < 128) {
        int col0 = (blockIdx.x & 7) * 256, row0 = (blockIdx.x >> 3) * 128;
        mainloop_128x256<1>(pkX, pkR, row0, col0, D_OUT, 0, D_OUT / 32, cvta_smem(smem), F);
        run_epi<2>(F, row0, col0, D_OUT, pT, pc, pd, x, a1, a2, pkXw);
    } else {
        int b = blockIdx.x - 128;
        int ks = b >> 4;                      // K slice 0/1
        int row0 = (b & 15) * 128;
        float* gp = ks ? gp1 : gp0;
        mainloop_128x256<2>(pkG, pkV, row0, 0, D_OUT, ks * 32, 32, cvta_smem(smem), F);
        run_epi<6>(F, row0, 0, D_C, nullptr, nullptr, nullptr, gp, nullptr, nullptr, nullptr);
    }
}

// merged setup: blocks [0,128) = M2->diag+R (EPI4), [128,256) = c (EPI5); K=1024, 3-term
__global__ __launch_bounds__(512, 1)
void setup_k(const uint32_t* __restrict__ pkW, const uint32_t* __restrict__ pkIn,
             uint32_t* __restrict__ pkR, float* __restrict__ pdiag, float* __restrict__ pc)
{
    extern __shared__ __align__(1024) char smem[];
    Frag F;
    const bool rolec = blockIdx.x >= 128;
    int b = rolec ? blockIdx.x - 128 : blockIdx.x;
    int col0 = (b & 7) * 256, row0 = (b >> 3) * 128;
    const uint32_t* pkA = rolec ? pkIn : pkW;
    mainloop_128x256<3>(pkA, pkW, row0, col0, D_IN, 0, D_IN / 32, cvta_smem(smem), F);
    if (!rolec)
        run_epi<4>(F, row0, col0, D_OUT, nullptr, nullptr, nullptr, pdiag, nullptr, nullptr, pkR);
    else
        run_epi<5>(F, row0, col0, D_OUT, nullptr, nullptr, nullptr, pc, nullptr, nullptr, nullptr);
}

// ============================================================================

extern "C" void kernel_launch(void* const* d_in, const int* in_sizes, int n_in,
                              void* d_out, int out_size)
{
    (void)in_sizes; (void)n_in; (void)out_size;
    const float* inputs = (const float*)d_in[0];
    const float* W      = (const float*)d_in[1];
    const float* V      = (const float*)d_in[2];
    float* x = (float*)d_out;

    float *pT, *pa1, *pa2, *pu, *pb1, *pb2, *pVT, *pc, *pvs, *pd, *gp0, *gp1;
    uint32_t *kW, *kV, *kVT, *kIn, *kR, *kG, *kX[2], *kU[2];
    cudaGetSymbolAddress((void**)&pT,  g_T);
    cudaGetSymbolAddress((void**)&pa1, g_a1);
    cudaGetSymbolAddress((void**)&pa2, g_a2);
    cudaGetSymbolAddress((void**)&pu,  g_u);
    cudaGetSymbolAddress((void**)&pb1, g_b1);
    cudaGetSymbolAddress((void**)&pb2, g_b2);
    cudaGetSymbolAddress((void**)&pVT, g_VT);
    cudaGetSymbolAddress((void**)&pc,  g_c);
    cudaGetSymbolAddress((void**)&pvs, g_vs);
    cudaGetSymbolAddress((void**)&pd,  g_d);
    cudaGetSymbolAddress((void**)&gp0, g_gp0);
    cudaGetSymbolAddress((void**)&gp1, g_gp1);
    cudaGetSymbolAddress((void**)&kW,  g_pkW);
    cudaGetSymbolAddress((void**)&kV,  g_pkV);
    cudaGetSymbolAddress((void**)&kVT, g_pkVT);
    cudaGetSymbolAddress((void**)&kIn, g_pkIn);
    cudaGetSymbolAddress((void**)&kR,  g_pkR);
    cudaGetSymbolAddress((void**)&kG,  g_pkG);
    cudaGetSymbolAddress((void**)&kX[0], g_pkX0);
    cudaGetSymbolAddress((void**)&kX[1], g_pkX1);
    cudaGetSymbolAddress((void**)&kU[0], g_pkU0);
    cudaGetSymbolAddress((void**)&kU[1], g_pkU1);

    constexpr int SMEM = 3 * (128 + 256) * 128;   // 147456
    cudaFuncSetAttribute(gemm2_k,  cudaFuncAttributeMaxDynamicSharedMemorySize, SMEM);
    cudaFuncSetAttribute(gemm34_k, cudaFuncAttributeMaxDynamicSharedMemorySize, SMEM);
    cudaFuncSetAttribute(setup_k,  cudaFuncAttributeMaxDynamicSharedMemorySize, SMEM);

    const int TPB = 256;

    // ---- setup: transpose/pack; merged (diag+R) = 2*W@W^T and c = -2*inputs@W^T
    transpose_k<<<dim3(D_OUT / 32, D_C / 32), dim3(32, 8)>>>(V, pVT, D_C, D_OUT);
    pack_k<<<(D_OUT * D_IN / 8 + TPB - 1) / TPB, TPB>>>(W,      kW,  D_OUT * D_IN / 8);
    pack_k<<<(D_C * D_OUT / 8 + TPB - 1) / TPB, TPB>>>(V,       kV,  D_C * D_OUT / 8);
    pack_k<<<(D_OUT * D_C / 8 + TPB - 1) / TPB, TPB>>>(pVT,     kVT, D_OUT * D_C / 8);
    pack_k<<<(B_SZ * D_IN / 8 + TPB - 1) / TPB, TPB>>>(inputs,  kIn, B_SZ * D_IN / 8);

    setup_k<<<256, 512, SMEM>>>(kW, kIn, kR, pd, pc);

    // ---- step 0: x from g=c ; u from g = G0 * rowsum(V) broadcast ----
    vsum_k<<<D_C, 256>>>(V, pvs);
    step0_k<0><<<(B_SZ * D_OUT / 8 + TPB - 1) / TPB, TPB>>>(
        pc, x, pa1, pa2, kX[0], B_SZ * D_OUT / 8);
    step0_k<1><<<(B_SZ * D_C / 8 + TPB - 1) / TPB, TPB>>>(
        pvs, pu, pb1, pb2, kU[0], B_SZ * D_C / 8);

    // ---- steps 1..9: GEMM2 ; balanced gx + gu-partials ; gu reduction ----
    for (int s = 1; s < 10; s++) {
        const int rd = (s - 1) & 1, wr = s & 1;
        gemm2_k<<<128, 512, SMEM>>>(kU[rd], kVT, x, pT, kG);
        gemm34_k<<<160, 512, SMEM>>>(kX[rd], kR, kG, kV, pT, pc, pd,
                                     x, pa1, pa2, kX[wr], gp0, gp1);
        guredux_k<<<(B_SZ * D_C / 8 + TPB - 1) / TPB, TPB>>>(
            gp0, gp1, pu, pb1, pb2, kU[wr], B_SZ * D_C / 8);
    }
}